// round 2
// baseline (speedup 1.0000x reference)
#include <cuda_runtime.h>
#include <cuda_bf16.h>
#include <math.h>

// ============================================================================
// BatchNormSPDMean: affine-invariant Karcher mean (3 iters) + whitening + bias
//   data: (B=8192, 64, 64) fp32 SPD;  bias_param: (64,64) fp32
//   out_b = S * (G data_b G) * S,  G = mean^{-1/2},  S = expm(sym(bias)/2)
// All spectral functions via batched parallel Jacobi eigensolver in SMEM.
// ============================================================================

#define N64 64
#define NN 4096
#define LD 65                 // padded row stride (65 mod 32 == 1 -> conflict-free)
#define NSWEEP_B 9            // Jacobi sweeps for batched eigh
#define NSWEEP_S 12           // Jacobi sweeps for single-matrix eigh (cheap)
#define TPB 128

// ---- persistent scratch (device globals; no allocations allowed) ----
__device__ float g_M [NN];    // running mean M
__device__ float g_Ms[NN];    // M^{1/2}
__device__ float g_Mi[NN];    // M^{-1/2}
__device__ float g_T [NN];    // tangent mean accumulator
__device__ float g_W [NN];    // final combined transform W = S*G

// ---------------------------------------------------------------------------
// helpers (assume blockDim.x == 128)
// ---------------------------------------------------------------------------
__device__ __forceinline__ void load_g2s(const float* __restrict__ g, float* S) {
    for (int idx = threadIdx.x; idx < NN; idx += TPB)
        S[(idx >> 6) * LD + (idx & 63)] = g[idx];
}
__device__ __forceinline__ void store_s2g(const float* S, float* __restrict__ g) {
    for (int idx = threadIdx.x; idx < NN; idx += TPB)
        g[idx] = S[(idx >> 6) * LD + (idx & 63)];
}
__device__ __forceinline__ void sym_s(float* A) {
    for (int idx = threadIdx.x; idx < NN; idx += TPB) {
        int i = idx >> 6, j = idx & 63;
        if (i < j) {
            float v = 0.5f * (A[i * LD + j] + A[j * LD + i]);
            A[i * LD + j] = v;
            A[j * LD + i] = v;
        }
    }
}
// C = A * B   (all shared, 64x64, ld=LD)
__device__ __forceinline__ void smm(const float* A, const float* B, float* C) {
    int j  = threadIdx.x & 63;
    int ib = (threadIdx.x >> 6) << 5;
    float acc[32];
#pragma unroll
    for (int i = 0; i < 32; i++) acc[i] = 0.f;
    for (int k = 0; k < 64; k++) {
        float bv = B[k * LD + j];
#pragma unroll
        for (int i = 0; i < 32; i++) acc[i] = fmaf(A[(ib + i) * LD + k], bv, acc[i]);
    }
#pragma unroll
    for (int i = 0; i < 32; i++) C[(ib + i) * LD + j] = acc[i];
}
// C = A * B^T  (shared)
__device__ __forceinline__ void smm_bt(const float* A, const float* B, float* C) {
    int j  = threadIdx.x & 63;
    int ib = (threadIdx.x >> 6) << 5;
    float acc[32];
#pragma unroll
    for (int i = 0; i < 32; i++) acc[i] = 0.f;
    for (int k = 0; k < 64; k++) {
        float bv = B[j * LD + k];
#pragma unroll
        for (int i = 0; i < 32; i++) acc[i] = fmaf(A[(ib + i) * LD + k], bv, acc[i]);
    }
#pragma unroll
    for (int i = 0; i < 32; i++) C[(ib + i) * LD + j] = acc[i];
}
// gout = A * B  (to global, row-major 64)
__device__ __forceinline__ void smm_glob(const float* A, const float* B, float* __restrict__ gout) {
    int j  = threadIdx.x & 63;
    int ib = (threadIdx.x >> 6) << 5;
    float acc[32];
#pragma unroll
    for (int i = 0; i < 32; i++) acc[i] = 0.f;
    for (int k = 0; k < 64; k++) {
        float bv = B[k * LD + j];
#pragma unroll
        for (int i = 0; i < 32; i++) acc[i] = fmaf(A[(ib + i) * LD + k], bv, acc[i]);
    }
#pragma unroll
    for (int i = 0; i < 32; i++) gout[(ib + i) * 64 + j] = acc[i];
}
// gout = A * B^T  (to global)
__device__ __forceinline__ void smm_bt_glob(const float* A, const float* B, float* __restrict__ gout) {
    int j  = threadIdx.x & 63;
    int ib = (threadIdx.x >> 6) << 5;
    float acc[32];
#pragma unroll
    for (int i = 0; i < 32; i++) acc[i] = 0.f;
    for (int k = 0; k < 64; k++) {
        float bv = B[j * LD + k];
#pragma unroll
        for (int i = 0; i < 32; i++) acc[i] = fmaf(A[(ib + i) * LD + k], bv, acc[i]);
    }
#pragma unroll
    for (int i = 0; i < 32; i++) gout[(ib + i) * 64 + j] = acc[i];
}
// atomicAdd(gacc, scale * A * B^T)
__device__ __forceinline__ void smm_bt_atomic(const float* A, const float* B,
                                              float* __restrict__ gacc, float scale) {
    int j  = threadIdx.x & 63;
    int ib = (threadIdx.x >> 6) << 5;
    float acc[32];
#pragma unroll
    for (int i = 0; i < 32; i++) acc[i] = 0.f;
    for (int k = 0; k < 64; k++) {
        float bv = B[j * LD + k];
#pragma unroll
        for (int i = 0; i < 32; i++) acc[i] = fmaf(A[(ib + i) * LD + k], bv, acc[i]);
    }
#pragma unroll
    for (int i = 0; i < 32; i++) atomicAdd(&gacc[(ib + i) * 64 + j], acc[i] * scale);
}
// O[i][k] = V[i][k] * w[k]
__device__ __forceinline__ void scalecols(const float* V, const float* w, float* O) {
    for (int idx = threadIdx.x; idx < NN; idx += TPB) {
        int i = idx >> 6, k = idx & 63;
        O[i * LD + k] = V[i * LD + k] * w[k];
    }
}

// tournament (round-robin) pairing: round r in [0,63), pair k in [0,32)
__device__ __forceinline__ void get_pair(int r, int k, int& p, int& q) {
    int a = (k == 0) ? 0 : 1 + (k - 1 + r) % 63;
    int b = 1 + (62 - k + r) % 63;
    p = a < b ? a : b;
    q = a < b ? b : a;
}

// parallel cyclic Jacobi on shared A (64x64, ld=LD); V accumulates eigenvectors.
// Post: diag(A) = eigenvalues, A = V diag VT.
__device__ void jacobi(float* A, float* V, int nsweeps) {
    int t = threadIdx.x;
    __shared__ float cs[32], sn[32];
    for (int idx = t; idx < NN; idx += TPB) {
        int i = idx >> 6, j = idx & 63;
        V[i * LD + j] = (i == j) ? 1.f : 0.f;
    }
    __syncthreads();
    for (int sw = 0; sw < nsweeps; ++sw) {
        for (int r = 0; r < 63; ++r) {
            if (t < 32) {
                int p, q; get_pair(r, t, p, q);
                float app = A[p * LD + p], aqq = A[q * LD + q], apq = A[p * LD + q];
                float c, s;
                if (fabsf(apq) < 1e-30f) { c = 1.f; s = 0.f; }
                else {
                    float tau = (aqq - app) / (2.f * apq);
                    float tt  = copysignf(1.f, tau) / (fabsf(tau) + sqrtf(1.f + tau * tau));
                    c = 1.0f / sqrtf(1.f + tt * tt);
                    s = tt * c;
                }
                cs[t] = c; sn[t] = s;
            }
            __syncthreads();
            // row phase: A <- J^T A
            for (int w = t; w < 2048; w += TPB) {
                int k = w >> 6, j = w & 63;
                int p, q; get_pair(r, k, p, q);
                float c = cs[k], s = sn[k];
                float ap = A[p * LD + j], aq = A[q * LD + j];
                A[p * LD + j] = c * ap - s * aq;
                A[q * LD + j] = fmaf(s, ap, c * aq);
            }
            __syncthreads();
            // col phase: A <- A J, V <- V J
            for (int w = t; w < 2048; w += TPB) {
                int k = w >> 6, i = w & 63;
                int p, q; get_pair(r, k, p, q);
                float c = cs[k], s = sn[k];
                float ap = A[i * LD + p], aq = A[i * LD + q];
                A[i * LD + p] = c * ap - s * aq;
                A[i * LD + q] = fmaf(s, ap, c * aq);
                float vp = V[i * LD + p], vq = V[i * LD + q];
                V[i * LD + p] = c * vp - s * vq;
                V[i * LD + q] = fmaf(s, vp, c * vq);
            }
            __syncthreads();
        }
    }
}

// ---------------------------------------------------------------------------
// kernels
// ---------------------------------------------------------------------------
__global__ void k_zero(int which) {
    int i = blockIdx.x * blockDim.x + threadIdx.x;
    if (i < NN) { if (which == 0) g_M[i] = 0.f; else g_T[i] = 0.f; }
}

// arithmetic mean accumulate: grid (NN/256, NCHUNK), each chunk handles nb/NCHUNK mats
__global__ void k_mean_acc(const float* __restrict__ data, int per_chunk, float inv_nb) {
    int e = blockIdx.x * blockDim.x + threadIdx.x;   // 0..4095
    const float* p = data + (size_t)(blockIdx.y) * per_chunk * NN + e;
    float sum = 0.f;
#pragma unroll 8
    for (int i = 0; i < per_chunk; i++) sum += p[(size_t)i * NN];
    atomicAdd(&g_M[e], sum * inv_nb);
}

// eigh(M) -> g_Ms = M^{1/2}, g_Mi = M^{-1/2}
__global__ void __launch_bounds__(TPB) k_eig_M() {
    extern __shared__ float sm[];
    float* A  = sm;
    float* V  = sm + 4160;
    float* T1 = sm + 8320;
    float* T2 = sm + 12480;
    __shared__ float w1[64], w2[64];
    load_g2s(g_M, A);
    __syncthreads();
    sym_s(A);
    __syncthreads();
    jacobi(A, V, NSWEEP_S);
    int t = threadIdx.x;
    if (t < 64) {
        float w = fmaxf(A[t * LD + t], 1e-12f);
        w1[t] = sqrtf(w);
        w2[t] = 1.0f / sqrtf(w);
    }
    __syncthreads();
    scalecols(V, w1, T1); __syncthreads();
    smm_bt(T1, V, T2);    __syncthreads();
    store_s2g(T2, g_Ms);
    __syncthreads();
    scalecols(V, w2, T1); __syncthreads();
    smm_bt(T1, V, T2);    __syncthreads();
    store_s2g(T2, g_Mi);
}

// per-matrix: C = Mi*data_b*Mi, eigh, T += logm(C)/nb
__global__ void __launch_bounds__(TPB) k_batch_step(const float* __restrict__ data, float inv_nb) {
    extern __shared__ float sm[];
    float* sMi = sm;
    float* sD  = sm + 4160;
    float* sA  = sm + 8320;
    float* sV  = sm + 12480;
    __shared__ float lw[64];
    size_t b = blockIdx.x;
    load_g2s(g_Mi, sMi);
    load_g2s(data + b * NN, sD);
    __syncthreads();
    smm(sMi, sD, sA);   // sA = Mi * D
    __syncthreads();
    smm(sA, sMi, sD);   // sD = Mi * D * Mi
    __syncthreads();
    sym_s(sD);
    __syncthreads();
    jacobi(sD, sV, NSWEEP_B);
    int t = threadIdx.x;
    if (t < 64) lw[t] = logf(fmaxf(sD[t * LD + t], 1e-12f));
    __syncthreads();
    scalecols(sV, lw, sA);  // sA = V * diag(log w)
    __syncthreads();
    smm_bt_atomic(sA, sV, g_T, inv_nb);   // T += (V diag(logw) V^T)/nb
}

// eigh(T) -> E = expm(T); g_M = Ms * E * Ms
__global__ void __launch_bounds__(TPB) k_update_M() {
    extern __shared__ float sm[];
    float* A  = sm;
    float* V  = sm + 4160;
    float* T1 = sm + 8320;
    float* T2 = sm + 12480;
    __shared__ float ew[64];
    load_g2s(g_T, A);
    __syncthreads();
    sym_s(A);
    __syncthreads();
    jacobi(A, V, NSWEEP_S);
    int t = threadIdx.x;
    if (t < 64) ew[t] = expf(A[t * LD + t]);
    __syncthreads();
    scalecols(V, ew, T1); __syncthreads();
    smm_bt(T1, V, T2);    __syncthreads();   // T2 = E
    load_g2s(g_Ms, A);    __syncthreads();   // A = Ms
    smm(A, T2, T1);       __syncthreads();   // T1 = Ms*E
    smm_glob(T1, A, g_M);                    // M = Ms*E*Ms
}

// S = expm(sym(bias)/2);  g_W = S * G   (G = g_Mi)
__global__ void __launch_bounds__(TPB) k_bias(const float* __restrict__ bias) {
    extern __shared__ float sm[];
    float* A  = sm;
    float* V  = sm + 4160;
    float* T1 = sm + 8320;
    float* T2 = sm + 12480;
    __shared__ float ew[64];
    int t = threadIdx.x;
    for (int idx = t; idx < NN; idx += TPB) {
        int i = idx >> 6, j = idx & 63;
        A[i * LD + j] = 0.5f * (bias[i * 64 + j] + bias[j * 64 + i]);
    }
    __syncthreads();
    jacobi(A, V, NSWEEP_S);
    if (t < 64) ew[t] = expf(0.5f * A[t * LD + t]);
    __syncthreads();
    scalecols(V, ew, T1); __syncthreads();
    smm_bt(T1, V, T2);    __syncthreads();   // T2 = S
    load_g2s(g_Mi, A);    __syncthreads();   // A = G
    smm_glob(T2, A, g_W);                    // W = S*G
}

// out_b = W * data_b * W^T   (since (S G)^T = G S)
__global__ void __launch_bounds__(TPB) k_final(const float* __restrict__ data,
                                               float* __restrict__ out) {
    extern __shared__ float sm[];
    float* sW = sm;
    float* sD = sm + 4160;
    float* sT = sm + 8320;
    size_t b = blockIdx.x;
    load_g2s(g_W, sW);
    load_g2s(data + b * NN, sD);
    __syncthreads();
    smm(sW, sD, sT);
    __syncthreads();
    smm_bt_glob(sT, sW, out + b * NN);
}

// ---------------------------------------------------------------------------
extern "C" void kernel_launch(void* const* d_in, const int* in_sizes, int n_in,
                              void* d_out, int out_size) {
    // identify inputs by size (data is much larger than bias)
    const float* data;
    const float* bias;
    int nb;
    if (in_sizes[0] >= in_sizes[1]) {
        data = (const float*)d_in[0]; bias = (const float*)d_in[1];
        nb = in_sizes[0] / NN;
    } else {
        data = (const float*)d_in[1]; bias = (const float*)d_in[0];
        nb = in_sizes[1] / NN;
    }
    float* out = (float*)d_out;
    float inv_nb = 1.0f / (float)nb;

    size_t smem = 4 * 4160 * sizeof(float);   // 66560 B
    cudaFuncSetAttribute(k_eig_M,      cudaFuncAttributeMaxDynamicSharedMemorySize, (int)smem);
    cudaFuncSetAttribute(k_batch_step, cudaFuncAttributeMaxDynamicSharedMemorySize, (int)smem);
    cudaFuncSetAttribute(k_update_M,   cudaFuncAttributeMaxDynamicSharedMemorySize, (int)smem);
    cudaFuncSetAttribute(k_bias,       cudaFuncAttributeMaxDynamicSharedMemorySize, (int)smem);
    cudaFuncSetAttribute(k_final,      cudaFuncAttributeMaxDynamicSharedMemorySize, (int)smem);

    // arithmetic mean
    k_zero<<<16, 256>>>(0);
    {
        int nchunk = 64;
        while (nchunk > 1 && (nb % nchunk) != 0) nchunk >>= 1;
        int per_chunk = nb / nchunk;
        dim3 g(NN / 256, nchunk);
        k_mean_acc<<<g, 256>>>(data, per_chunk, inv_nb);
    }

    // 3 Karcher iterations
    for (int it = 0; it < 3; ++it) {
        k_eig_M<<<1, TPB, smem>>>();
        k_zero<<<16, 256>>>(1);
        k_batch_step<<<nb, TPB, smem>>>(data, inv_nb);
        k_update_M<<<1, TPB, smem>>>();
    }

    // final whitening transform + bias congruence
    k_eig_M<<<1, TPB, smem>>>();        // g_Mi = G = mean^{-1/2}
    k_bias<<<1, TPB, smem>>>(bias);     // g_W = S*G
    k_final<<<nb, TPB, smem>>>(data, out);
}

// round 3
// speedup vs baseline: 2.0426x; 2.0426x over previous
#include <cuda_runtime.h>
#include <cuda_bf16.h>
#include <math.h>

// ============================================================================
// BatchNormSPDMean: affine-invariant Karcher mean (3 iters) + whitening + bias
// R3: TPB=256, 3 smem buffers (4 CTAs/SM), precomputed Jacobi pair tables,
//     sweeps 9->7 (batch) / 12->10 (single).
// ============================================================================

#define NN 4096
#define LD 65                 // padded row stride (65 mod 32 == 1 -> conflict-free)
#define NSWEEP_B 7            // Jacobi sweeps for batched eigh
#define NSWEEP_S 10           // Jacobi sweeps for single-matrix eigh
#define TPB 256
#define BUF 4160              // 64*65 floats per matrix buffer

// ---- persistent scratch (device globals; no allocations allowed) ----
__device__ float g_M [NN];    // running mean M
__device__ float g_Ms[NN];    // M^{1/2}
__device__ float g_Mi[NN];    // M^{-1/2}
__device__ float g_T [NN];    // tangent mean accumulator
__device__ float g_W [NN];    // final combined transform W = S*G

// ---------------------------------------------------------------------------
// helpers (blockDim.x == 256)
// ---------------------------------------------------------------------------
__device__ __forceinline__ void load_g2s(const float* __restrict__ g, float* S) {
    for (int idx = threadIdx.x; idx < NN; idx += TPB)
        S[(idx >> 6) * LD + (idx & 63)] = g[idx];
}
__device__ __forceinline__ void store_s2g(const float* S, float* __restrict__ g) {
    for (int idx = threadIdx.x; idx < NN; idx += TPB)
        g[idx] = S[(idx >> 6) * LD + (idx & 63)];
}
__device__ __forceinline__ void sym_s(float* A) {
    for (int idx = threadIdx.x; idx < NN; idx += TPB) {
        int i = idx >> 6, j = idx & 63;
        if (i < j) {
            float v = 0.5f * (A[i * LD + j] + A[j * LD + i]);
            A[i * LD + j] = v;
            A[j * LD + i] = v;
        }
    }
}
// C = A * B   (shared, 64x64, ld=LD). 256 threads: 4 row-groups x 16 rows.
__device__ __forceinline__ void smm(const float* A, const float* B, float* C) {
    int j  = threadIdx.x & 63;
    int ib = (threadIdx.x >> 6) << 4;
    float acc[16];
#pragma unroll
    for (int i = 0; i < 16; i++) acc[i] = 0.f;
    for (int k = 0; k < 64; k++) {
        float bv = B[k * LD + j];
#pragma unroll
        for (int i = 0; i < 16; i++) acc[i] = fmaf(A[(ib + i) * LD + k], bv, acc[i]);
    }
#pragma unroll
    for (int i = 0; i < 16; i++) C[(ib + i) * LD + j] = acc[i];
}
// C = A * B^T  (shared)
__device__ __forceinline__ void smm_bt(const float* A, const float* B, float* C) {
    int j  = threadIdx.x & 63;
    int ib = (threadIdx.x >> 6) << 4;
    float acc[16];
#pragma unroll
    for (int i = 0; i < 16; i++) acc[i] = 0.f;
    for (int k = 0; k < 64; k++) {
        float bv = B[j * LD + k];
#pragma unroll
        for (int i = 0; i < 16; i++) acc[i] = fmaf(A[(ib + i) * LD + k], bv, acc[i]);
    }
#pragma unroll
    for (int i = 0; i < 16; i++) C[(ib + i) * LD + j] = acc[i];
}
// gout = A * B  (to global, row-major 64)
__device__ __forceinline__ void smm_glob(const float* A, const float* B, float* __restrict__ gout) {
    int j  = threadIdx.x & 63;
    int ib = (threadIdx.x >> 6) << 4;
    float acc[16];
#pragma unroll
    for (int i = 0; i < 16; i++) acc[i] = 0.f;
    for (int k = 0; k < 64; k++) {
        float bv = B[k * LD + j];
#pragma unroll
        for (int i = 0; i < 16; i++) acc[i] = fmaf(A[(ib + i) * LD + k], bv, acc[i]);
    }
#pragma unroll
    for (int i = 0; i < 16; i++) gout[(ib + i) * 64 + j] = acc[i];
}
// gout = A * B^T  (to global)
__device__ __forceinline__ void smm_bt_glob(const float* A, const float* B, float* __restrict__ gout) {
    int j  = threadIdx.x & 63;
    int ib = (threadIdx.x >> 6) << 4;
    float acc[16];
#pragma unroll
    for (int i = 0; i < 16; i++) acc[i] = 0.f;
    for (int k = 0; k < 64; k++) {
        float bv = B[j * LD + k];
#pragma unroll
        for (int i = 0; i < 16; i++) acc[i] = fmaf(A[(ib + i) * LD + k], bv, acc[i]);
    }
#pragma unroll
    for (int i = 0; i < 16; i++) gout[(ib + i) * 64 + j] = acc[i];
}
// atomicAdd(gacc, scale * A * B^T)
__device__ __forceinline__ void smm_bt_atomic(const float* A, const float* B,
                                              float* __restrict__ gacc, float scale) {
    int j  = threadIdx.x & 63;
    int ib = (threadIdx.x >> 6) << 4;
    float acc[16];
#pragma unroll
    for (int i = 0; i < 16; i++) acc[i] = 0.f;
    for (int k = 0; k < 64; k++) {
        float bv = B[j * LD + k];
#pragma unroll
        for (int i = 0; i < 16; i++) acc[i] = fmaf(A[(ib + i) * LD + k], bv, acc[i]);
    }
#pragma unroll
    for (int i = 0; i < 16; i++) atomicAdd(&gacc[(ib + i) * 64 + j], acc[i] * scale);
}
// O[i][k] = V[i][k] * w[k]
__device__ __forceinline__ void scalecols(const float* V, const float* w, float* O) {
    for (int idx = threadIdx.x; idx < NN; idx += TPB) {
        int i = idx >> 6, k = idx & 63;
        O[i * LD + k] = V[i * LD + k] * w[k];
    }
}

// tournament (round-robin) pairing: round r in [0,63), pair k in [0,32)
__device__ __forceinline__ void get_pair(int r, int k, int& p, int& q) {
    int a = (k == 0) ? 0 : 1 + (k - 1 + r) % 63;
    int b = 1 + (62 - k + r) % 63;
    p = a < b ? a : b;
    q = a < b ? b : a;
}

// parallel cyclic Jacobi on shared A (64x64, ld=LD); V accumulates eigenvectors.
// Post: diag(A) = eigenvalues, A = V diag VT.
__device__ void jacobi(float* A, float* V, int nsweeps) {
    int t = threadIdx.x;
    __shared__ float cs[32], sn[32];
    __shared__ uchar2 tab[63 * 32];
    // build pair table + init V
    for (int idx = t; idx < 63 * 32; idx += TPB) {
        int r = idx >> 5, k = idx & 31, p, q;
        get_pair(r, k, p, q);
        tab[idx] = make_uchar2((unsigned char)p, (unsigned char)q);
    }
    for (int idx = t; idx < NN; idx += TPB) {
        int i = idx >> 6, j = idx & 63;
        V[i * LD + j] = (i == j) ? 1.f : 0.f;
    }
    __syncthreads();
    for (int sw = 0; sw < nsweeps; ++sw) {
        for (int r = 0; r < 63; ++r) {
            const uchar2* trow = tab + (r << 5);
            if (t < 32) {
                uchar2 pq = trow[t];
                int pl = pq.x * LD, ql = pq.y * LD;
                float app = A[pl + pq.x], aqq = A[ql + pq.y], apq = A[pl + pq.y];
                float c, s;
                if (fabsf(apq) < 1e-30f) { c = 1.f; s = 0.f; }
                else {
                    float tau = (aqq - app) / (2.f * apq);
                    float tt  = copysignf(1.f, tau) / (fabsf(tau) + sqrtf(1.f + tau * tau));
                    c = rsqrtf(1.f + tt * tt);
                    s = tt * c;
                }
                cs[t] = c; sn[t] = s;
            }
            __syncthreads();
            // row phase: A <- J^T A   (lanes in a warp share k; j consecutive)
#pragma unroll
            for (int m = 0; m < 2048 / TPB; m++) {
                int w = t + m * TPB;
                int k = w >> 6, j = w & 63;
                uchar2 pq = trow[k];
                int pl = pq.x * LD + j, ql = pq.y * LD + j;
                float c = cs[k], s = sn[k];
                float ap = A[pl], aq = A[ql];
                A[pl] = c * ap - s * aq;
                A[ql] = fmaf(s, ap, c * aq);
            }
            __syncthreads();
            // col phase: A <- A J, V <- V J
#pragma unroll
            for (int m = 0; m < 2048 / TPB; m++) {
                int w = t + m * TPB;
                int k = w >> 6, i = w & 63;
                uchar2 pq = trow[k];
                int il = i * LD;
                int pl = il + pq.x, ql = il + pq.y;
                float c = cs[k], s = sn[k];
                float ap = A[pl], aq = A[ql];
                A[pl] = c * ap - s * aq;
                A[ql] = fmaf(s, ap, c * aq);
                float vp = V[pl], vq = V[ql];
                V[pl] = c * vp - s * vq;
                V[ql] = fmaf(s, vp, c * vq);
            }
            __syncthreads();
        }
    }
}

// ---------------------------------------------------------------------------
// kernels
// ---------------------------------------------------------------------------
__global__ void k_zero(int which) {
    int i = blockIdx.x * blockDim.x + threadIdx.x;
    if (i < NN) { if (which == 0) g_M[i] = 0.f; else g_T[i] = 0.f; }
}

// arithmetic mean accumulate: grid (NN/256, NCHUNK)
__global__ void k_mean_acc(const float* __restrict__ data, int per_chunk, float inv_nb) {
    int e = blockIdx.x * blockDim.x + threadIdx.x;   // 0..4095
    const float* p = data + (size_t)(blockIdx.y) * per_chunk * NN + e;
    float sum = 0.f;
#pragma unroll 8
    for (int i = 0; i < per_chunk; i++) sum += p[(size_t)i * NN];
    atomicAdd(&g_M[e], sum * inv_nb);
}

// eigh(M) -> g_Ms = M^{1/2}, g_Mi = M^{-1/2}   (single CTA; 4 buffers)
__global__ void __launch_bounds__(TPB) k_eig_M() {
    extern __shared__ float sm[];
    float* A  = sm;
    float* V  = sm + BUF;
    float* T1 = sm + 2 * BUF;
    float* T2 = sm + 3 * BUF;
    __shared__ float w1[64], w2[64];
    load_g2s(g_M, A);
    __syncthreads();
    sym_s(A);
    __syncthreads();
    jacobi(A, V, NSWEEP_S);
    int t = threadIdx.x;
    if (t < 64) {
        float w = fmaxf(A[t * LD + t], 1e-12f);
        w1[t] = sqrtf(w);
        w2[t] = rsqrtf(w);
    }
    __syncthreads();
    scalecols(V, w1, T1); __syncthreads();
    smm_bt(T1, V, T2);    __syncthreads();
    store_s2g(T2, g_Ms);
    __syncthreads();
    scalecols(V, w2, T1); __syncthreads();
    smm_bt(T1, V, T2);    __syncthreads();
    store_s2g(T2, g_Mi);
}

// per-matrix: C = Mi*data_b*Mi, eigh, T += logm(C)/nb.  3 smem buffers.
__global__ void __launch_bounds__(TPB, 4) k_batch_step(const float* __restrict__ data, float inv_nb) {
    extern __shared__ float sm[];
    float* s0 = sm;             // Mi, later V*diag(logw)
    float* s1 = sm + BUF;       // data, later A (eigh workspace)
    float* s2 = sm + 2 * BUF;   // Mi*D temp, later V
    __shared__ float lw[64];
    size_t b = blockIdx.x;
    load_g2s(g_Mi, s0);
    load_g2s(data + b * NN, s1);
    __syncthreads();
    smm(s0, s1, s2);    // s2 = Mi * D
    __syncthreads();
    smm(s2, s0, s1);    // s1 = Mi * D * Mi  (overwrites data copy; not an operand)
    __syncthreads();
    sym_s(s1);
    __syncthreads();
    jacobi(s1, s2, NSWEEP_B);   // s1 -> diag eigenvalues, s2 = V
    int t = threadIdx.x;
    if (t < 64) lw[t] = logf(fmaxf(s1[t * LD + t], 1e-12f));
    __syncthreads();
    scalecols(s2, lw, s0);                // s0 = V * diag(log w)
    __syncthreads();
    smm_bt_atomic(s0, s2, g_T, inv_nb);   // T += (V diag(logw) V^T)/nb
}

// eigh(T) -> E = expm(T); g_M = Ms * E * Ms   (single CTA; 4 buffers)
__global__ void __launch_bounds__(TPB) k_update_M() {
    extern __shared__ float sm[];
    float* A  = sm;
    float* V  = sm + BUF;
    float* T1 = sm + 2 * BUF;
    float* T2 = sm + 3 * BUF;
    __shared__ float ew[64];
    load_g2s(g_T, A);
    __syncthreads();
    sym_s(A);
    __syncthreads();
    jacobi(A, V, NSWEEP_S);
    int t = threadIdx.x;
    if (t < 64) ew[t] = expf(A[t * LD + t]);
    __syncthreads();
    scalecols(V, ew, T1); __syncthreads();
    smm_bt(T1, V, T2);    __syncthreads();   // T2 = E
    load_g2s(g_Ms, A);    __syncthreads();   // A = Ms
    smm(A, T2, T1);       __syncthreads();   // T1 = Ms*E
    smm_glob(T1, A, g_M);                    // M = Ms*E*Ms
}

// S = expm(sym(bias)/2);  g_W = S * G   (G = g_Mi)
__global__ void __launch_bounds__(TPB) k_bias(const float* __restrict__ bias) {
    extern __shared__ float sm[];
    float* A  = sm;
    float* V  = sm + BUF;
    float* T1 = sm + 2 * BUF;
    float* T2 = sm + 3 * BUF;
    __shared__ float ew[64];
    int t = threadIdx.x;
    for (int idx = t; idx < NN; idx += TPB) {
        int i = idx >> 6, j = idx & 63;
        A[i * LD + j] = 0.5f * (bias[i * 64 + j] + bias[j * 64 + i]);
    }
    __syncthreads();
    jacobi(A, V, NSWEEP_S);
    if (t < 64) ew[t] = expf(0.5f * A[t * LD + t]);
    __syncthreads();
    scalecols(V, ew, T1); __syncthreads();
    smm_bt(T1, V, T2);    __syncthreads();   // T2 = S
    load_g2s(g_Mi, A);    __syncthreads();   // A = G
    smm_glob(T2, A, g_W);                    // W = S*G
}

// out_b = W * data_b * W^T   (since (S G)^T = G S).  3 smem buffers.
__global__ void __launch_bounds__(TPB, 4) k_final(const float* __restrict__ data,
                                                  float* __restrict__ out) {
    extern __shared__ float sm[];
    float* sW = sm;
    float* sD = sm + BUF;
    float* sT = sm + 2 * BUF;
    size_t b = blockIdx.x;
    load_g2s(g_W, sW);
    load_g2s(data + b * NN, sD);
    __syncthreads();
    smm(sW, sD, sT);
    __syncthreads();
    smm_bt_glob(sT, sW, out + b * NN);
}

// ---------------------------------------------------------------------------
extern "C" void kernel_launch(void* const* d_in, const int* in_sizes, int n_in,
                              void* d_out, int out_size) {
    const float* data;
    const float* bias;
    int nb;
    if (in_sizes[0] >= in_sizes[1]) {
        data = (const float*)d_in[0]; bias = (const float*)d_in[1];
        nb = in_sizes[0] / NN;
    } else {
        data = (const float*)d_in[1]; bias = (const float*)d_in[0];
        nb = in_sizes[1] / NN;
    }
    float* out = (float*)d_out;
    float inv_nb = 1.0f / (float)nb;

    size_t smem4 = 4 * BUF * sizeof(float);   // 66560 B (single-CTA kernels)
    size_t smem3 = 3 * BUF * sizeof(float);   // 49920 B (batch kernels)
    cudaFuncSetAttribute(k_eig_M,      cudaFuncAttributeMaxDynamicSharedMemorySize, (int)smem4);
    cudaFuncSetAttribute(k_batch_step, cudaFuncAttributeMaxDynamicSharedMemorySize, (int)smem3);
    cudaFuncSetAttribute(k_update_M,   cudaFuncAttributeMaxDynamicSharedMemorySize, (int)smem4);
    cudaFuncSetAttribute(k_bias,       cudaFuncAttributeMaxDynamicSharedMemorySize, (int)smem4);
    cudaFuncSetAttribute(k_final,      cudaFuncAttributeMaxDynamicSharedMemorySize, (int)smem3);

    // arithmetic mean
    k_zero<<<16, 256>>>(0);
    {
        int nchunk = 64;
        while (nchunk > 1 && (nb % nchunk) != 0) nchunk >>= 1;
        int per_chunk = nb / nchunk;
        dim3 g(NN / 256, nchunk);
        k_mean_acc<<<g, 256>>>(data, per_chunk, inv_nb);
    }

    // 3 Karcher iterations
    for (int it = 0; it < 3; ++it) {
        k_eig_M<<<1, TPB, smem4>>>();
        k_zero<<<16, 256>>>(1);
        k_batch_step<<<nb, TPB, smem3>>>(data, inv_nb);
        k_update_M<<<1, TPB, smem4>>>();
    }

    // final whitening transform + bias congruence
    k_eig_M<<<1, TPB, smem4>>>();        // g_Mi = G = mean^{-1/2}
    k_bias<<<1, TPB, smem4>>>(bias);     // g_W = S*G
    k_final<<<nb, TPB, smem3>>>(data, out);
}

// round 4
// speedup vs baseline: 3.2287x; 1.5807x over previous
#include <cuda_runtime.h>
#include <cuda_bf16.h>
#include <math.h>

// ============================================================================
// BatchNormSPDMean: affine-invariant Karcher mean (3 iters) + whitening + bias
// R4: batched eigh -> ONE-SIDED Jacobi (no V matrix, 3x less smem traffic),
//     float4 column ops, 8-lane-per-pair shuffle dots, converged-pair skip.
// ============================================================================

#define NN 4096
#define LD 65                 // padded row stride for row-major buffers
#define NSWEEP_B 8            // one-sided Jacobi sweeps (batched)
#define NSWEEP_S 10           // two-sided sweeps for single-matrix eigh
#define TPB 256
#define BUF 4160              // 64*65 floats per row-major buffer

// ---- persistent scratch ----
__device__ float g_M [NN];
__device__ float g_Ms[NN];
__device__ float g_Mi[NN];
__device__ float g_T [NN];
__device__ float g_W [NN];

// ---------------------------------------------------------------------------
__device__ __forceinline__ void load_g2s(const float* __restrict__ g, float* S) {
    for (int idx = threadIdx.x; idx < NN; idx += TPB)
        S[(idx >> 6) * LD + (idx & 63)] = g[idx];
}
__device__ __forceinline__ void store_s2g(const float* S, float* __restrict__ g) {
    for (int idx = threadIdx.x; idx < NN; idx += TPB)
        g[idx] = S[(idx >> 6) * LD + (idx & 63)];
}
__device__ __forceinline__ void sym_s(float* A) {
    for (int idx = threadIdx.x; idx < NN; idx += TPB) {
        int i = idx >> 6, j = idx & 63;
        if (i < j) {
            float v = 0.5f * (A[i * LD + j] + A[j * LD + i]);
            A[i * LD + j] = v;
            A[j * LD + i] = v;
        }
    }
}
// C = A * B   (row-major LD). 256 threads: 4 row-groups x 16 rows.
__device__ __forceinline__ void smm(const float* A, const float* B, float* C) {
    int j  = threadIdx.x & 63;
    int ib = (threadIdx.x >> 6) << 4;
    float acc[16];
#pragma unroll
    for (int i = 0; i < 16; i++) acc[i] = 0.f;
    for (int k = 0; k < 64; k++) {
        float bv = B[k * LD + j];
#pragma unroll
        for (int i = 0; i < 16; i++) acc[i] = fmaf(A[(ib + i) * LD + k], bv, acc[i]);
    }
#pragma unroll
    for (int i = 0; i < 16; i++) C[(ib + i) * LD + j] = acc[i];
}
__device__ __forceinline__ void smm_bt(const float* A, const float* B, float* C) {
    int j  = threadIdx.x & 63;
    int ib = (threadIdx.x >> 6) << 4;
    float acc[16];
#pragma unroll
    for (int i = 0; i < 16; i++) acc[i] = 0.f;
    for (int k = 0; k < 64; k++) {
        float bv = B[j * LD + k];
#pragma unroll
        for (int i = 0; i < 16; i++) acc[i] = fmaf(A[(ib + i) * LD + k], bv, acc[i]);
    }
#pragma unroll
    for (int i = 0; i < 16; i++) C[(ib + i) * LD + j] = acc[i];
}
__device__ __forceinline__ void smm_glob(const float* A, const float* B, float* __restrict__ gout) {
    int j  = threadIdx.x & 63;
    int ib = (threadIdx.x >> 6) << 4;
    float acc[16];
#pragma unroll
    for (int i = 0; i < 16; i++) acc[i] = 0.f;
    for (int k = 0; k < 64; k++) {
        float bv = B[k * LD + j];
#pragma unroll
        for (int i = 0; i < 16; i++) acc[i] = fmaf(A[(ib + i) * LD + k], bv, acc[i]);
    }
#pragma unroll
    for (int i = 0; i < 16; i++) gout[(ib + i) * 64 + j] = acc[i];
}
__device__ __forceinline__ void smm_bt_glob(const float* A, const float* B, float* __restrict__ gout) {
    int j  = threadIdx.x & 63;
    int ib = (threadIdx.x >> 6) << 4;
    float acc[16];
#pragma unroll
    for (int i = 0; i < 16; i++) acc[i] = 0.f;
    for (int k = 0; k < 64; k++) {
        float bv = B[j * LD + k];
#pragma unroll
        for (int i = 0; i < 16; i++) acc[i] = fmaf(A[(ib + i) * LD + k], bv, acc[i]);
    }
#pragma unroll
    for (int i = 0; i < 16; i++) gout[(ib + i) * 64 + j] = acc[i];
}
__device__ __forceinline__ void scalecols(const float* V, const float* w, float* O) {
    for (int idx = threadIdx.x; idx < NN; idx += TPB) {
        int i = idx >> 6, k = idx & 63;
        O[i * LD + k] = V[i * LD + k] * w[k];
    }
}

// tournament pairing
__device__ __forceinline__ void get_pair(int r, int k, int& p, int& q) {
    int a = (k == 0) ? 0 : 1 + (k - 1 + r) % 63;
    int b = 1 + (62 - k + r) % 63;
    p = a < b ? a : b;
    q = a < b ? b : a;
}

__device__ __forceinline__ float dot4(float4 a, float4 b) {
    return fmaf(a.x, b.x, fmaf(a.y, b.y, fmaf(a.z, b.z, a.w * b.w)));
}

// ---------------------------------------------------------------------------
// TWO-SIDED Jacobi (single-matrix kernels only; cost negligible)
// ---------------------------------------------------------------------------
__device__ void jacobi2s(float* A, float* V, int nsweeps) {
    int t = threadIdx.x;
    __shared__ float cs[32], sn[32];
    __shared__ uchar2 tab2[63 * 32];
    for (int idx = t; idx < 63 * 32; idx += TPB) {
        int r = idx >> 5, k = idx & 31, p, q;
        get_pair(r, k, p, q);
        tab2[idx] = make_uchar2((unsigned char)p, (unsigned char)q);
    }
    for (int idx = t; idx < NN; idx += TPB) {
        int i = idx >> 6, j = idx & 63;
        V[i * LD + j] = (i == j) ? 1.f : 0.f;
    }
    __syncthreads();
    for (int sw = 0; sw < nsweeps; ++sw) {
        for (int r = 0; r < 63; ++r) {
            const uchar2* trow = tab2 + (r << 5);
            if (t < 32) {
                uchar2 pq = trow[t];
                int pl = pq.x * LD, ql = pq.y * LD;
                float app = A[pl + pq.x], aqq = A[ql + pq.y], apq = A[pl + pq.y];
                float c, s;
                if (fabsf(apq) < 1e-30f) { c = 1.f; s = 0.f; }
                else {
                    float tau = (aqq - app) / (2.f * apq);
                    float tt  = copysignf(1.f, tau) / (fabsf(tau) + sqrtf(1.f + tau * tau));
                    c = rsqrtf(1.f + tt * tt);
                    s = tt * c;
                }
                cs[t] = c; sn[t] = s;
            }
            __syncthreads();
#pragma unroll
            for (int m = 0; m < 2048 / TPB; m++) {
                int w = t + m * TPB;
                int k = w >> 6, j = w & 63;
                uchar2 pq = trow[k];
                int pl = pq.x * LD + j, ql = pq.y * LD + j;
                float c = cs[k], s = sn[k];
                float ap = A[pl], aq = A[ql];
                A[pl] = c * ap - s * aq;
                A[ql] = fmaf(s, ap, c * aq);
            }
            __syncthreads();
#pragma unroll
            for (int m = 0; m < 2048 / TPB; m++) {
                int w = t + m * TPB;
                int k = w >> 6, i = w & 63;
                uchar2 pq = trow[k];
                int il = i * LD;
                int pl = il + pq.x, ql = il + pq.y;
                float c = cs[k], s = sn[k];
                float ap = A[pl], aq = A[ql];
                A[pl] = c * ap - s * aq;
                A[ql] = fmaf(s, ap, c * aq);
                float vp = V[pl], vq = V[ql];
                V[pl] = c * vp - s * vq;
                V[ql] = fmaf(s, vp, c * vq);
            }
            __syncthreads();
        }
    }
}

// ---------------------------------------------------------------------------
// ONE-SIDED Jacobi on column-major B (64 cols x 64 rows, contiguous cols).
// 8 warps x 4 pairs, 8 lanes per pair, float4 columns. One barrier per round.
// Post: columns of B are lambda_k * u_k (orthogonal).
// ---------------------------------------------------------------------------
__device__ void jacobi1s(float* B, const uchar2* tab, int nsweeps) {
    int lane = threadIdx.x & 31;
    int warp = threadIdx.x >> 5;
    int grp  = lane >> 3;      // pair index within warp (0..3)
    int sub  = lane & 7;       // lane within pair (0..7) -> rows [sub*8, sub*8+8)
    for (int sw = 0; sw < nsweeps; ++sw) {
        for (int r = 0; r < 63; ++r) {
            uchar2 pq = tab[(r << 5) + (warp << 2) + grp];
            float4* colp = reinterpret_cast<float4*>(B + pq.x * 64);
            float4* colq = reinterpret_cast<float4*>(B + pq.y * 64);
            float4 p0 = colp[sub * 2], p1 = colp[sub * 2 + 1];
            float4 q0 = colq[sub * 2], q1 = colq[sub * 2 + 1];
            float app = dot4(p0, p0) + dot4(p1, p1);
            float aqq = dot4(q0, q0) + dot4(q1, q1);
            float apq = dot4(p0, q0) + dot4(p1, q1);
#pragma unroll
            for (int d = 1; d < 8; d <<= 1) {
                app += __shfl_xor_sync(0xffffffffu, app, d);
                aqq += __shfl_xor_sync(0xffffffffu, aqq, d);
                apq += __shfl_xor_sync(0xffffffffu, apq, d);
            }
            if (apq * apq > 1e-14f * app * aqq) {
                float tau = (aqq - app) / (2.f * apq);
                float tt  = copysignf(1.f, tau) / (fabsf(tau) + sqrtf(1.f + tau * tau));
                float c = rsqrtf(1.f + tt * tt);
                float s = tt * c;
                float4 a, b;
                a.x = c*p0.x - s*q0.x; b.x = fmaf(s, p0.x, c*q0.x);
                a.y = c*p0.y - s*q0.y; b.y = fmaf(s, p0.y, c*q0.y);
                a.z = c*p0.z - s*q0.z; b.z = fmaf(s, p0.z, c*q0.z);
                a.w = c*p0.w - s*q0.w; b.w = fmaf(s, p0.w, c*q0.w);
                colp[sub * 2] = a;  colq[sub * 2] = b;
                a.x = c*p1.x - s*q1.x; b.x = fmaf(s, p1.x, c*q1.x);
                a.y = c*p1.y - s*q1.y; b.y = fmaf(s, p1.y, c*q1.y);
                a.z = c*p1.z - s*q1.z; b.z = fmaf(s, p1.z, c*q1.z);
                a.w = c*p1.w - s*q1.w; b.w = fmaf(s, p1.w, c*q1.w);
                colp[sub * 2 + 1] = a;  colq[sub * 2 + 1] = b;
            }
            __syncthreads();
        }
    }
}

// ---------------------------------------------------------------------------
// kernels
// ---------------------------------------------------------------------------
__global__ void k_zero(int which) {
    int i = blockIdx.x * blockDim.x + threadIdx.x;
    if (i < NN) { if (which == 0) g_M[i] = 0.f; else g_T[i] = 0.f; }
}

__global__ void k_mean_acc(const float* __restrict__ data, int per_chunk, float inv_nb) {
    int e = blockIdx.x * blockDim.x + threadIdx.x;
    const float* p = data + (size_t)(blockIdx.y) * per_chunk * NN + e;
    float sum = 0.f;
#pragma unroll 8
    for (int i = 0; i < per_chunk; i++) sum += p[(size_t)i * NN];
    atomicAdd(&g_M[e], sum * inv_nb);
}

// eigh(M) -> g_Ms = M^{1/2}, g_Mi = M^{-1/2}  (single CTA, two-sided)
__global__ void __launch_bounds__(TPB) k_eig_M() {
    extern __shared__ float sm[];
    float* A  = sm;
    float* V  = sm + BUF;
    float* T1 = sm + 2 * BUF;
    float* T2 = sm + 3 * BUF;
    __shared__ float w1[64], w2[64];
    load_g2s(g_M, A);
    __syncthreads();
    sym_s(A);
    __syncthreads();
    jacobi2s(A, V, NSWEEP_S);
    int t = threadIdx.x;
    if (t < 64) {
        float w = fmaxf(A[t * LD + t], 1e-12f);
        w1[t] = sqrtf(w);
        w2[t] = rsqrtf(w);
    }
    __syncthreads();
    scalecols(V, w1, T1); __syncthreads();
    smm_bt(T1, V, T2);    __syncthreads();
    store_s2g(T2, g_Ms);
    __syncthreads();
    scalecols(V, w2, T1); __syncthreads();
    smm_bt(T1, V, T2);    __syncthreads();
    store_s2g(T2, g_Mi);
}

// per-matrix: C = Mi*D*Mi; one-sided Jacobi; T += logm(C)/nb
__global__ void __launch_bounds__(TPB, 4) k_batch_step(const float* __restrict__ data, float inv_nb) {
    extern __shared__ float sm[];
    float* s0 = sm;             // Mi -> W (col-major, scaled)
    float* s1 = sm + BUF;       // D  -> C (row-major LD)
    float* s2 = sm + 2 * BUF;   // T1 -> B (col-major 64, Jacobi workspace)
    __shared__ uchar2 tab[63 * 32];
    int t = threadIdx.x;
    for (int idx = t; idx < 63 * 32; idx += TPB) {
        int r = idx >> 5, k = idx & 31, p, q;
        get_pair(r, k, p, q);
        tab[idx] = make_uchar2((unsigned char)p, (unsigned char)q);
    }
    size_t b = blockIdx.x;
    load_g2s(g_Mi, s0);
    load_g2s(data + b * NN, s1);
    __syncthreads();
    smm(s0, s1, s2);    // s2 = Mi * D
    __syncthreads();
    smm(s2, s0, s1);    // s1 = C = Mi * D * Mi  (row-major)
    __syncthreads();
    // symmetrize C into column-major contiguous B (s2)
    for (int idx = t; idx < NN; idx += TPB) {
        int c = idx >> 6, r2 = idx & 63;
        s2[idx] = 0.5f * (s1[r2 * LD + c] + s1[c * LD + r2]);
    }
    __syncthreads();
    jacobi1s(s2, tab, NSWEEP_B);     // columns -> lambda_k * u_k
    // per-column: nrm2 = lambda^2, g = log(lambda)/lambda^2 = 0.5*log(nrm2)/nrm2
    // W[:,k] = B[:,k] * g_k   (into s0)
    {
        int col = t >> 2, qc = t & 3;    // 64 cols x 4 quarters of 16 floats
        const float4* bc = reinterpret_cast<const float4*>(s2 + col * 64);
        float4 v0 = bc[qc * 4 + 0], v1 = bc[qc * 4 + 1];
        float4 v2 = bc[qc * 4 + 2], v3 = bc[qc * 4 + 3];
        float pn = dot4(v0, v0) + dot4(v1, v1) + dot4(v2, v2) + dot4(v3, v3);
        pn += __shfl_xor_sync(0xffffffffu, pn, 1);
        pn += __shfl_xor_sync(0xffffffffu, pn, 2);
        float nrm2 = fmaxf(pn, 1e-24f);
        float g = 0.5f * logf(nrm2) / nrm2;
        float4* wc = reinterpret_cast<float4*>(s0 + col * 64);
        v0.x *= g; v0.y *= g; v0.z *= g; v0.w *= g;
        v1.x *= g; v1.y *= g; v1.z *= g; v1.w *= g;
        v2.x *= g; v2.y *= g; v2.z *= g; v2.w *= g;
        v3.x *= g; v3.y *= g; v3.z *= g; v3.w *= g;
        wc[qc * 4 + 0] = v0; wc[qc * 4 + 1] = v1;
        wc[qc * 4 + 2] = v2; wc[qc * 4 + 3] = v3;
    }
    __syncthreads();
    // logm(C)[i][j] = sum_k W[k*64+i] * B[k*64+j];  T += logm/nb
    {
        int j  = t & 63;
        int ib = (t >> 6) << 4;
        float acc[16];
#pragma unroll
        for (int i = 0; i < 16; i++) acc[i] = 0.f;
        for (int k = 0; k < 64; k++) {
            float bj = s2[k * 64 + j];
#pragma unroll
            for (int i = 0; i < 16; i++) acc[i] = fmaf(s0[k * 64 + ib + i], bj, acc[i]);
        }
#pragma unroll
        for (int i = 0; i < 16; i++) atomicAdd(&g_T[(ib + i) * 64 + j], acc[i] * inv_nb);
    }
}

// eigh(T) -> E = expm(T); g_M = Ms * E * Ms
__global__ void __launch_bounds__(TPB) k_update_M() {
    extern __shared__ float sm[];
    float* A  = sm;
    float* V  = sm + BUF;
    float* T1 = sm + 2 * BUF;
    float* T2 = sm + 3 * BUF;
    __shared__ float ew[64];
    load_g2s(g_T, A);
    __syncthreads();
    sym_s(A);
    __syncthreads();
    jacobi2s(A, V, NSWEEP_S);
    int t = threadIdx.x;
    if (t < 64) ew[t] = expf(A[t * LD + t]);
    __syncthreads();
    scalecols(V, ew, T1); __syncthreads();
    smm_bt(T1, V, T2);    __syncthreads();   // T2 = E
    load_g2s(g_Ms, A);    __syncthreads();
    smm(A, T2, T1);       __syncthreads();
    smm_glob(T1, A, g_M);
}

// S = expm(sym(bias)/2);  g_W = S * G
__global__ void __launch_bounds__(TPB) k_bias(const float* __restrict__ bias) {
    extern __shared__ float sm[];
    float* A  = sm;
    float* V  = sm + BUF;
    float* T1 = sm + 2 * BUF;
    float* T2 = sm + 3 * BUF;
    __shared__ float ew[64];
    int t = threadIdx.x;
    for (int idx = t; idx < NN; idx += TPB) {
        int i = idx >> 6, j = idx & 63;
        A[i * LD + j] = 0.5f * (bias[i * 64 + j] + bias[j * 64 + i]);
    }
    __syncthreads();
    jacobi2s(A, V, NSWEEP_S);
    if (t < 64) ew[t] = expf(0.5f * A[t * LD + t]);
    __syncthreads();
    scalecols(V, ew, T1); __syncthreads();
    smm_bt(T1, V, T2);    __syncthreads();   // T2 = S
    load_g2s(g_Mi, A);    __syncthreads();
    smm_glob(T2, A, g_W);
}

// out_b = W * data_b * W^T
__global__ void __launch_bounds__(TPB, 4) k_final(const float* __restrict__ data,
                                                  float* __restrict__ out) {
    extern __shared__ float sm[];
    float* sW = sm;
    float* sD = sm + BUF;
    float* sT = sm + 2 * BUF;
    size_t b = blockIdx.x;
    load_g2s(g_W, sW);
    load_g2s(data + b * NN, sD);
    __syncthreads();
    smm(sW, sD, sT);
    __syncthreads();
    smm_bt_glob(sT, sW, out + b * NN);
}

// ---------------------------------------------------------------------------
extern "C" void kernel_launch(void* const* d_in, const int* in_sizes, int n_in,
                              void* d_out, int out_size) {
    const float* data;
    const float* bias;
    int nb;
    if (in_sizes[0] >= in_sizes[1]) {
        data = (const float*)d_in[0]; bias = (const float*)d_in[1];
        nb = in_sizes[0] / NN;
    } else {
        data = (const float*)d_in[1]; bias = (const float*)d_in[0];
        nb = in_sizes[1] / NN;
    }
    float* out = (float*)d_out;
    float inv_nb = 1.0f / (float)nb;

    size_t smem4 = 4 * BUF * sizeof(float);   // single-CTA kernels
    size_t smem3 = 3 * BUF * sizeof(float);   // batch kernels
    cudaFuncSetAttribute(k_eig_M,      cudaFuncAttributeMaxDynamicSharedMemorySize, (int)smem4);
    cudaFuncSetAttribute(k_batch_step, cudaFuncAttributeMaxDynamicSharedMemorySize, (int)smem3);
    cudaFuncSetAttribute(k_update_M,   cudaFuncAttributeMaxDynamicSharedMemorySize, (int)smem4);
    cudaFuncSetAttribute(k_bias,       cudaFuncAttributeMaxDynamicSharedMemorySize, (int)smem4);
    cudaFuncSetAttribute(k_final,      cudaFuncAttributeMaxDynamicSharedMemorySize, (int)smem3);

    // arithmetic mean
    k_zero<<<16, 256>>>(0);
    {
        int nchunk = 64;
        while (nchunk > 1 && (nb % nchunk) != 0) nchunk >>= 1;
        int per_chunk = nb / nchunk;
        dim3 g(NN / 256, nchunk);
        k_mean_acc<<<g, 256>>>(data, per_chunk, inv_nb);
    }

    // 3 Karcher iterations
    for (int it = 0; it < 3; ++it) {
        k_eig_M<<<1, TPB, smem4>>>();
        k_zero<<<16, 256>>>(1);
        k_batch_step<<<nb, TPB, smem3>>>(data, inv_nb);
        k_update_M<<<1, TPB, smem4>>>();
    }

    // final whitening + bias congruence
    k_eig_M<<<1, TPB, smem4>>>();
    k_bias<<<1, TPB, smem4>>>(bias);
    k_final<<<nb, TPB, smem3>>>(data, out);
}

// round 5
// speedup vs baseline: 4.7234x; 1.4629x over previous
#include <cuda_runtime.h>
#include <cuda_bf16.h>
#include <math.h>

// ============================================================================
// BatchNormSPDMean: affine-invariant Karcher mean (3 iters) + whitening + bias
// R5: conflict-free lane->row mapping in one-sided Jacobi (LDS.128 at 4-cyc
//     floor), sweeps 8->7, fast divide in rotation.
// ============================================================================

#define NN 4096
#define LD 65                 // padded row stride for row-major buffers
#define NSWEEP_B 7            // one-sided Jacobi sweeps (batched)
#define NSWEEP_S 10           // two-sided sweeps for single-matrix eigh
#define TPB 256
#define BUF 4160              // 64*65 floats per row-major buffer

// ---- persistent scratch ----
__device__ float g_M [NN];
__device__ float g_Ms[NN];
__device__ float g_Mi[NN];
__device__ float g_T [NN];
__device__ float g_W [NN];

// ---------------------------------------------------------------------------
__device__ __forceinline__ void load_g2s(const float* __restrict__ g, float* S) {
    for (int idx = threadIdx.x; idx < NN; idx += TPB)
        S[(idx >> 6) * LD + (idx & 63)] = g[idx];
}
__device__ __forceinline__ void store_s2g(const float* S, float* __restrict__ g) {
    for (int idx = threadIdx.x; idx < NN; idx += TPB)
        g[idx] = S[(idx >> 6) * LD + (idx & 63)];
}
__device__ __forceinline__ void sym_s(float* A) {
    for (int idx = threadIdx.x; idx < NN; idx += TPB) {
        int i = idx >> 6, j = idx & 63;
        if (i < j) {
            float v = 0.5f * (A[i * LD + j] + A[j * LD + i]);
            A[i * LD + j] = v;
            A[j * LD + i] = v;
        }
    }
}
// C = A * B   (row-major LD). 256 threads: 4 row-groups x 16 rows.
__device__ __forceinline__ void smm(const float* A, const float* B, float* C) {
    int j  = threadIdx.x & 63;
    int ib = (threadIdx.x >> 6) << 4;
    float acc[16];
#pragma unroll
    for (int i = 0; i < 16; i++) acc[i] = 0.f;
    for (int k = 0; k < 64; k++) {
        float bv = B[k * LD + j];
#pragma unroll
        for (int i = 0; i < 16; i++) acc[i] = fmaf(A[(ib + i) * LD + k], bv, acc[i]);
    }
#pragma unroll
    for (int i = 0; i < 16; i++) C[(ib + i) * LD + j] = acc[i];
}
__device__ __forceinline__ void smm_bt(const float* A, const float* B, float* C) {
    int j  = threadIdx.x & 63;
    int ib = (threadIdx.x >> 6) << 4;
    float acc[16];
#pragma unroll
    for (int i = 0; i < 16; i++) acc[i] = 0.f;
    for (int k = 0; k < 64; k++) {
        float bv = B[j * LD + k];
#pragma unroll
        for (int i = 0; i < 16; i++) acc[i] = fmaf(A[(ib + i) * LD + k], bv, acc[i]);
    }
#pragma unroll
    for (int i = 0; i < 16; i++) C[(ib + i) * LD + j] = acc[i];
}
__device__ __forceinline__ void smm_glob(const float* A, const float* B, float* __restrict__ gout) {
    int j  = threadIdx.x & 63;
    int ib = (threadIdx.x >> 6) << 4;
    float acc[16];
#pragma unroll
    for (int i = 0; i < 16; i++) acc[i] = 0.f;
    for (int k = 0; k < 64; k++) {
        float bv = B[k * LD + j];
#pragma unroll
        for (int i = 0; i < 16; i++) acc[i] = fmaf(A[(ib + i) * LD + k], bv, acc[i]);
    }
#pragma unroll
    for (int i = 0; i < 16; i++) gout[(ib + i) * 64 + j] = acc[i];
}
__device__ __forceinline__ void smm_bt_glob(const float* A, const float* B, float* __restrict__ gout) {
    int j  = threadIdx.x & 63;
    int ib = (threadIdx.x >> 6) << 4;
    float acc[16];
#pragma unroll
    for (int i = 0; i < 16; i++) acc[i] = 0.f;
    for (int k = 0; k < 64; k++) {
        float bv = B[j * LD + k];
#pragma unroll
        for (int i = 0; i < 16; i++) acc[i] = fmaf(A[(ib + i) * LD + k], bv, acc[i]);
    }
#pragma unroll
    for (int i = 0; i < 16; i++) gout[(ib + i) * 64 + j] = acc[i];
}
__device__ __forceinline__ void scalecols(const float* V, const float* w, float* O) {
    for (int idx = threadIdx.x; idx < NN; idx += TPB) {
        int i = idx >> 6, k = idx & 63;
        O[i * LD + k] = V[i * LD + k] * w[k];
    }
}

// tournament pairing
__device__ __forceinline__ void get_pair(int r, int k, int& p, int& q) {
    int a = (k == 0) ? 0 : 1 + (k - 1 + r) % 63;
    int b = 1 + (62 - k + r) % 63;
    p = a < b ? a : b;
    q = a < b ? b : a;
}

__device__ __forceinline__ float dot4(float4 a, float4 b) {
    return fmaf(a.x, b.x, fmaf(a.y, b.y, fmaf(a.z, b.z, a.w * b.w)));
}

// ---------------------------------------------------------------------------
// TWO-SIDED Jacobi (single-matrix kernels only; cost negligible)
// ---------------------------------------------------------------------------
__device__ void jacobi2s(float* A, float* V, int nsweeps) {
    int t = threadIdx.x;
    __shared__ float cs[32], sn[32];
    __shared__ uchar2 tab2[63 * 32];
    for (int idx = t; idx < 63 * 32; idx += TPB) {
        int r = idx >> 5, k = idx & 31, p, q;
        get_pair(r, k, p, q);
        tab2[idx] = make_uchar2((unsigned char)p, (unsigned char)q);
    }
    for (int idx = t; idx < NN; idx += TPB) {
        int i = idx >> 6, j = idx & 63;
        V[i * LD + j] = (i == j) ? 1.f : 0.f;
    }
    __syncthreads();
    for (int sw = 0; sw < nsweeps; ++sw) {
        for (int r = 0; r < 63; ++r) {
            const uchar2* trow = tab2 + (r << 5);
            if (t < 32) {
                uchar2 pq = trow[t];
                int pl = pq.x * LD, ql = pq.y * LD;
                float app = A[pl + pq.x], aqq = A[ql + pq.y], apq = A[pl + pq.y];
                float c, s;
                if (fabsf(apq) < 1e-30f) { c = 1.f; s = 0.f; }
                else {
                    float tau = (aqq - app) / (2.f * apq);
                    float tt  = copysignf(1.f, tau) / (fabsf(tau) + sqrtf(1.f + tau * tau));
                    c = rsqrtf(1.f + tt * tt);
                    s = tt * c;
                }
                cs[t] = c; sn[t] = s;
            }
            __syncthreads();
#pragma unroll
            for (int m = 0; m < 2048 / TPB; m++) {
                int w = t + m * TPB;
                int k = w >> 6, j = w & 63;
                uchar2 pq = trow[k];
                int pl = pq.x * LD + j, ql = pq.y * LD + j;
                float c = cs[k], s = sn[k];
                float ap = A[pl], aq = A[ql];
                A[pl] = c * ap - s * aq;
                A[ql] = fmaf(s, ap, c * aq);
            }
            __syncthreads();
#pragma unroll
            for (int m = 0; m < 2048 / TPB; m++) {
                int w = t + m * TPB;
                int k = w >> 6, i = w & 63;
                uchar2 pq = trow[k];
                int il = i * LD;
                int pl = il + pq.x, ql = il + pq.y;
                float c = cs[k], s = sn[k];
                float ap = A[pl], aq = A[ql];
                A[pl] = c * ap - s * aq;
                A[ql] = fmaf(s, ap, c * aq);
                float vp = V[pl], vq = V[ql];
                V[pl] = c * vp - s * vq;
                V[ql] = fmaf(s, vp, c * vq);
            }
            __syncthreads();
        }
    }
}

// ---------------------------------------------------------------------------
// ONE-SIDED Jacobi on column-major B (64 cols, contiguous, stride 64).
// 8 warps x 4 pairs; 8 lanes/pair. Lane sub handles rows [4*sub,4*sub+4) and
// [32+4*sub, 32+4*sub+4): each quarter-warp phase covers all 32 banks once ->
// conflict-free LDS.128/STS.128.
// Post: columns of B are lambda_k * u_k (orthogonal).
// ---------------------------------------------------------------------------
__device__ void jacobi1s(float* B, const uchar2* tab, int nsweeps) {
    int lane = threadIdx.x & 31;
    int warp = threadIdx.x >> 5;
    int grp  = lane >> 3;      // pair index within warp (0..3)
    int sub  = lane & 7;       // lane within pair
    for (int sw = 0; sw < nsweeps; ++sw) {
        for (int r = 0; r < 63; ++r) {
            uchar2 pq = tab[(r << 5) + (warp << 2) + grp];
            float4* colp = reinterpret_cast<float4*>(B + pq.x * 64);
            float4* colq = reinterpret_cast<float4*>(B + pq.y * 64);
            float4 p0 = colp[sub], p1 = colp[sub + 8];
            float4 q0 = colq[sub], q1 = colq[sub + 8];
            float app = dot4(p0, p0) + dot4(p1, p1);
            float aqq = dot4(q0, q0) + dot4(q1, q1);
            float apq = dot4(p0, q0) + dot4(p1, q1);
#pragma unroll
            for (int d = 1; d < 8; d <<= 1) {
                app += __shfl_xor_sync(0xffffffffu, app, d);
                aqq += __shfl_xor_sync(0xffffffffu, aqq, d);
                apq += __shfl_xor_sync(0xffffffffu, apq, d);
            }
            if (apq * apq > 1e-14f * app * aqq) {
                float tau = __fdividef(aqq - app, 2.f * apq);
                float tt  = copysignf(1.f, tau) / (fabsf(tau) + sqrtf(1.f + tau * tau));
                float c = rsqrtf(1.f + tt * tt);
                float s = tt * c;
                float4 a, b;
                a.x = c*p0.x - s*q0.x; b.x = fmaf(s, p0.x, c*q0.x);
                a.y = c*p0.y - s*q0.y; b.y = fmaf(s, p0.y, c*q0.y);
                a.z = c*p0.z - s*q0.z; b.z = fmaf(s, p0.z, c*q0.z);
                a.w = c*p0.w - s*q0.w; b.w = fmaf(s, p0.w, c*q0.w);
                colp[sub] = a;  colq[sub] = b;
                a.x = c*p1.x - s*q1.x; b.x = fmaf(s, p1.x, c*q1.x);
                a.y = c*p1.y - s*q1.y; b.y = fmaf(s, p1.y, c*q1.y);
                a.z = c*p1.z - s*q1.z; b.z = fmaf(s, p1.z, c*q1.z);
                a.w = c*p1.w - s*q1.w; b.w = fmaf(s, p1.w, c*q1.w);
                colp[sub + 8] = a;  colq[sub + 8] = b;
            }
            __syncthreads();
        }
    }
}

// ---------------------------------------------------------------------------
// kernels
// ---------------------------------------------------------------------------
__global__ void k_zero(int which) {
    int i = blockIdx.x * blockDim.x + threadIdx.x;
    if (i < NN) { if (which == 0) g_M[i] = 0.f; else g_T[i] = 0.f; }
}

__global__ void k_mean_acc(const float* __restrict__ data, int per_chunk, float inv_nb) {
    int e = blockIdx.x * blockDim.x + threadIdx.x;
    const float* p = data + (size_t)(blockIdx.y) * per_chunk * NN + e;
    float sum = 0.f;
#pragma unroll 8
    for (int i = 0; i < per_chunk; i++) sum += p[(size_t)i * NN];
    atomicAdd(&g_M[e], sum * inv_nb);
}

// eigh(M) -> g_Ms = M^{1/2}, g_Mi = M^{-1/2}  (single CTA, two-sided)
__global__ void __launch_bounds__(TPB) k_eig_M() {
    extern __shared__ float sm[];
    float* A  = sm;
    float* V  = sm + BUF;
    float* T1 = sm + 2 * BUF;
    float* T2 = sm + 3 * BUF;
    __shared__ float w1[64], w2[64];
    load_g2s(g_M, A);
    __syncthreads();
    sym_s(A);
    __syncthreads();
    jacobi2s(A, V, NSWEEP_S);
    int t = threadIdx.x;
    if (t < 64) {
        float w = fmaxf(A[t * LD + t], 1e-12f);
        w1[t] = sqrtf(w);
        w2[t] = rsqrtf(w);
    }
    __syncthreads();
    scalecols(V, w1, T1); __syncthreads();
    smm_bt(T1, V, T2);    __syncthreads();
    store_s2g(T2, g_Ms);
    __syncthreads();
    scalecols(V, w2, T1); __syncthreads();
    smm_bt(T1, V, T2);    __syncthreads();
    store_s2g(T2, g_Mi);
}

// per-matrix: C = Mi*D*Mi; one-sided Jacobi; T += logm(C)/nb
__global__ void __launch_bounds__(TPB, 4) k_batch_step(const float* __restrict__ data, float inv_nb) {
    extern __shared__ float sm[];
    float* s0 = sm;             // Mi -> W (col-major, scaled)
    float* s1 = sm + BUF;       // D  -> C (row-major LD)
    float* s2 = sm + 2 * BUF;   // temp -> B (col-major 64, Jacobi workspace)
    __shared__ uchar2 tab[63 * 32];
    int t = threadIdx.x;
    for (int idx = t; idx < 63 * 32; idx += TPB) {
        int r = idx >> 5, k = idx & 31, p, q;
        get_pair(r, k, p, q);
        tab[idx] = make_uchar2((unsigned char)p, (unsigned char)q);
    }
    size_t b = blockIdx.x;
    load_g2s(g_Mi, s0);
    load_g2s(data + b * NN, s1);
    __syncthreads();
    smm(s0, s1, s2);    // s2 = Mi * D
    __syncthreads();
    smm(s2, s0, s1);    // s1 = C = Mi * D * Mi  (row-major)
    __syncthreads();
    // symmetrize C into column-major contiguous B (s2)
    for (int idx = t; idx < NN; idx += TPB) {
        int c = idx >> 6, r2 = idx & 63;
        s2[idx] = 0.5f * (s1[r2 * LD + c] + s1[c * LD + r2]);
    }
    __syncthreads();
    jacobi1s(s2, tab, NSWEEP_B);     // columns -> lambda_k * u_k
    // per-column: g = log(lambda)/lambda^2 = 0.5*log(nrm2)/nrm2; W[:,k]=B[:,k]*g
    {
        int col = t >> 2, qc = t & 3;
        const float4* bc = reinterpret_cast<const float4*>(s2 + col * 64);
        float4 v0 = bc[qc * 4 + 0], v1 = bc[qc * 4 + 1];
        float4 v2 = bc[qc * 4 + 2], v3 = bc[qc * 4 + 3];
        float pn = dot4(v0, v0) + dot4(v1, v1) + dot4(v2, v2) + dot4(v3, v3);
        pn += __shfl_xor_sync(0xffffffffu, pn, 1);
        pn += __shfl_xor_sync(0xffffffffu, pn, 2);
        float nrm2 = fmaxf(pn, 1e-24f);
        float g = 0.5f * logf(nrm2) / nrm2;
        float4* wc = reinterpret_cast<float4*>(s0 + col * 64);
        v0.x *= g; v0.y *= g; v0.z *= g; v0.w *= g;
        v1.x *= g; v1.y *= g; v1.z *= g; v1.w *= g;
        v2.x *= g; v2.y *= g; v2.z *= g; v2.w *= g;
        v3.x *= g; v3.y *= g; v3.z *= g; v3.w *= g;
        wc[qc * 4 + 0] = v0; wc[qc * 4 + 1] = v1;
        wc[qc * 4 + 2] = v2; wc[qc * 4 + 3] = v3;
    }
    __syncthreads();
    // logm(C)[i][j] = sum_k W[k*64+i] * B[k*64+j];  T += logm/nb
    {
        int j  = t & 63;
        int ib = (t >> 6) << 4;
        float acc[16];
#pragma unroll
        for (int i = 0; i < 16; i++) acc[i] = 0.f;
        for (int k = 0; k < 64; k++) {
            float bj = s2[k * 64 + j];
#pragma unroll
            for (int i = 0; i < 16; i++) acc[i] = fmaf(s0[k * 64 + ib + i], bj, acc[i]);
        }
#pragma unroll
        for (int i = 0; i < 16; i++) atomicAdd(&g_T[(ib + i) * 64 + j], acc[i] * inv_nb);
    }
}

// eigh(T) -> E = expm(T); g_M = Ms * E * Ms
__global__ void __launch_bounds__(TPB) k_update_M() {
    extern __shared__ float sm[];
    float* A  = sm;
    float* V  = sm + BUF;
    float* T1 = sm + 2 * BUF;
    float* T2 = sm + 3 * BUF;
    __shared__ float ew[64];
    load_g2s(g_T, A);
    __syncthreads();
    sym_s(A);
    __syncthreads();
    jacobi2s(A, V, NSWEEP_S);
    int t = threadIdx.x;
    if (t < 64) ew[t] = expf(A[t * LD + t]);
    __syncthreads();
    scalecols(V, ew, T1); __syncthreads();
    smm_bt(T1, V, T2);    __syncthreads();   // T2 = E
    load_g2s(g_Ms, A);    __syncthreads();
    smm(A, T2, T1);       __syncthreads();
    smm_glob(T1, A, g_M);
}

// S = expm(sym(bias)/2);  g_W = S * G
__global__ void __launch_bounds__(TPB) k_bias(const float* __restrict__ bias) {
    extern __shared__ float sm[];
    float* A  = sm;
    float* V  = sm + BUF;
    float* T1 = sm + 2 * BUF;
    float* T2 = sm + 3 * BUF;
    __shared__ float ew[64];
    int t = threadIdx.x;
    for (int idx = t; idx < NN; idx += TPB) {
        int i = idx >> 6, j = idx & 63;
        A[i * LD + j] = 0.5f * (bias[i * 64 + j] + bias[j * 64 + i]);
    }
    __syncthreads();
    jacobi2s(A, V, NSWEEP_S);
    if (t < 64) ew[t] = expf(0.5f * A[t * LD + t]);
    __syncthreads();
    scalecols(V, ew, T1); __syncthreads();
    smm_bt(T1, V, T2);    __syncthreads();   // T2 = S
    load_g2s(g_Mi, A);    __syncthreads();
    smm_glob(T2, A, g_W);
}

// out_b = W * data_b * W^T
__global__ void __launch_bounds__(TPB, 4) k_final(const float* __restrict__ data,
                                                  float* __restrict__ out) {
    extern __shared__ float sm[];
    float* sW = sm;
    float* sD = sm + BUF;
    float* sT = sm + 2 * BUF;
    size_t b = blockIdx.x;
    load_g2s(g_W, sW);
    load_g2s(data + b * NN, sD);
    __syncthreads();
    smm(sW, sD, sT);
    __syncthreads();
    smm_bt_glob(sT, sW, out + b * NN);
}

// ---------------------------------------------------------------------------
extern "C" void kernel_launch(void* const* d_in, const int* in_sizes, int n_in,
                              void* d_out, int out_size) {
    const float* data;
    const float* bias;
    int nb;
    if (in_sizes[0] >= in_sizes[1]) {
        data = (const float*)d_in[0]; bias = (const float*)d_in[1];
        nb = in_sizes[0] / NN;
    } else {
        data = (const float*)d_in[1]; bias = (const float*)d_in[0];
        nb = in_sizes[1] / NN;
    }
    float* out = (float*)d_out;
    float inv_nb = 1.0f / (float)nb;

    size_t smem4 = 4 * BUF * sizeof(float);
    size_t smem3 = 3 * BUF * sizeof(float);
    cudaFuncSetAttribute(k_eig_M,      cudaFuncAttributeMaxDynamicSharedMemorySize, (int)smem4);
    cudaFuncSetAttribute(k_batch_step, cudaFuncAttributeMaxDynamicSharedMemorySize, (int)smem3);
    cudaFuncSetAttribute(k_update_M,   cudaFuncAttributeMaxDynamicSharedMemorySize, (int)smem4);
    cudaFuncSetAttribute(k_bias,       cudaFuncAttributeMaxDynamicSharedMemorySize, (int)smem4);
    cudaFuncSetAttribute(k_final,      cudaFuncAttributeMaxDynamicSharedMemorySize, (int)smem3);

    // arithmetic mean
    k_zero<<<16, 256>>>(0);
    {
        int nchunk = 64;
        while (nchunk > 1 && (nb % nchunk) != 0) nchunk >>= 1;
        int per_chunk = nb / nchunk;
        dim3 g(NN / 256, nchunk);
        k_mean_acc<<<g, 256>>>(data, per_chunk, inv_nb);
    }

    // 3 Karcher iterations
    for (int it = 0; it < 3; ++it) {
        k_eig_M<<<1, TPB, smem4>>>();
        k_zero<<<16, 256>>>(1);
        k_batch_step<<<nb, TPB, smem3>>>(data, inv_nb);
        k_update_M<<<1, TPB, smem4>>>();
    }

    // final whitening + bias congruence
    k_eig_M<<<1, TPB, smem4>>>();
    k_bias<<<1, TPB, smem4>>>(bias);
    k_final<<<nb, TPB, smem3>>>(data, out);
}

// round 6
// speedup vs baseline: 4.7309x; 1.0016x over previous
#include <cuda_runtime.h>
#include <cuda_bf16.h>
#include <math.h>

// ============================================================================
// BatchNormSPDMean R6: dual-matrix ILP jacobi + f32x2 packed math + faster GEMMs
// ============================================================================

#define NN 4096
#define LD 65        // single-matrix kernels row stride (unchanged, conflict-free)
#define BLD 66       // batch row-major stride (even -> 8B-aligned float2 along k)
#define CST 68       // batch col-major column stride (conflict-free float4 phases)
#define BUFB 4352    // batch buffer floats (>= 64*68)
#define NSWEEP_B 7
#define NSWEEP_S 10
#define TPB 256
#define BUF 4160     // single-matrix buffer floats (64*65)

typedef unsigned long long ull;

// ---- persistent scratch ----
__device__ float g_M [NN];
__device__ float g_Ms[NN];
__device__ float g_Mi[NN];
__device__ float g_T [NN];
__device__ float g_W [NN];

// ---------------------------------------------------------------------------
// f32x2 packed helpers (sm_103a)
// ---------------------------------------------------------------------------
__device__ __forceinline__ ull pk2(float lo, float hi) {
    ull r; asm("mov.b64 %0,{%1,%2};" : "=l"(r) : "f"(lo), "f"(hi)); return r;
}
__device__ __forceinline__ float2 upk2(ull v) {
    float2 r; asm("mov.b64 {%0,%1},%2;" : "=f"(r.x), "=f"(r.y) : "l"(v)); return r;
}
__device__ __forceinline__ ull fma2(ull a, ull b, ull c) {
    ull r; asm("fma.rn.f32x2 %0,%1,%2,%3;" : "=l"(r) : "l"(a), "l"(b), "l"(c)); return r;
}
__device__ __forceinline__ ull mul2(ull a, ull b) {
    ull r; asm("mul.rn.f32x2 %0,%1,%2;" : "=l"(r) : "l"(a), "l"(b)); return r;
}
__device__ __forceinline__ float d4(float4 a, float4 b) {
    return fmaf(a.x, b.x, fmaf(a.y, b.y, fmaf(a.z, b.z, a.w * b.w)));
}

// tournament pairing
__device__ __forceinline__ void get_pair(int r, int k, int& p, int& q) {
    int a = (k == 0) ? 0 : 1 + (k - 1 + r) % 63;
    int b = 1 + (62 - k + r) % 63;
    p = a < b ? a : b;
    q = a < b ? b : a;
}

// ---------------------------------------------------------------------------
// single-matrix helpers (LD=65 world, unchanged from R5; negligible cost)
// ---------------------------------------------------------------------------
__device__ __forceinline__ void load_g2s(const float* __restrict__ g, float* S) {
    for (int idx = threadIdx.x; idx < NN; idx += TPB)
        S[(idx >> 6) * LD + (idx & 63)] = g[idx];
}
__device__ __forceinline__ void store_s2g(const float* S, float* __restrict__ g) {
    for (int idx = threadIdx.x; idx < NN; idx += TPB)
        g[idx] = S[(idx >> 6) * LD + (idx & 63)];
}
__device__ __forceinline__ void sym_s(float* A) {
    for (int idx = threadIdx.x; idx < NN; idx += TPB) {
        int i = idx >> 6, j = idx & 63;
        if (i < j) {
            float v = 0.5f * (A[i * LD + j] + A[j * LD + i]);
            A[i * LD + j] = v;
            A[j * LD + i] = v;
        }
    }
}
__device__ __forceinline__ void smm(const float* A, const float* B, float* C) {
    int j  = threadIdx.x & 63;
    int ib = (threadIdx.x >> 6) << 4;
    float acc[16];
#pragma unroll
    for (int i = 0; i < 16; i++) acc[i] = 0.f;
    for (int k = 0; k < 64; k++) {
        float bv = B[k * LD + j];
#pragma unroll
        for (int i = 0; i < 16; i++) acc[i] = fmaf(A[(ib + i) * LD + k], bv, acc[i]);
    }
#pragma unroll
    for (int i = 0; i < 16; i++) C[(ib + i) * LD + j] = acc[i];
}
__device__ __forceinline__ void smm_bt(const float* A, const float* B, float* C) {
    int j  = threadIdx.x & 63;
    int ib = (threadIdx.x >> 6) << 4;
    float acc[16];
#pragma unroll
    for (int i = 0; i < 16; i++) acc[i] = 0.f;
    for (int k = 0; k < 64; k++) {
        float bv = B[j * LD + k];
#pragma unroll
        for (int i = 0; i < 16; i++) acc[i] = fmaf(A[(ib + i) * LD + k], bv, acc[i]);
    }
#pragma unroll
    for (int i = 0; i < 16; i++) C[(ib + i) * LD + j] = acc[i];
}
__device__ __forceinline__ void smm_glob(const float* A, const float* B, float* __restrict__ gout) {
    int j  = threadIdx.x & 63;
    int ib = (threadIdx.x >> 6) << 4;
    float acc[16];
#pragma unroll
    for (int i = 0; i < 16; i++) acc[i] = 0.f;
    for (int k = 0; k < 64; k++) {
        float bv = B[k * LD + j];
#pragma unroll
        for (int i = 0; i < 16; i++) acc[i] = fmaf(A[(ib + i) * LD + k], bv, acc[i]);
    }
#pragma unroll
    for (int i = 0; i < 16; i++) gout[(ib + i) * 64 + j] = acc[i];
}
__device__ __forceinline__ void scalecols(const float* V, const float* w, float* O) {
    for (int idx = threadIdx.x; idx < NN; idx += TPB) {
        int i = idx >> 6, k = idx & 63;
        O[i * LD + k] = V[i * LD + k] * w[k];
    }
}

// two-sided Jacobi (single-matrix kernels only)
__device__ void jacobi2s(float* A, float* V, int nsweeps) {
    int t = threadIdx.x;
    __shared__ float cs[32], sn[32];
    __shared__ uchar2 tab2[63 * 32];
    for (int idx = t; idx < 63 * 32; idx += TPB) {
        int r = idx >> 5, k = idx & 31, p, q;
        get_pair(r, k, p, q);
        tab2[idx] = make_uchar2((unsigned char)p, (unsigned char)q);
    }
    for (int idx = t; idx < NN; idx += TPB) {
        int i = idx >> 6, j = idx & 63;
        V[i * LD + j] = (i == j) ? 1.f : 0.f;
    }
    __syncthreads();
    for (int sw = 0; sw < nsweeps; ++sw) {
        for (int r = 0; r < 63; ++r) {
            const uchar2* trow = tab2 + (r << 5);
            if (t < 32) {
                uchar2 pq = trow[t];
                int pl = pq.x * LD, ql = pq.y * LD;
                float app = A[pl + pq.x], aqq = A[ql + pq.y], apq = A[pl + pq.y];
                float c, s;
                if (fabsf(apq) < 1e-30f) { c = 1.f; s = 0.f; }
                else {
                    float tau = (aqq - app) / (2.f * apq);
                    float tt  = copysignf(1.f, tau) / (fabsf(tau) + sqrtf(1.f + tau * tau));
                    c = rsqrtf(1.f + tt * tt);
                    s = tt * c;
                }
                cs[t] = c; sn[t] = s;
            }
            __syncthreads();
#pragma unroll
            for (int m = 0; m < 2048 / TPB; m++) {
                int w = t + m * TPB;
                int k = w >> 6, j = w & 63;
                uchar2 pq = trow[k];
                int pl = pq.x * LD + j, ql = pq.y * LD + j;
                float c = cs[k], s = sn[k];
                float ap = A[pl], aq = A[ql];
                A[pl] = c * ap - s * aq;
                A[ql] = fmaf(s, ap, c * aq);
            }
            __syncthreads();
#pragma unroll
            for (int m = 0; m < 2048 / TPB; m++) {
                int w = t + m * TPB;
                int k = w >> 6, i = w & 63;
                uchar2 pq = trow[k];
                int il = i * LD;
                int pl = il + pq.x, ql = il + pq.y;
                float c = cs[k], s = sn[k];
                float ap = A[pl], aq = A[ql];
                A[pl] = c * ap - s * aq;
                A[ql] = fmaf(s, ap, c * aq);
                float vp = V[pl], vq = V[ql];
                V[pl] = c * vp - s * vq;
                V[ql] = fmaf(s, vp, c * vq);
            }
            __syncthreads();
        }
    }
}

// ---------------------------------------------------------------------------
// batch GEMMs (row stride BLD=66, f32x2 packed along k)
// ---------------------------------------------------------------------------
// C(row) = A(row) * B(row)
__device__ __forceinline__ void gemm_rr(const float* A, const float* B, float* C) {
    int j  = threadIdx.x & 63;
    int ib = (threadIdx.x >> 6) << 4;
    ull acc[16];
#pragma unroll
    for (int i = 0; i < 16; i++) acc[i] = 0ull;
    for (int k = 0; k < 64; k += 2) {
        ull b2 = pk2(B[k * BLD + j], B[(k + 1) * BLD + j]);
#pragma unroll
        for (int i = 0; i < 16; i++) {
            ull a2 = *(const ull*)(A + (ib + i) * BLD + k);
            acc[i] = fma2(a2, b2, acc[i]);
        }
    }
#pragma unroll
    for (int i = 0; i < 16; i++) {
        float2 f = upk2(acc[i]);
        C[(ib + i) * BLD + j] = f.x + f.y;
    }
}
// C(col, stride CST) = A(row) * B(row)
__device__ __forceinline__ void gemm_r2c(const float* A, const float* B, float* C) {
    int j  = threadIdx.x & 63;
    int ib = (threadIdx.x >> 6) << 4;
    ull acc[16];
#pragma unroll
    for (int i = 0; i < 16; i++) acc[i] = 0ull;
    for (int k = 0; k < 64; k += 2) {
        ull b2 = pk2(B[k * BLD + j], B[(k + 1) * BLD + j]);
#pragma unroll
        for (int i = 0; i < 16; i++) {
            ull a2 = *(const ull*)(A + (ib + i) * BLD + k);
            acc[i] = fma2(a2, b2, acc[i]);
        }
    }
    float r[16];
#pragma unroll
    for (int i = 0; i < 16; i++) { float2 f = upk2(acc[i]); r[i] = f.x + f.y; }
    float4* dst = (float4*)(C + j * CST + ib);
    dst[0] = make_float4(r[0],  r[1],  r[2],  r[3]);
    dst[1] = make_float4(r[4],  r[5],  r[6],  r[7]);
    dst[2] = make_float4(r[8],  r[9],  r[10], r[11]);
    dst[3] = make_float4(r[12], r[13], r[14], r[15]);
}

// ---------------------------------------------------------------------------
// dual one-sided Jacobi: two col-major (CST) matrices, interleaved per round
// ---------------------------------------------------------------------------
__device__ __forceinline__ void dots8(ulonglong2 p0, ulonglong2 p1,
                                      ulonglong2 q0, ulonglong2 q1,
                                      float& app, float& aqq, float& apq) {
    ull aPP = mul2(p0.x, p0.x); aPP = fma2(p0.y, p0.y, aPP);
    aPP = fma2(p1.x, p1.x, aPP); aPP = fma2(p1.y, p1.y, aPP);
    ull aQQ = mul2(q0.x, q0.x); aQQ = fma2(q0.y, q0.y, aQQ);
    aQQ = fma2(q1.x, q1.x, aQQ); aQQ = fma2(q1.y, q1.y, aQQ);
    ull aPQ = mul2(p0.x, q0.x); aPQ = fma2(p0.y, q0.y, aPQ);
    aPQ = fma2(p1.x, q1.x, aPQ); aPQ = fma2(p1.y, q1.y, aPQ);
    float2 f;
    f = upk2(aPP); app = f.x + f.y;
    f = upk2(aQQ); aqq = f.x + f.y;
    f = upk2(aPQ); apq = f.x + f.y;
#pragma unroll
    for (int d = 1; d < 8; d <<= 1) {
        app += __shfl_xor_sync(0xffffffffu, app, d);
        aqq += __shfl_xor_sync(0xffffffffu, aqq, d);
        apq += __shfl_xor_sync(0xffffffffu, apq, d);
    }
}
__device__ __forceinline__ void rot_store(ulonglong2* P, ulonglong2* Q, int sub,
        ulonglong2 p0, ulonglong2 p1, ulonglong2 q0, ulonglong2 q1,
        float c, float s) {
    ull c2 = pk2(c, c), s2 = pk2(s, s), ns2 = pk2(-s, -s);
    ulonglong2 np, nq;
    np.x = fma2(ns2, q0.x, mul2(c2, p0.x)); np.y = fma2(ns2, q0.y, mul2(c2, p0.y));
    nq.x = fma2(c2, q0.x, mul2(s2, p0.x)); nq.y = fma2(c2, q0.y, mul2(s2, p0.y));
    P[sub] = np; Q[sub] = nq;
    np.x = fma2(ns2, q1.x, mul2(c2, p1.x)); np.y = fma2(ns2, q1.y, mul2(c2, p1.y));
    nq.x = fma2(c2, q1.x, mul2(s2, p1.x)); nq.y = fma2(c2, q1.y, mul2(s2, p1.y));
    P[sub + 8] = np; Q[sub + 8] = nq;
}
__device__ void jacobi1s_dual(float* BA, float* BB, const uchar2* tab, int nsweeps) {
    int lane = threadIdx.x & 31;
    int warp = threadIdx.x >> 5;
    int grp  = lane >> 3;
    int sub  = lane & 7;
    for (int sw = 0; sw < nsweeps; ++sw) {
        for (int r = 0; r < 63; ++r) {
            uchar2 pq = tab[(r << 5) + (warp << 2) + grp];
            ulonglong2* PA = (ulonglong2*)(BA + pq.x * CST);
            ulonglong2* QA = (ulonglong2*)(BA + pq.y * CST);
            ulonglong2* PB = (ulonglong2*)(BB + pq.x * CST);
            ulonglong2* QB = (ulonglong2*)(BB + pq.y * CST);
            ulonglong2 pa0 = PA[sub], pa1 = PA[sub + 8];
            ulonglong2 qa0 = QA[sub], qa1 = QA[sub + 8];
            ulonglong2 pb0 = PB[sub], pb1 = PB[sub + 8];
            ulonglong2 qb0 = QB[sub], qb1 = QB[sub + 8];
            float appA, aqqA, apqA, appB, aqqB, apqB;
            dots8(pa0, pa1, qa0, qa1, appA, aqqA, apqA);
            dots8(pb0, pb1, qb0, qb1, appB, aqqB, apqB);
            if (apqA * apqA > 1e-14f * appA * aqqA) {
                float tau = __fdividef(aqqA - appA, 2.f * apqA);
                float tt  = copysignf(1.f, tau) / (fabsf(tau) + sqrtf(1.f + tau * tau));
                float c = rsqrtf(1.f + tt * tt), s = tt * c;
                rot_store(PA, QA, sub, pa0, pa1, qa0, qa1, c, s);
            }
            if (apqB * apqB > 1e-14f * appB * aqqB) {
                float tau = __fdividef(aqqB - appB, 2.f * apqB);
                float tt  = copysignf(1.f, tau) / (fabsf(tau) + sqrtf(1.f + tau * tau));
                float c = rsqrtf(1.f + tt * tt), s = tt * c;
                rot_store(PB, QB, sub, pb0, pb1, qb0, qb1, c, s);
            }
            __syncthreads();
        }
    }
}

// epilogue: W[:,k] = B[:,k] * 0.5*log(|B[:,k]|^2)/|B[:,k]|^2  (col-major CST)
__device__ __forceinline__ void colscale_log(const float* B, float* W) {
    int t = threadIdx.x;
    int col = t >> 2, qc = t & 3;
    const float4* bc = (const float4*)(B + col * CST);
    float4 v0 = bc[qc * 4 + 0], v1 = bc[qc * 4 + 1];
    float4 v2 = bc[qc * 4 + 2], v3 = bc[qc * 4 + 3];
    float pn = d4(v0, v0) + d4(v1, v1) + d4(v2, v2) + d4(v3, v3);
    pn += __shfl_xor_sync(0xffffffffu, pn, 1);
    pn += __shfl_xor_sync(0xffffffffu, pn, 2);
    float n2 = fmaxf(pn, 1e-24f);
    float g = 0.5f * logf(n2) / n2;
    float4* wc = (float4*)(W + col * CST);
    v0.x *= g; v0.y *= g; v0.z *= g; v0.w *= g;
    v1.x *= g; v1.y *= g; v1.z *= g; v1.w *= g;
    v2.x *= g; v2.y *= g; v2.z *= g; v2.w *= g;
    v3.x *= g; v3.y *= g; v3.z *= g; v3.w *= g;
    wc[qc * 4 + 0] = v0; wc[qc * 4 + 1] = v1;
    wc[qc * 4 + 2] = v2; wc[qc * 4 + 3] = v3;
}
// g_T += scale * W * B^T (both col-major CST)
__device__ __forceinline__ void logm_atomic(const float* W, const float* B, float scale) {
    int j  = threadIdx.x & 63;
    int ib = (threadIdx.x >> 6) << 4;
    float acc[16];
#pragma unroll
    for (int i = 0; i < 16; i++) acc[i] = 0.f;
    for (int k = 0; k < 64; k++) {
        float bj = B[k * CST + j];
        const float4* wr = (const float4*)(W + k * CST + ib);
        float4 w0 = wr[0], w1 = wr[1], w2 = wr[2], w3 = wr[3];
        acc[0]  = fmaf(w0.x, bj, acc[0]);  acc[1]  = fmaf(w0.y, bj, acc[1]);
        acc[2]  = fmaf(w0.z, bj, acc[2]);  acc[3]  = fmaf(w0.w, bj, acc[3]);
        acc[4]  = fmaf(w1.x, bj, acc[4]);  acc[5]  = fmaf(w1.y, bj, acc[5]);
        acc[6]  = fmaf(w1.z, bj, acc[6]);  acc[7]  = fmaf(w1.w, bj, acc[7]);
        acc[8]  = fmaf(w2.x, bj, acc[8]);  acc[9]  = fmaf(w2.y, bj, acc[9]);
        acc[10] = fmaf(w2.z, bj, acc[10]); acc[11] = fmaf(w2.w, bj, acc[11]);
        acc[12] = fmaf(w3.x, bj, acc[12]); acc[13] = fmaf(w3.y, bj, acc[13]);
        acc[14] = fmaf(w3.z, bj, acc[14]); acc[15] = fmaf(w3.w, bj, acc[15]);
    }
#pragma unroll
    for (int i = 0; i < 16; i++) atomicAdd(&g_T[(ib + i) * 64 + j], acc[i] * scale);
}

// ---------------------------------------------------------------------------
// kernels
// ---------------------------------------------------------------------------
__global__ void k_zero(int which) {
    int i = blockIdx.x * blockDim.x + threadIdx.x;
    if (i < NN) { if (which == 0) g_M[i] = 0.f; else g_T[i] = 0.f; }
}

__global__ void k_mean_acc(const float* __restrict__ data, int per_chunk, float inv_nb) {
    int e = blockIdx.x * blockDim.x + threadIdx.x;
    const float* p = data + (size_t)(blockIdx.y) * per_chunk * NN + e;
    float sum = 0.f;
#pragma unroll 8
    for (int i = 0; i < per_chunk; i++) sum += p[(size_t)i * NN];
    atomicAdd(&g_M[e], sum * inv_nb);
}

__global__ void __launch_bounds__(TPB) k_eig_M() {
    extern __shared__ float sm[];
    float* A  = sm;
    float* V  = sm + BUF;
    float* T1 = sm + 2 * BUF;
    float* T2 = sm + 3 * BUF;
    __shared__ float w1[64], w2[64];
    load_g2s(g_M, A);
    __syncthreads();
    sym_s(A);
    __syncthreads();
    jacobi2s(A, V, NSWEEP_S);
    int t = threadIdx.x;
    if (t < 64) {
        float w = fmaxf(A[t * LD + t], 1e-12f);
        w1[t] = sqrtf(w);
        w2[t] = rsqrtf(w);
    }
    __syncthreads();
    scalecols(V, w1, T1); __syncthreads();
    smm_bt(T1, V, T2);    __syncthreads();
    store_s2g(T2, g_Ms);
    __syncthreads();
    scalecols(V, w2, T1); __syncthreads();
    smm_bt(T1, V, T2);    __syncthreads();
    store_s2g(T2, g_Mi);
}

// dual-matrix batch step: 2 matrices per CTA
__global__ void __launch_bounds__(TPB, 3) k_batch_dual(const float* __restrict__ data,
                                                       float inv_nb, int nb) {
    extern __shared__ float sm[];
    float* b0 = sm;             // Mi (row) -> W_A (col)
    float* b1 = sm + BUFB;      // D (row)  -> C_B (col)
    float* b2 = sm + 2 * BUFB;  // temp row -> W_B (col)
    float* b3 = sm + 3 * BUFB;  // C_A (col)
    __shared__ uchar2 tab[63 * 32];
    int t = threadIdx.x;
    for (int idx = t; idx < 63 * 32; idx += TPB) {
        int r = idx >> 5, k = idx & 31, p, q;
        get_pair(r, k, p, q);
        tab[idx] = make_uchar2((unsigned char)p, (unsigned char)q);
    }
    int bA = blockIdx.x * 2;
    int bB = min(bA + 1, nb - 1);
    float scaleB = (bA + 1 < nb) ? inv_nb : 0.f;

    for (int idx = t; idx < NN; idx += TPB)
        b0[(idx >> 6) * BLD + (idx & 63)] = g_Mi[idx];
    const float* DA = data + (size_t)bA * NN;
    for (int idx = t; idx < NN; idx += TPB)
        b1[(idx >> 6) * BLD + (idx & 63)] = DA[idx];
    __syncthreads();
    gemm_rr(b0, b1, b2);           // b2 = Mi * D_A
    __syncthreads();
    gemm_r2c(b2, b0, b3);          // b3 = C_A (col-major)
    const float* DB = data + (size_t)bB * NN;
    for (int idx = t; idx < NN; idx += TPB)
        b1[(idx >> 6) * BLD + (idx & 63)] = DB[idx];
    __syncthreads();
    gemm_rr(b0, b1, b2);           // b2 = Mi * D_B
    __syncthreads();
    gemm_r2c(b2, b0, b1);          // b1 = C_B (col-major)
    __syncthreads();
    // symmetrize both in place
    for (int idx = t; idx < NN; idx += TPB) {
        int i = idx >> 6, j = idx & 63;
        if (i < j) {
            float v = 0.5f * (b3[i * CST + j] + b3[j * CST + i]);
            b3[i * CST + j] = v; b3[j * CST + i] = v;
            v = 0.5f * (b1[i * CST + j] + b1[j * CST + i]);
            b1[i * CST + j] = v; b1[j * CST + i] = v;
        }
    }
    __syncthreads();
    jacobi1s_dual(b3, b1, tab, NSWEEP_B);
    colscale_log(b3, b0);          // W_A
    colscale_log(b1, b2);          // W_B
    __syncthreads();
    logm_atomic(b0, b3, inv_nb);
    logm_atomic(b2, b1, scaleB);
}

__global__ void __launch_bounds__(TPB) k_update_M() {
    extern __shared__ float sm[];
    float* A  = sm;
    float* V  = sm + BUF;
    float* T1 = sm + 2 * BUF;
    float* T2 = sm + 3 * BUF;
    __shared__ float ew[64];
    load_g2s(g_T, A);
    __syncthreads();
    sym_s(A);
    __syncthreads();
    jacobi2s(A, V, NSWEEP_S);
    int t = threadIdx.x;
    if (t < 64) ew[t] = expf(A[t * LD + t]);
    __syncthreads();
    scalecols(V, ew, T1); __syncthreads();
    smm_bt(T1, V, T2);    __syncthreads();
    load_g2s(g_Ms, A);    __syncthreads();
    smm(A, T2, T1);       __syncthreads();
    smm_glob(T1, A, g_M);
}

__global__ void __launch_bounds__(TPB) k_bias(const float* __restrict__ bias) {
    extern __shared__ float sm[];
    float* A  = sm;
    float* V  = sm + BUF;
    float* T1 = sm + 2 * BUF;
    float* T2 = sm + 3 * BUF;
    __shared__ float ew[64];
    int t = threadIdx.x;
    for (int idx = t; idx < NN; idx += TPB) {
        int i = idx >> 6, j = idx & 63;
        A[i * LD + j] = 0.5f * (bias[i * 64 + j] + bias[j * 64 + i]);
    }
    __syncthreads();
    jacobi2s(A, V, NSWEEP_S);
    if (t < 64) ew[t] = expf(0.5f * A[t * LD + t]);
    __syncthreads();
    scalecols(V, ew, T1); __syncthreads();
    smm_bt(T1, V, T2);    __syncthreads();
    load_g2s(g_Mi, A);    __syncthreads();
    smm_glob(T2, A, g_W);
}

// out_b = W * data_b * W^T  (batch GEMMs, BLD stride, f32x2)
__global__ void __launch_bounds__(TPB, 4) k_final(const float* __restrict__ data,
                                                  float* __restrict__ out) {
    extern __shared__ float sm[];
    float* sW = sm;
    float* sD = sm + BUFB;
    float* sT = sm + 2 * BUFB;
    size_t b = blockIdx.x;
    int t = threadIdx.x;
    for (int idx = t; idx < NN; idx += TPB)
        sW[(idx >> 6) * BLD + (idx & 63)] = g_W[idx];
    const float* D = data + b * NN;
    for (int idx = t; idx < NN; idx += TPB)
        sD[(idx >> 6) * BLD + (idx & 63)] = D[idx];
    __syncthreads();
    gemm_rr(sW, sD, sT);
    __syncthreads();
    // out = T * W^T
    int j  = t & 63;
    int ib = (t >> 6) << 4;
    ull acc[16];
#pragma unroll
    for (int i = 0; i < 16; i++) acc[i] = 0ull;
    for (int k = 0; k < 64; k += 2) {
        ull b2 = *(const ull*)(sW + j * BLD + k);
#pragma unroll
        for (int i = 0; i < 16; i++) {
            ull a2 = *(const ull*)(sT + (ib + i) * BLD + k);
            acc[i] = fma2(a2, b2, acc[i]);
        }
    }
    float* o = out + b * NN;
#pragma unroll
    for (int i = 0; i < 16; i++) {
        float2 f = upk2(acc[i]);
        o[(ib + i) * 64 + j] = f.x + f.y;
    }
}

// ---------------------------------------------------------------------------
extern "C" void kernel_launch(void* const* d_in, const int* in_sizes, int n_in,
                              void* d_out, int out_size) {
    const float* data;
    const float* bias;
    int nb;
    if (in_sizes[0] >= in_sizes[1]) {
        data = (const float*)d_in[0]; bias = (const float*)d_in[1];
        nb = in_sizes[0] / NN;
    } else {
        data = (const float*)d_in[1]; bias = (const float*)d_in[0];
        nb = in_sizes[1] / NN;
    }
    float* out = (float*)d_out;
    float inv_nb = 1.0f / (float)nb;

    size_t smemS = 4 * BUF  * sizeof(float);   // single-matrix kernels (66560)
    size_t smemD = 4 * BUFB * sizeof(float);   // dual batch (69632)
    size_t smemF = 3 * BUFB * sizeof(float);   // k_final (52224)
    cudaFuncSetAttribute(k_eig_M,     cudaFuncAttributeMaxDynamicSharedMemorySize, (int)smemS);
    cudaFuncSetAttribute(k_batch_dual,cudaFuncAttributeMaxDynamicSharedMemorySize, (int)smemD);
    cudaFuncSetAttribute(k_update_M,  cudaFuncAttributeMaxDynamicSharedMemorySize, (int)smemS);
    cudaFuncSetAttribute(k_bias,      cudaFuncAttributeMaxDynamicSharedMemorySize, (int)smemS);
    cudaFuncSetAttribute(k_final,     cudaFuncAttributeMaxDynamicSharedMemorySize, (int)smemF);

    // arithmetic mean
    k_zero<<<16, 256>>>(0);
    {
        int nchunk = 64;
        while (nchunk > 1 && (nb % nchunk) != 0) nchunk >>= 1;
        int per_chunk = nb / nchunk;
        dim3 g(NN / 256, nchunk);
        k_mean_acc<<<g, 256>>>(data, per_chunk, inv_nb);
    }

    int nbHalf = (nb + 1) / 2;
    // 3 Karcher iterations
    for (int it = 0; it < 3; ++it) {
        k_eig_M<<<1, TPB, smemS>>>();
        k_zero<<<16, 256>>>(1);
        k_batch_dual<<<nbHalf, TPB, smemD>>>(data, inv_nb, nb);
        k_update_M<<<1, TPB, smemS>>>();
    }

    // final whitening + bias congruence
    k_eig_M<<<1, TPB, smemS>>>();
    k_bias<<<1, TPB, smemS>>>(bias);
    k_final<<<nb, TPB, smemF>>>(data, out);
}

// round 7
// speedup vs baseline: 4.9859x; 1.0539x over previous
#include <cuda_runtime.h>
#include <cuda_bf16.h>
#include <math.h>

// ============================================================================
// BatchNormSPDMean R7: register-resident one-sided Jacobi (odd-even ordering,
// columns live in registers, shfl/column-migration), f32x2 everywhere.
// ============================================================================

#define NN 4096
#define LD 65        // single-matrix kernels row stride
#define BLD 66       // batch row-major stride (8B-aligned k-pairs)
#define CST 68       // batch col-major column stride (16B-aligned columns)
#define BUFB 4352
#define NSWEEP_B 7
#define NSWEEP_S 10
#define TPB 256
#define BUF 4160
#define FULLM 0xffffffffu

typedef unsigned long long ull;

// ---- persistent scratch ----
__device__ float g_M [NN];
__device__ float g_Ms[NN];
__device__ float g_Mi[NN];
__device__ float g_T [NN];
__device__ float g_W [NN];

// ---------------------------------------------------------------------------
// f32x2 packed helpers
// ---------------------------------------------------------------------------
__device__ __forceinline__ ull pk2(float lo, float hi) {
    ull r; asm("mov.b64 %0,{%1,%2};" : "=l"(r) : "f"(lo), "f"(hi)); return r;
}
__device__ __forceinline__ float2 upk2(ull v) {
    float2 r; asm("mov.b64 {%0,%1},%2;" : "=f"(r.x), "=f"(r.y) : "l"(v)); return r;
}
__device__ __forceinline__ ull fma2(ull a, ull b, ull c) {
    ull r; asm("fma.rn.f32x2 %0,%1,%2,%3;" : "=l"(r) : "l"(a), "l"(b), "l"(c)); return r;
}
__device__ __forceinline__ ull mul2(ull a, ull b) {
    ull r; asm("mul.rn.f32x2 %0,%1,%2;" : "=l"(r) : "l"(a), "l"(b)); return r;
}
__device__ __forceinline__ float hadd2(ull v) { float2 f = upk2(v); return f.x + f.y; }
__device__ __forceinline__ float red8(float x) {
    x += __shfl_xor_sync(FULLM, x, 1);
    x += __shfl_xor_sync(FULLM, x, 2);
    x += __shfl_xor_sync(FULLM, x, 4);
    return x;
}
__device__ __forceinline__ ull shfl_ull(ull v, int src) {
    float2 f = upk2(v);
    f.x = __shfl_sync(FULLM, f.x, src);
    f.y = __shfl_sync(FULLM, f.y, src);
    return pk2(f.x, f.y);
}
__device__ __forceinline__ float d4(float4 a, float4 b) {
    return fmaf(a.x, b.x, fmaf(a.y, b.y, fmaf(a.z, b.z, a.w * b.w)));
}
// Jacobi rotation params from 2x2 Gram
__device__ __forceinline__ void rot_params(float app, float aqq, float apq,
                                           float& c, float& s) {
    if (apq * apq > 1e-14f * app * aqq) {
        float tau = __fdividef(aqq - app, 2.f * apq);
        float tt  = copysignf(1.f, tau) / (fabsf(tau) + sqrtf(1.f + tau * tau));
        c = rsqrtf(1.f + tt * tt);
        s = tt * c;
    } else { c = 1.f; s = 0.f; }
}
// dots over 4-ull register columns + 8-lane reduce
__device__ __forceinline__ void dots8(const ull* a, const ull* b,
                                      float& app, float& aqq, float& apq) {
    ull A = mul2(a[0], a[0]), B = mul2(b[0], b[0]), C = mul2(a[0], b[0]);
#pragma unroll
    for (int i = 1; i < 4; i++) {
        A = fma2(a[i], a[i], A);
        B = fma2(b[i], b[i], B);
        C = fma2(a[i], b[i], C);
    }
    app = red8(hadd2(A));
    aqq = red8(hadd2(B));
    apq = red8(hadd2(C));
}

// tournament pairing (two-sided jacobi only)
__device__ __forceinline__ void get_pair(int r, int k, int& p, int& q) {
    int a = (k == 0) ? 0 : 1 + (k - 1 + r) % 63;
    int b = 1 + (62 - k + r) % 63;
    p = a < b ? a : b;
    q = a < b ? b : a;
}

// ---------------------------------------------------------------------------
// single-matrix helpers (LD=65 world)
// ---------------------------------------------------------------------------
__device__ __forceinline__ void load_g2s(const float* __restrict__ g, float* S) {
    for (int idx = threadIdx.x; idx < NN; idx += TPB)
        S[(idx >> 6) * LD + (idx & 63)] = g[idx];
}
__device__ __forceinline__ void store_s2g(const float* S, float* __restrict__ g) {
    for (int idx = threadIdx.x; idx < NN; idx += TPB)
        g[idx] = S[(idx >> 6) * LD + (idx & 63)];
}
__device__ __forceinline__ void sym_s(float* A) {
    for (int idx = threadIdx.x; idx < NN; idx += TPB) {
        int i = idx >> 6, j = idx & 63;
        if (i < j) {
            float v = 0.5f * (A[i * LD + j] + A[j * LD + i]);
            A[i * LD + j] = v;
            A[j * LD + i] = v;
        }
    }
}
__device__ __forceinline__ void smm(const float* A, const float* B, float* C) {
    int j  = threadIdx.x & 63;
    int ib = (threadIdx.x >> 6) << 4;
    float acc[16];
#pragma unroll
    for (int i = 0; i < 16; i++) acc[i] = 0.f;
    for (int k = 0; k < 64; k++) {
        float bv = B[k * LD + j];
#pragma unroll
        for (int i = 0; i < 16; i++) acc[i] = fmaf(A[(ib + i) * LD + k], bv, acc[i]);
    }
#pragma unroll
    for (int i = 0; i < 16; i++) C[(ib + i) * LD + j] = acc[i];
}
__device__ __forceinline__ void smm_bt(const float* A, const float* B, float* C) {
    int j  = threadIdx.x & 63;
    int ib = (threadIdx.x >> 6) << 4;
    float acc[16];
#pragma unroll
    for (int i = 0; i < 16; i++) acc[i] = 0.f;
    for (int k = 0; k < 64; k++) {
        float bv = B[j * LD + k];
#pragma unroll
        for (int i = 0; i < 16; i++) acc[i] = fmaf(A[(ib + i) * LD + k], bv, acc[i]);
    }
#pragma unroll
    for (int i = 0; i < 16; i++) C[(ib + i) * LD + j] = acc[i];
}
__device__ __forceinline__ void smm_glob(const float* A, const float* B, float* __restrict__ gout) {
    int j  = threadIdx.x & 63;
    int ib = (threadIdx.x >> 6) << 4;
    float acc[16];
#pragma unroll
    for (int i = 0; i < 16; i++) acc[i] = 0.f;
    for (int k = 0; k < 64; k++) {
        float bv = B[k * LD + j];
#pragma unroll
        for (int i = 0; i < 16; i++) acc[i] = fmaf(A[(ib + i) * LD + k], bv, acc[i]);
    }
#pragma unroll
    for (int i = 0; i < 16; i++) gout[(ib + i) * 64 + j] = acc[i];
}
__device__ __forceinline__ void scalecols(const float* V, const float* w, float* O) {
    for (int idx = threadIdx.x; idx < NN; idx += TPB) {
        int i = idx >> 6, k = idx & 63;
        O[i * LD + k] = V[i * LD + k] * w[k];
    }
}

// two-sided Jacobi (single-matrix kernels only)
__device__ void jacobi2s(float* A, float* V, int nsweeps) {
    int t = threadIdx.x;
    __shared__ float cs[32], sn[32];
    __shared__ uchar2 tab2[63 * 32];
    for (int idx = t; idx < 63 * 32; idx += TPB) {
        int r = idx >> 5, k = idx & 31, p, q;
        get_pair(r, k, p, q);
        tab2[idx] = make_uchar2((unsigned char)p, (unsigned char)q);
    }
    for (int idx = t; idx < NN; idx += TPB) {
        int i = idx >> 6, j = idx & 63;
        V[i * LD + j] = (i == j) ? 1.f : 0.f;
    }
    __syncthreads();
    for (int sw = 0; sw < nsweeps; ++sw) {
        for (int r = 0; r < 63; ++r) {
            const uchar2* trow = tab2 + (r << 5);
            if (t < 32) {
                uchar2 pq = trow[t];
                int pl = pq.x * LD, ql = pq.y * LD;
                float app = A[pl + pq.x], aqq = A[ql + pq.y], apq = A[pl + pq.y];
                float c, s;
                if (fabsf(apq) < 1e-30f) { c = 1.f; s = 0.f; }
                else {
                    float tau = (aqq - app) / (2.f * apq);
                    float tt  = copysignf(1.f, tau) / (fabsf(tau) + sqrtf(1.f + tau * tau));
                    c = rsqrtf(1.f + tt * tt);
                    s = tt * c;
                }
                cs[t] = c; sn[t] = s;
            }
            __syncthreads();
#pragma unroll
            for (int m = 0; m < 2048 / TPB; m++) {
                int w = t + m * TPB;
                int k = w >> 6, j = w & 63;
                uchar2 pq = trow[k];
                int pl = pq.x * LD + j, ql = pq.y * LD + j;
                float c = cs[k], s = sn[k];
                float ap = A[pl], aq = A[ql];
                A[pl] = c * ap - s * aq;
                A[ql] = fmaf(s, ap, c * aq);
            }
            __syncthreads();
#pragma unroll
            for (int m = 0; m < 2048 / TPB; m++) {
                int w = t + m * TPB;
                int k = w >> 6, i = w & 63;
                uchar2 pq = trow[k];
                int il = i * LD;
                int pl = il + pq.x, ql = il + pq.y;
                float c = cs[k], s = sn[k];
                float ap = A[pl], aq = A[ql];
                A[pl] = c * ap - s * aq;
                A[ql] = fmaf(s, ap, c * aq);
                float vp = V[pl], vq = V[ql];
                V[pl] = c * vp - s * vq;
                V[ql] = fmaf(s, vp, c * vq);
            }
            __syncthreads();
        }
    }
}

// ---------------------------------------------------------------------------
// batch GEMMs (f32x2)
// ---------------------------------------------------------------------------
__device__ __forceinline__ void gemm_rr(const float* A, const float* B, float* C) {
    int j  = threadIdx.x & 63;
    int ib = (threadIdx.x >> 6) << 4;
    ull acc[16];
#pragma unroll
    for (int i = 0; i < 16; i++) acc[i] = 0ull;
    for (int k = 0; k < 64; k += 2) {
        ull b2 = pk2(B[k * BLD + j], B[(k + 1) * BLD + j]);
#pragma unroll
        for (int i = 0; i < 16; i++) {
            ull a2 = *(const ull*)(A + (ib + i) * BLD + k);
            acc[i] = fma2(a2, b2, acc[i]);
        }
    }
#pragma unroll
    for (int i = 0; i < 16; i++) {
        float2 f = upk2(acc[i]);
        C[(ib + i) * BLD + j] = f.x + f.y;
    }
}
__device__ __forceinline__ void gemm_r2c(const float* A, const float* B, float* C) {
    int j  = threadIdx.x & 63;
    int ib = (threadIdx.x >> 6) << 4;
    ull acc[16];
#pragma unroll
    for (int i = 0; i < 16; i++) acc[i] = 0ull;
    for (int k = 0; k < 64; k += 2) {
        ull b2 = pk2(B[k * BLD + j], B[(k + 1) * BLD + j]);
#pragma unroll
        for (int i = 0; i < 16; i++) {
            ull a2 = *(const ull*)(A + (ib + i) * BLD + k);
            acc[i] = fma2(a2, b2, acc[i]);
        }
    }
    float r[16];
#pragma unroll
    for (int i = 0; i < 16; i++) { float2 f = upk2(acc[i]); r[i] = f.x + f.y; }
    float4* dst = (float4*)(C + j * CST + ib);
    dst[0] = make_float4(r[0],  r[1],  r[2],  r[3]);
    dst[1] = make_float4(r[4],  r[5],  r[6],  r[7]);
    dst[2] = make_float4(r[8],  r[9],  r[10], r[11]);
    dst[3] = make_float4(r[12], r[13], r[14], r[15]);
}

// epilogue: W[:,k] = B[:,k] * 0.5*log(n2)/n2
__device__ __forceinline__ void colscale_log(const float* B, float* W) {
    int t = threadIdx.x;
    int col = t >> 2, qc = t & 3;
    const float4* bc = (const float4*)(B + col * CST);
    float4 v0 = bc[qc * 4 + 0], v1 = bc[qc * 4 + 1];
    float4 v2 = bc[qc * 4 + 2], v3 = bc[qc * 4 + 3];
    float pn = d4(v0, v0) + d4(v1, v1) + d4(v2, v2) + d4(v3, v3);
    pn += __shfl_xor_sync(FULLM, pn, 1);
    pn += __shfl_xor_sync(FULLM, pn, 2);
    float n2 = fmaxf(pn, 1e-24f);
    float g = 0.5f * logf(n2) / n2;
    float4* wc = (float4*)(W + col * CST);
    v0.x *= g; v0.y *= g; v0.z *= g; v0.w *= g;
    v1.x *= g; v1.y *= g; v1.z *= g; v1.w *= g;
    v2.x *= g; v2.y *= g; v2.z *= g; v2.w *= g;
    v3.x *= g; v3.y *= g; v3.z *= g; v3.w *= g;
    wc[qc * 4 + 0] = v0; wc[qc * 4 + 1] = v1;
    wc[qc * 4 + 2] = v2; wc[qc * 4 + 3] = v3;
}
__device__ __forceinline__ void logm_atomic(const float* W, const float* B, float scale) {
    int j  = threadIdx.x & 63;
    int ib = (threadIdx.x >> 6) << 4;
    float acc[16];
#pragma unroll
    for (int i = 0; i < 16; i++) acc[i] = 0.f;
    for (int k = 0; k < 64; k++) {
        float bj = B[k * CST + j];
        const float4* wr = (const float4*)(W + k * CST + ib);
        float4 w0 = wr[0], w1 = wr[1], w2 = wr[2], w3 = wr[3];
        acc[0]  = fmaf(w0.x, bj, acc[0]);  acc[1]  = fmaf(w0.y, bj, acc[1]);
        acc[2]  = fmaf(w0.z, bj, acc[2]);  acc[3]  = fmaf(w0.w, bj, acc[3]);
        acc[4]  = fmaf(w1.x, bj, acc[4]);  acc[5]  = fmaf(w1.y, bj, acc[5]);
        acc[6]  = fmaf(w1.z, bj, acc[6]);  acc[7]  = fmaf(w1.w, bj, acc[7]);
        acc[8]  = fmaf(w2.x, bj, acc[8]);  acc[9]  = fmaf(w2.y, bj, acc[9]);
        acc[10] = fmaf(w2.z, bj, acc[10]); acc[11] = fmaf(w2.w, bj, acc[11]);
        acc[12] = fmaf(w3.x, bj, acc[12]); acc[13] = fmaf(w3.y, bj, acc[13]);
        acc[14] = fmaf(w3.z, bj, acc[14]); acc[15] = fmaf(w3.w, bj, acc[15]);
    }
#pragma unroll
    for (int i = 0; i < 16; i++) atomicAdd(&g_T[(ib + i) * 64 + j], acc[i] * scale);
}

// ---------------------------------------------------------------------------
// kernels
// ---------------------------------------------------------------------------
__global__ void k_zero(int which) {
    int i = blockIdx.x * blockDim.x + threadIdx.x;
    if (i < NN) { if (which == 0) g_M[i] = 0.f; else g_T[i] = 0.f; }
}

__global__ void k_mean_acc(const float* __restrict__ data, int per_chunk, float inv_nb) {
    int e = blockIdx.x * blockDim.x + threadIdx.x;
    const float* p = data + (size_t)(blockIdx.y) * per_chunk * NN + e;
    float sum = 0.f;
#pragma unroll 8
    for (int i = 0; i < per_chunk; i++) sum += p[(size_t)i * NN];
    atomicAdd(&g_M[e], sum * inv_nb);
}

__global__ void __launch_bounds__(TPB) k_eig_M() {
    extern __shared__ float sm[];
    float* A  = sm;
    float* V  = sm + BUF;
    float* T1 = sm + 2 * BUF;
    float* T2 = sm + 3 * BUF;
    __shared__ float w1[64], w2[64];
    load_g2s(g_M, A);
    __syncthreads();
    sym_s(A);
    __syncthreads();
    jacobi2s(A, V, NSWEEP_S);
    int t = threadIdx.x;
    if (t < 64) {
        float w = fmaxf(A[t * LD + t], 1e-12f);
        w1[t] = sqrtf(w);
        w2[t] = rsqrtf(w);
    }
    __syncthreads();
    scalecols(V, w1, T1); __syncthreads();
    smm_bt(T1, V, T2);    __syncthreads();
    store_s2g(T2, g_Ms);
    __syncthreads();
    scalecols(V, w2, T1); __syncthreads();
    smm_bt(T1, V, T2);    __syncthreads();
    store_s2g(T2, g_Mi);
}

// -------- register-resident odd-even one-sided Jacobi batch step -----------
__global__ void __launch_bounds__(TPB, 4) k_batch_oe(const float* __restrict__ data,
                                                     float inv_nb) {
    extern __shared__ float sm[];
    float* s0 = sm;             // Mi (row) -> xbufA overlay -> W (col)
    float* s1 = sm + BUFB;      // D (row)  -> C (col) -> B (col)
    float* s2 = sm + 2 * BUFB;  // temp (row) -> xbufB overlay
    __shared__ float2 xP[2][8];
    int t = threadIdx.x;
    size_t b = blockIdx.x;

    for (int idx = t; idx < NN; idx += TPB)
        s0[(idx >> 6) * BLD + (idx & 63)] = g_Mi[idx];
    const float* D = data + b * NN;
    for (int idx = t; idx < NN; idx += TPB)
        s1[(idx >> 6) * BLD + (idx & 63)] = D[idx];
    __syncthreads();
    gemm_rr(s0, s1, s2);    // s2 = Mi * D (row)
    __syncthreads();
    gemm_r2c(s2, s0, s1);   // s1 = C (col-major CST)
    __syncthreads();
    // symmetrize C in place
    for (int idx = t; idx < NN; idx += TPB) {
        int i = idx >> 6, j = idx & 63;
        if (i < j) {
            float v = 0.5f * (s1[i * CST + j] + s1[j * CST + i]);
            s1[i * CST + j] = v;
            s1[j * CST + i] = v;
        }
    }
    __syncthreads();

    // ---- load 2 columns per 8-lane group into registers ----
    int lane = t & 31, warp = t >> 5, grp = lane >> 3, sub = lane & 7;
    int G = warp * 4 + grp;           // group id / slot pair (2G, 2G+1)
    ull cL[4], cR[4];
    {
        const ulonglong2* pc = (const ulonglong2*)(s1 + (2 * G) * CST);
        ulonglong2 q0 = pc[2 * sub], q1 = pc[2 * sub + 1];
        cL[0] = q0.x; cL[1] = q0.y; cL[2] = q1.x; cL[3] = q1.y;
        const ulonglong2* pd = (const ulonglong2*)(s1 + (2 * G + 1) * CST);
        q0 = pd[2 * sub]; q1 = pd[2 * sub + 1];
        cR[0] = q0.x; cR[1] = q0.y; cR[2] = q1.x; cR[3] = q1.y;
    }
    __syncthreads();   // everyone has read s1 -> safe to keep, xbufs live in s0/s2

    ull* xA = (ull*)s0;     // grp3 right-columns, [2][8] cols, 34 ull stride
    ull* xB = (ull*)s2;     // grp0 left-columns
    const bool hasR = !(warp == 7 && grp == 3);
    const bool hasL = !(warp == 0 && grp == 0);
    const int srcR = (lane + 8) & 31;     // pull from grp+1
    const int srcL = (lane + 24) & 31;    // pull from grp-1
    int pb = 0;

    for (int sw = 0; sw < NSWEEP_B; ++sw) {
        for (int rr = 0; rr < 32; ++rr) {
            // ---- EVEN round: pair (2G, 2G+1), registers only ----
            {
                float app, aqq, apq;
                dots8(cL, cR, app, aqq, apq);
                float c, s;
                rot_params(app, aqq, apq, c, s);
                ull c2 = pk2(c, c), s2p = pk2(s, s), ns2 = pk2(-s, -s);
#pragma unroll
                for (int i = 0; i < 4; i++) {
                    ull u = cL[i], v = cR[i];
                    cL[i] = fma2(s2p, u, mul2(c2, v));   // v' = s u + c v
                    cR[i] = fma2(ns2, v, mul2(c2, u));   // u' = c u - s v
                }
            }
            // ---- ODD round: pair (2G+1, 2G+2) ----
            {
                // boundary column publish
                if (grp == 3) {
                    ulonglong2* p = (ulonglong2*)(xA + (pb * 8 + warp) * 34);
                    p[2 * sub]     = make_ulonglong2(cR[0], cR[1]);
                    p[2 * sub + 1] = make_ulonglong2(cR[2], cR[3]);
                }
                if (grp == 0) {
                    ulonglong2* p = (ulonglong2*)(xB + (pb * 8 + warp) * 34);
                    p[2 * sub]     = make_ulonglong2(cL[0], cL[1]);
                    p[2 * sub + 1] = make_ulonglong2(cL[2], cL[3]);
                }
                __syncthreads();
                ull vR[4], uL[4];
#pragma unroll
                for (int i = 0; i < 4; i++) vR[i] = shfl_ull(cL[i], srcR);
#pragma unroll
                for (int i = 0; i < 4; i++) uL[i] = shfl_ull(cR[i], srcL);
                if (grp == 3 && warp < 7) {
                    const ulonglong2* p = (const ulonglong2*)(xB + (pb * 8 + warp + 1) * 34);
                    ulonglong2 q0 = p[2 * sub], q1 = p[2 * sub + 1];
                    vR[0] = q0.x; vR[1] = q0.y; vR[2] = q1.x; vR[3] = q1.y;
                }
                if (grp == 0 && warp > 0) {
                    const ulonglong2* p = (const ulonglong2*)(xA + (pb * 8 + warp - 1) * 34);
                    ulonglong2 q0 = p[2 * sub], q1 = p[2 * sub + 1];
                    uL[0] = q0.x; uL[1] = q0.y; uL[2] = q1.x; uL[3] = q1.y;
                }
                // right-pair params (u = cR, v = vR)
                float app, aqq, apq;
                dots8(cR, vR, app, aqq, apq);
                float c, s;
                rot_params(app, aqq, apq, c, s);
                if (grp == 3 && sub == 0) xP[pb][warp] = make_float2(c, s);
                __syncthreads();
                // left-pair params = left neighbor's right-pair params
                float cl = __shfl_sync(FULLM, c, srcL);
                float sl = __shfl_sync(FULLM, s, srcL);
                if (grp == 0 && warp > 0) {
                    float2 ps = xP[pb][warp - 1];
                    cl = ps.x; sl = ps.y;
                }
                if (hasR) {
                    ull c2 = pk2(c, c), s2p = pk2(s, s);
#pragma unroll
                    for (int i = 0; i < 4; i++)
                        cR[i] = fma2(s2p, cR[i], mul2(c2, vR[i]));   // v' = s u + c v
                }
                if (hasL) {
                    ull cl2 = pk2(cl, cl), nsl2 = pk2(-sl, -sl);
#pragma unroll
                    for (int i = 0; i < 4; i++)
                        cL[i] = fma2(nsl2, cL[i], mul2(cl2, uL[i])); // u' = cl u - sl v
                }
                pb ^= 1;
            }
        }
    }

    // ---- store columns back to s1 (col-major CST), permutation irrelevant ----
    {
        ulonglong2* pc = (ulonglong2*)(s1 + (2 * G) * CST);
        pc[2 * sub]     = make_ulonglong2(cL[0], cL[1]);
        pc[2 * sub + 1] = make_ulonglong2(cL[2], cL[3]);
        ulonglong2* pd = (ulonglong2*)(s1 + (2 * G + 1) * CST);
        pd[2 * sub]     = make_ulonglong2(cR[0], cR[1]);
        pd[2 * sub + 1] = make_ulonglong2(cR[2], cR[3]);
    }
    __syncthreads();
    colscale_log(s1, s0);     // s0 = W = B * diag(log l / l^2)
    __syncthreads();
    logm_atomic(s0, s1, inv_nb);
}

__global__ void __launch_bounds__(TPB) k_update_M() {
    extern __shared__ float sm[];
    float* A  = sm;
    float* V  = sm + BUF;
    float* T1 = sm + 2 * BUF;
    float* T2 = sm + 3 * BUF;
    __shared__ float ew[64];
    load_g2s(g_T, A);
    __syncthreads();
    sym_s(A);
    __syncthreads();
    jacobi2s(A, V, NSWEEP_S);
    int t = threadIdx.x;
    if (t < 64) ew[t] = expf(A[t * LD + t]);
    __syncthreads();
    scalecols(V, ew, T1); __syncthreads();
    smm_bt(T1, V, T2);    __syncthreads();
    load_g2s(g_Ms, A);    __syncthreads();
    smm(A, T2, T1);       __syncthreads();
    smm_glob(T1, A, g_M);
}

__global__ void __launch_bounds__(TPB) k_bias(const float* __restrict__ bias) {
    extern __shared__ float sm[];
    float* A  = sm;
    float* V  = sm + BUF;
    float* T1 = sm + 2 * BUF;
    float* T2 = sm + 3 * BUF;
    __shared__ float ew[64];
    int t = threadIdx.x;
    for (int idx = t; idx < NN; idx += TPB) {
        int i = idx >> 6, j = idx & 63;
        A[i * LD + j] = 0.5f * (bias[i * 64 + j] + bias[j * 64 + i]);
    }
    __syncthreads();
    jacobi2s(A, V, NSWEEP_S);
    if (t < 64) ew[t] = expf(0.5f * A[t * LD + t]);
    __syncthreads();
    scalecols(V, ew, T1); __syncthreads();
    smm_bt(T1, V, T2);    __syncthreads();
    load_g2s(g_Mi, A);    __syncthreads();
    smm_glob(T2, A, g_W);
}

__global__ void __launch_bounds__(TPB, 4) k_final(const float* __restrict__ data,
                                                  float* __restrict__ out) {
    extern __shared__ float sm[];
    float* sW = sm;
    float* sD = sm + BUFB;
    float* sT = sm + 2 * BUFB;
    size_t b = blockIdx.x;
    int t = threadIdx.x;
    for (int idx = t; idx < NN; idx += TPB)
        sW[(idx >> 6) * BLD + (idx & 63)] = g_W[idx];
    const float* D = data + b * NN;
    for (int idx = t; idx < NN; idx += TPB)
        sD[(idx >> 6) * BLD + (idx & 63)] = D[idx];
    __syncthreads();
    gemm_rr(sW, sD, sT);
    __syncthreads();
    int j  = t & 63;
    int ib = (t >> 6) << 4;
    ull acc[16];
#pragma unroll
    for (int i = 0; i < 16; i++) acc[i] = 0ull;
    for (int k = 0; k < 64; k += 2) {
        ull b2 = *(const ull*)(sW + j * BLD + k);
#pragma unroll
        for (int i = 0; i < 16; i++) {
            ull a2 = *(const ull*)(sT + (ib + i) * BLD + k);
            acc[i] = fma2(a2, b2, acc[i]);
        }
    }
    float* o = out + b * NN;
#pragma unroll
    for (int i = 0; i < 16; i++) {
        float2 f = upk2(acc[i]);
        o[(ib + i) * 64 + j] = f.x + f.y;
    }
}

// ---------------------------------------------------------------------------
extern "C" void kernel_launch(void* const* d_in, const int* in_sizes, int n_in,
                              void* d_out, int out_size) {
    const float* data;
    const float* bias;
    int nb;
    if (in_sizes[0] >= in_sizes[1]) {
        data = (const float*)d_in[0]; bias = (const float*)d_in[1];
        nb = in_sizes[0] / NN;
    } else {
        data = (const float*)d_in[1]; bias = (const float*)d_in[0];
        nb = in_sizes[1] / NN;
    }
    float* out = (float*)d_out;
    float inv_nb = 1.0f / (float)nb;

    size_t smemS = 4 * BUF  * sizeof(float);
    size_t smemB = 3 * BUFB * sizeof(float);
    cudaFuncSetAttribute(k_eig_M,    cudaFuncAttributeMaxDynamicSharedMemorySize, (int)smemS);
    cudaFuncSetAttribute(k_batch_oe, cudaFuncAttributeMaxDynamicSharedMemorySize, (int)smemB);
    cudaFuncSetAttribute(k_update_M, cudaFuncAttributeMaxDynamicSharedMemorySize, (int)smemS);
    cudaFuncSetAttribute(k_bias,     cudaFuncAttributeMaxDynamicSharedMemorySize, (int)smemS);
    cudaFuncSetAttribute(k_final,    cudaFuncAttributeMaxDynamicSharedMemorySize, (int)smemB);

    // arithmetic mean
    k_zero<<<16, 256>>>(0);
    {
        int nchunk = 64;
        while (nchunk > 1 && (nb % nchunk) != 0) nchunk >>= 1;
        int per_chunk = nb / nchunk;
        dim3 g(NN / 256, nchunk);
        k_mean_acc<<<g, 256>>>(data, per_chunk, inv_nb);
    }

    // 3 Karcher iterations
    for (int it = 0; it < 3; ++it) {
        k_eig_M<<<1, TPB, smemS>>>();
        k_zero<<<16, 256>>>(1);
        k_batch_oe<<<nb, TPB, smemB>>>(data, inv_nb);
        k_update_M<<<1, TPB, smemS>>>();
    }

    // final whitening + bias congruence
    k_eig_M<<<1, TPB, smemS>>>();
    k_bias<<<1, TPB, smemS>>>(bias);
    k_final<<<nb, TPB, smemB>>>(data, out);
}

// round 9
// speedup vs baseline: 5.4083x; 1.0847x over previous
#include <cuda_runtime.h>
#include <cuda_bf16.h>
#include <math.h>

// ============================================================================
// BatchNormSPDMean R9: R8 (smem column migration, 2-term reduction) with the
// divergent-shfl hang fixed: collectives run unconditionally on all lanes;
// boundary groups get zero neighbor columns -> identity rotation.
// ============================================================================

#define NN 4096
#define LD 65        // single-matrix kernels row stride
#define BLD 66       // batch row-major stride
#define CST 68       // batch col-major column stride
#define BUFB 4352
#define NSWEEP_B 7
#define NSWEEP_S 10
#define TPB 256
#define BUF 4160
#define FULLM 0xffffffffu

typedef unsigned long long ull;

// ---- persistent scratch ----
__device__ float g_M [NN];
__device__ float g_Ms[NN];
__device__ float g_Mi[NN];
__device__ float g_T [NN];
__device__ float g_W [NN];

// ---------------------------------------------------------------------------
// f32x2 packed helpers
// ---------------------------------------------------------------------------
__device__ __forceinline__ ull pk2(float lo, float hi) {
    ull r; asm("mov.b64 %0,{%1,%2};" : "=l"(r) : "f"(lo), "f"(hi)); return r;
}
__device__ __forceinline__ float2 upk2(ull v) {
    float2 r; asm("mov.b64 {%0,%1},%2;" : "=f"(r.x), "=f"(r.y) : "l"(v)); return r;
}
__device__ __forceinline__ ull fma2(ull a, ull b, ull c) {
    ull r; asm("fma.rn.f32x2 %0,%1,%2,%3;" : "=l"(r) : "l"(a), "l"(b), "l"(c)); return r;
}
__device__ __forceinline__ ull mul2(ull a, ull b) {
    ull r; asm("mul.rn.f32x2 %0,%1,%2;" : "=l"(r) : "l"(a), "l"(b)); return r;
}
__device__ __forceinline__ float hadd2(ull v) { float2 f = upk2(v); return f.x + f.y; }
__device__ __forceinline__ float d4(float4 a, float4 b) {
    return fmaf(a.x, b.x, fmaf(a.y, b.y, fmaf(a.z, b.z, a.w * b.w)));
}
// 2-term dots: dd = |v|^2 - |u|^2, apq = <u,v>, reduced over 8-lane group.
// MUST be executed by all 32 lanes of a warp (contains full-mask shfl).
__device__ __forceinline__ void dots2(const ull* u, const ull* v,
                                      float& dd, float& apq) {
    ull U = mul2(u[0], u[0]), V = mul2(v[0], v[0]), P = mul2(u[0], v[0]);
#pragma unroll
    for (int i = 1; i < 4; i++) {
        U = fma2(u[i], u[i], U);
        V = fma2(v[i], v[i], V);
        P = fma2(u[i], v[i], P);
    }
    float d = hadd2(V) - hadd2(U);
    float p = hadd2(P);
#pragma unroll
    for (int k = 1; k < 8; k <<= 1) {
        d += __shfl_xor_sync(FULLM, d, k);
        p += __shfl_xor_sync(FULLM, p, k);
    }
    dd = d; apq = p;
}
// rotation params from dd = aqq-app and apq (apq==0 -> exact identity)
__device__ __forceinline__ void rot_params2(float dd, float apq, float& c, float& s) {
    if (fabsf(apq) > 1e-34f) {
        float tau = __fdividef(dd, 2.f * apq);
        float tt  = copysignf(1.f, tau) / (fabsf(tau) + sqrtf(1.f + tau * tau));
        c = rsqrtf(1.f + tt * tt);
        s = tt * c;
    } else { c = 1.f; s = 0.f; }
}

// tournament pairing (two-sided jacobi only)
__device__ __forceinline__ void get_pair(int r, int k, int& p, int& q) {
    int a = (k == 0) ? 0 : 1 + (k - 1 + r) % 63;
    int b = 1 + (62 - k + r) % 63;
    p = a < b ? a : b;
    q = a < b ? b : a;
}

// ---------------------------------------------------------------------------
// single-matrix helpers (LD=65 world)
// ---------------------------------------------------------------------------
__device__ __forceinline__ void load_g2s(const float* __restrict__ g, float* S) {
    for (int idx = threadIdx.x; idx < NN; idx += TPB)
        S[(idx >> 6) * LD + (idx & 63)] = g[idx];
}
__device__ __forceinline__ void store_s2g(const float* S, float* __restrict__ g) {
    for (int idx = threadIdx.x; idx < NN; idx += TPB)
        g[idx] = S[(idx >> 6) * LD + (idx & 63)];
}
__device__ __forceinline__ void sym_s(float* A) {
    for (int idx = threadIdx.x; idx < NN; idx += TPB) {
        int i = idx >> 6, j = idx & 63;
        if (i < j) {
            float v = 0.5f * (A[i * LD + j] + A[j * LD + i]);
            A[i * LD + j] = v;
            A[j * LD + i] = v;
        }
    }
}
__device__ __forceinline__ void smm(const float* A, const float* B, float* C) {
    int j  = threadIdx.x & 63;
    int ib = (threadIdx.x >> 6) << 4;
    float acc[16];
#pragma unroll
    for (int i = 0; i < 16; i++) acc[i] = 0.f;
    for (int k = 0; k < 64; k++) {
        float bv = B[k * LD + j];
#pragma unroll
        for (int i = 0; i < 16; i++) acc[i] = fmaf(A[(ib + i) * LD + k], bv, acc[i]);
    }
#pragma unroll
    for (int i = 0; i < 16; i++) C[(ib + i) * LD + j] = acc[i];
}
__device__ __forceinline__ void smm_bt(const float* A, const float* B, float* C) {
    int j  = threadIdx.x & 63;
    int ib = (threadIdx.x >> 6) << 4;
    float acc[16];
#pragma unroll
    for (int i = 0; i < 16; i++) acc[i] = 0.f;
    for (int k = 0; k < 64; k++) {
        float bv = B[j * LD + k];
#pragma unroll
        for (int i = 0; i < 16; i++) acc[i] = fmaf(A[(ib + i) * LD + k], bv, acc[i]);
    }
#pragma unroll
    for (int i = 0; i < 16; i++) C[(ib + i) * LD + j] = acc[i];
}
__device__ __forceinline__ void smm_glob(const float* A, const float* B, float* __restrict__ gout) {
    int j  = threadIdx.x & 63;
    int ib = (threadIdx.x >> 6) << 4;
    float acc[16];
#pragma unroll
    for (int i = 0; i < 16; i++) acc[i] = 0.f;
    for (int k = 0; k < 64; k++) {
        float bv = B[k * LD + j];
#pragma unroll
        for (int i = 0; i < 16; i++) acc[i] = fmaf(A[(ib + i) * LD + k], bv, acc[i]);
    }
#pragma unroll
    for (int i = 0; i < 16; i++) gout[(ib + i) * 64 + j] = acc[i];
}
__device__ __forceinline__ void scalecols(const float* V, const float* w, float* O) {
    for (int idx = threadIdx.x; idx < NN; idx += TPB) {
        int i = idx >> 6, k = idx & 63;
        O[i * LD + k] = V[i * LD + k] * w[k];
    }
}

// two-sided Jacobi (single-matrix kernels only)
__device__ void jacobi2s(float* A, float* V, int nsweeps) {
    int t = threadIdx.x;
    __shared__ float cs[32], sn[32];
    __shared__ uchar2 tab2[63 * 32];
    for (int idx = t; idx < 63 * 32; idx += TPB) {
        int r = idx >> 5, k = idx & 31, p, q;
        get_pair(r, k, p, q);
        tab2[idx] = make_uchar2((unsigned char)p, (unsigned char)q);
    }
    for (int idx = t; idx < NN; idx += TPB) {
        int i = idx >> 6, j = idx & 63;
        V[i * LD + j] = (i == j) ? 1.f : 0.f;
    }
    __syncthreads();
    for (int sw = 0; sw < nsweeps; ++sw) {
        for (int r = 0; r < 63; ++r) {
            const uchar2* trow = tab2 + (r << 5);
            if (t < 32) {
                uchar2 pq = trow[t];
                int pl = pq.x * LD, ql = pq.y * LD;
                float app = A[pl + pq.x], aqq = A[ql + pq.y], apq = A[pl + pq.y];
                float c, s;
                if (fabsf(apq) < 1e-30f) { c = 1.f; s = 0.f; }
                else {
                    float tau = (aqq - app) / (2.f * apq);
                    float tt  = copysignf(1.f, tau) / (fabsf(tau) + sqrtf(1.f + tau * tau));
                    c = rsqrtf(1.f + tt * tt);
                    s = tt * c;
                }
                cs[t] = c; sn[t] = s;
            }
            __syncthreads();
#pragma unroll
            for (int m = 0; m < 2048 / TPB; m++) {
                int w = t + m * TPB;
                int k = w >> 6, j = w & 63;
                uchar2 pq = trow[k];
                int pl = pq.x * LD + j, ql = pq.y * LD + j;
                float c = cs[k], s = sn[k];
                float ap = A[pl], aq = A[ql];
                A[pl] = c * ap - s * aq;
                A[ql] = fmaf(s, ap, c * aq);
            }
            __syncthreads();
#pragma unroll
            for (int m = 0; m < 2048 / TPB; m++) {
                int w = t + m * TPB;
                int k = w >> 6, i = w & 63;
                uchar2 pq = trow[k];
                int il = i * LD;
                int pl = il + pq.x, ql = il + pq.y;
                float c = cs[k], s = sn[k];
                float ap = A[pl], aq = A[ql];
                A[pl] = c * ap - s * aq;
                A[ql] = fmaf(s, ap, c * aq);
                float vp = V[pl], vq = V[ql];
                V[pl] = c * vp - s * vq;
                V[ql] = fmaf(s, vp, c * vq);
            }
            __syncthreads();
        }
    }
}

// ---------------------------------------------------------------------------
// batch GEMMs (f32x2)
// ---------------------------------------------------------------------------
__device__ __forceinline__ void gemm_rr(const float* A, const float* B, float* C) {
    int j  = threadIdx.x & 63;
    int ib = (threadIdx.x >> 6) << 4;
    ull acc[16];
#pragma unroll
    for (int i = 0; i < 16; i++) acc[i] = 0ull;
    for (int k = 0; k < 64; k += 2) {
        ull b2 = pk2(B[k * BLD + j], B[(k + 1) * BLD + j]);
#pragma unroll
        for (int i = 0; i < 16; i++) {
            ull a2 = *(const ull*)(A + (ib + i) * BLD + k);
            acc[i] = fma2(a2, b2, acc[i]);
        }
    }
#pragma unroll
    for (int i = 0; i < 16; i++) {
        float2 f = upk2(acc[i]);
        C[(ib + i) * BLD + j] = f.x + f.y;
    }
}
__device__ __forceinline__ void gemm_r2c(const float* A, const float* B, float* C) {
    int j  = threadIdx.x & 63;
    int ib = (threadIdx.x >> 6) << 4;
    ull acc[16];
#pragma unroll
    for (int i = 0; i < 16; i++) acc[i] = 0ull;
    for (int k = 0; k < 64; k += 2) {
        ull b2 = pk2(B[k * BLD + j], B[(k + 1) * BLD + j]);
#pragma unroll
        for (int i = 0; i < 16; i++) {
            ull a2 = *(const ull*)(A + (ib + i) * BLD + k);
            acc[i] = fma2(a2, b2, acc[i]);
        }
    }
    float r[16];
#pragma unroll
    for (int i = 0; i < 16; i++) { float2 f = upk2(acc[i]); r[i] = f.x + f.y; }
    float4* dst = (float4*)(C + j * CST + ib);
    dst[0] = make_float4(r[0],  r[1],  r[2],  r[3]);
    dst[1] = make_float4(r[4],  r[5],  r[6],  r[7]);
    dst[2] = make_float4(r[8],  r[9],  r[10], r[11]);
    dst[3] = make_float4(r[12], r[13], r[14], r[15]);
}

// epilogue: W[:,k] = B[:,k] * 0.5*log(n2)/n2
__device__ __forceinline__ void colscale_log(const float* B, float* W) {
    int t = threadIdx.x;
    int col = t >> 2, qc = t & 3;
    const float4* bc = (const float4*)(B + col * CST);
    float4 v0 = bc[qc * 4 + 0], v1 = bc[qc * 4 + 1];
    float4 v2 = bc[qc * 4 + 2], v3 = bc[qc * 4 + 3];
    float pn = d4(v0, v0) + d4(v1, v1) + d4(v2, v2) + d4(v3, v3);
    pn += __shfl_xor_sync(FULLM, pn, 1);
    pn += __shfl_xor_sync(FULLM, pn, 2);
    float n2 = fmaxf(pn, 1e-24f);
    float g = 0.5f * logf(n2) / n2;
    float4* wc = (float4*)(W + col * CST);
    v0.x *= g; v0.y *= g; v0.z *= g; v0.w *= g;
    v1.x *= g; v1.y *= g; v1.z *= g; v1.w *= g;
    v2.x *= g; v2.y *= g; v2.z *= g; v2.w *= g;
    v3.x *= g; v3.y *= g; v3.z *= g; v3.w *= g;
    wc[qc * 4 + 0] = v0; wc[qc * 4 + 1] = v1;
    wc[qc * 4 + 2] = v2; wc[qc * 4 + 3] = v3;
}
__device__ __forceinline__ void logm_atomic(const float* W, const float* B, float scale) {
    int j  = threadIdx.x & 63;
    int ib = (threadIdx.x >> 6) << 4;
    float acc[16];
#pragma unroll
    for (int i = 0; i < 16; i++) acc[i] = 0.f;
    for (int k = 0; k < 64; k++) {
        float bj = B[k * CST + j];
        const float4* wr = (const float4*)(W + k * CST + ib);
        float4 w0 = wr[0], w1 = wr[1], w2 = wr[2], w3 = wr[3];
        acc[0]  = fmaf(w0.x, bj, acc[0]);  acc[1]  = fmaf(w0.y, bj, acc[1]);
        acc[2]  = fmaf(w0.z, bj, acc[2]);  acc[3]  = fmaf(w0.w, bj, acc[3]);
        acc[4]  = fmaf(w1.x, bj, acc[4]);  acc[5]  = fmaf(w1.y, bj, acc[5]);
        acc[6]  = fmaf(w1.z, bj, acc[6]);  acc[7]  = fmaf(w1.w, bj, acc[7]);
        acc[8]  = fmaf(w2.x, bj, acc[8]);  acc[9]  = fmaf(w2.y, bj, acc[9]);
        acc[10] = fmaf(w2.z, bj, acc[10]); acc[11] = fmaf(w2.w, bj, acc[11]);
        acc[12] = fmaf(w3.x, bj, acc[12]); acc[13] = fmaf(w3.y, bj, acc[13]);
        acc[14] = fmaf(w3.z, bj, acc[14]); acc[15] = fmaf(w3.w, bj, acc[15]);
    }
#pragma unroll
    for (int i = 0; i < 16; i++) atomicAdd(&g_T[(ib + i) * 64 + j], acc[i] * scale);
}

// ---------------------------------------------------------------------------
// kernels
// ---------------------------------------------------------------------------
__global__ void k_zero(int which) {
    int i = blockIdx.x * blockDim.x + threadIdx.x;
    if (i < NN) { if (which == 0) g_M[i] = 0.f; else g_T[i] = 0.f; }
}

__global__ void k_mean_acc(const float* __restrict__ data, int per_chunk, float inv_nb) {
    int e = blockIdx.x * blockDim.x + threadIdx.x;
    const float* p = data + (size_t)(blockIdx.y) * per_chunk * NN + e;
    float sum = 0.f;
#pragma unroll 8
    for (int i = 0; i < per_chunk; i++) sum += p[(size_t)i * NN];
    atomicAdd(&g_M[e], sum * inv_nb);
}

__global__ void __launch_bounds__(TPB) k_eig_M() {
    extern __shared__ float sm[];
    float* A  = sm;
    float* V  = sm + BUF;
    float* T1 = sm + 2 * BUF;
    float* T2 = sm + 3 * BUF;
    __shared__ float w1[64], w2[64];
    load_g2s(g_M, A);
    __syncthreads();
    sym_s(A);
    __syncthreads();
    jacobi2s(A, V, NSWEEP_S);
    int t = threadIdx.x;
    if (t < 64) {
        float w = fmaxf(A[t * LD + t], 1e-12f);
        w1[t] = sqrtf(w);
        w2[t] = rsqrtf(w);
    }
    __syncthreads();
    scalecols(V, w1, T1); __syncthreads();
    smm_bt(T1, V, T2);    __syncthreads();
    store_s2g(T2, g_Ms);
    __syncthreads();
    scalecols(V, w2, T1); __syncthreads();
    smm_bt(T1, V, T2);    __syncthreads();
    store_s2g(T2, g_Mi);
}

// -------- register odd-even one-sided Jacobi, SMEM migration ----------------
__global__ void __launch_bounds__(TPB, 4) k_batch_oe(const float* __restrict__ data,
                                                     float inv_nb) {
    extern __shared__ float sm[];
    float* s0 = sm;             // Mi (row) -> xL overlay -> W (col)
    float* s1 = sm + BUFB;      // D (row)  -> C (col) -> B (col)
    float* s2 = sm + 2 * BUFB;  // temp (row) -> xR overlay
    __shared__ float2 prm[2][32];
    int t = threadIdx.x;
    size_t b = blockIdx.x;

    for (int idx = t; idx < NN; idx += TPB)
        s0[(idx >> 6) * BLD + (idx & 63)] = g_Mi[idx];
    const float* D = data + b * NN;
    for (int idx = t; idx < NN; idx += TPB)
        s1[(idx >> 6) * BLD + (idx & 63)] = D[idx];
    __syncthreads();
    gemm_rr(s0, s1, s2);    // s2 = Mi * D (row)
    __syncthreads();
    gemm_r2c(s2, s0, s1);   // s1 = C (col-major CST)
    __syncthreads();
    // symmetrize C in place
    for (int idx = t; idx < NN; idx += TPB) {
        int i = idx >> 6, j = idx & 63;
        if (i < j) {
            float v = 0.5f * (s1[i * CST + j] + s1[j * CST + i]);
            s1[i * CST + j] = v;
            s1[j * CST + i] = v;
        }
    }
    __syncthreads();

    // ---- load 2 columns per 8-lane group into registers ----
    int lane = t & 31, warp = t >> 5, grp = lane >> 3, sub = lane & 7;
    int G = warp * 4 + grp;           // group id; owns slots (2G, 2G+1)
    ull cL[4], cR[4];
    {
        const ulonglong2* pc = (const ulonglong2*)(s1 + (2 * G) * CST);
        ulonglong2 q0 = pc[2 * sub], q1 = pc[2 * sub + 1];
        cL[0] = q0.x; cL[1] = q0.y; cL[2] = q1.x; cL[3] = q1.y;
        const ulonglong2* pd = (const ulonglong2*)(s1 + (2 * G + 1) * CST);
        q0 = pd[2 * sub]; q1 = pd[2 * sub + 1];
        cR[0] = q0.x; cR[1] = q0.y; cR[2] = q1.x; cR[3] = q1.y;
    }
    __syncthreads();   // s0/s2 freed for xbuf overlays

    // xbuf layout: [pb][col G] of 64 floats (lane sub: float4 slots sub, sub+8)
    const bool hasR = (G < 31);
    const bool hasL = (G > 0);
    int pb = 0;

    for (int sw = 0; sw < NSWEEP_B; ++sw) {
        for (int rr = 0; rr < 32; ++rr) {
            // ---- EVEN round: pair (2G, 2G+1), registers only, swap ----
            {
                float dd, apq;
                dots2(cL, cR, dd, apq);          // all lanes (collective)
                float c, s;
                rot_params2(dd, apq, c, s);
                ull c2 = pk2(c, c), s2p = pk2(s, s), ns2 = pk2(-s, -s);
#pragma unroll
                for (int i = 0; i < 4; i++) {
                    ull u = cL[i], v = cR[i];
                    cL[i] = fma2(s2p, u, mul2(c2, v));   // v' = s u + c v
                    cR[i] = fma2(ns2, v, mul2(c2, u));   // u' = c u - s v
                }
            }
            // ---- ODD round: pair (2G+1, 2G+2) via smem exchange ----
            {
                float4* Lb = (float4*)(s0 + ((pb << 5) + G) * 64);
                float4* Rb = (float4*)(s2 + ((pb << 5) + G) * 64);
                Lb[sub]     = *(float4*)&cL[0];
                Lb[sub + 8] = *(float4*)&cL[2];
                Rb[sub]     = *(float4*)&cR[0];
                Rb[sub + 8] = *(float4*)&cR[2];
                __syncthreads();
                // zero-init neighbors: boundary groups -> apq==0 -> identity
                ull vR[4] = {0ull, 0ull, 0ull, 0ull};
                ull uL[4] = {0ull, 0ull, 0ull, 0ull};
                if (hasR) {
                    const float4* p = (const float4*)(s0 + ((pb << 5) + G + 1) * 64);
                    *(float4*)&vR[0] = p[sub];
                    *(float4*)&vR[2] = p[sub + 8];
                }
                if (hasL) {
                    const float4* p = (const float4*)(s2 + ((pb << 5) + G - 1) * 64);
                    *(float4*)&uL[0] = p[sub];
                    *(float4*)&uL[2] = p[sub + 8];
                }
                // collective: all lanes participate (vR=0 for G=31 -> identity)
                float dd, apq;
                dots2(cR, vR, dd, apq);
                float c, s;
                rot_params2(dd, apq, c, s);
                if (sub == 0) prm[pb][G] = make_float2(c, s);
                __syncthreads();
                if (hasR) {
                    ull c2 = pk2(c, c), s2p = pk2(s, s);
#pragma unroll
                    for (int i = 0; i < 4; i++)
                        cR[i] = fma2(s2p, cR[i], mul2(c2, vR[i]));   // v' = s u + c v
                }
                if (hasL) {
                    float2 ps = prm[pb][G - 1];
                    ull cl2 = pk2(ps.x, ps.x), nsl2 = pk2(-ps.y, -ps.y);
#pragma unroll
                    for (int i = 0; i < 4; i++)
                        cL[i] = fma2(nsl2, cL[i], mul2(cl2, uL[i])); // u' = c u - s v
                }
                pb ^= 1;
            }
        }
    }

    // ---- store columns back to s1 (col-major CST), permutation irrelevant ----
    {
        ulonglong2* pc = (ulonglong2*)(s1 + (2 * G) * CST);
        pc[2 * sub]     = make_ulonglong2(cL[0], cL[1]);
        pc[2 * sub + 1] = make_ulonglong2(cL[2], cL[3]);
        ulonglong2* pd = (ulonglong2*)(s1 + (2 * G + 1) * CST);
        pd[2 * sub]     = make_ulonglong2(cR[0], cR[1]);
        pd[2 * sub + 1] = make_ulonglong2(cR[2], cR[3]);
    }
    __syncthreads();
    colscale_log(s1, s0);     // s0 = W = B * diag(log l / l^2)
    __syncthreads();
    logm_atomic(s0, s1, inv_nb);
}

__global__ void __launch_bounds__(TPB) k_update_M() {
    extern __shared__ float sm[];
    float* A  = sm;
    float* V  = sm + BUF;
    float* T1 = sm + 2 * BUF;
    float* T2 = sm + 3 * BUF;
    __shared__ float ew[64];
    load_g2s(g_T, A);
    __syncthreads();
    sym_s(A);
    __syncthreads();
    jacobi2s(A, V, NSWEEP_S);
    int t = threadIdx.x;
    if (t < 64) ew[t] = expf(A[t * LD + t]);
    __syncthreads();
    scalecols(V, ew, T1); __syncthreads();
    smm_bt(T1, V, T2);    __syncthreads();
    load_g2s(g_Ms, A);    __syncthreads();
    smm(A, T2, T1);       __syncthreads();
    smm_glob(T1, A, g_M);
}

__global__ void __launch_bounds__(TPB) k_bias(const float* __restrict__ bias) {
    extern __shared__ float sm[];
    float* A  = sm;
    float* V  = sm + BUF;
    float* T1 = sm + 2 * BUF;
    float* T2 = sm + 3 * BUF;
    __shared__ float ew[64];
    int t = threadIdx.x;
    for (int idx = t; idx < NN; idx += TPB) {
        int i = idx >> 6, j = idx & 63;
        A[i * LD + j] = 0.5f * (bias[i * 64 + j] + bias[j * 64 + i]);
    }
    __syncthreads();
    jacobi2s(A, V, NSWEEP_S);
    if (t < 64) ew[t] = expf(0.5f * A[t * LD + t]);
    __syncthreads();
    scalecols(V, ew, T1); __syncthreads();
    smm_bt(T1, V, T2);    __syncthreads();
    load_g2s(g_Mi, A);    __syncthreads();
    smm_glob(T2, A, g_W);
}

__global__ void __launch_bounds__(TPB, 4) k_final(const float* __restrict__ data,
                                                  float* __restrict__ out) {
    extern __shared__ float sm[];
    float* sW = sm;
    float* sD = sm + BUFB;
    float* sT = sm + 2 * BUFB;
    size_t b = blockIdx.x;
    int t = threadIdx.x;
    for (int idx = t; idx < NN; idx += TPB)
        sW[(idx >> 6) * BLD + (idx & 63)] = g_W[idx];
    const float* D = data + b * NN;
    for (int idx = t; idx < NN; idx += TPB)
        sD[(idx >> 6) * BLD + (idx & 63)] = D[idx];
    __syncthreads();
    gemm_rr(sW, sD, sT);
    __syncthreads();
    int j  = t & 63;
    int ib = (t >> 6) << 4;
    ull acc[16];
#pragma unroll
    for (int i = 0; i < 16; i++) acc[i] = 0ull;
    for (int k = 0; k < 64; k += 2) {
        ull b2 = *(const ull*)(sW + j * BLD + k);
#pragma unroll
        for (int i = 0; i < 16; i++) {
            ull a2 = *(const ull*)(sT + (ib + i) * BLD + k);
            acc[i] = fma2(a2, b2, acc[i]);
        }
    }
    float* o = out + b * NN;
#pragma unroll
    for (int i = 0; i < 16; i++) {
        float2 f = upk2(acc[i]);
        o[(ib + i) * 64 + j] = f.x + f.y;
    }
}

// ---------------------------------------------------------------------------
extern "C" void kernel_launch(void* const* d_in, const int* in_sizes, int n_in,
                              void* d_out, int out_size) {
    const float* data;
    const float* bias;
    int nb;
    if (in_sizes[0] >= in_sizes[1]) {
        data = (const float*)d_in[0]; bias = (const float*)d_in[1];
        nb = in_sizes[0] / NN;
    } else {
        data = (const float*)d_in[1]; bias = (const float*)d_in[0];
        nb = in_sizes[1] / NN;
    }
    float* out = (float*)d_out;
    float inv_nb = 1.0f / (float)nb;

    size_t smemS = 4 * BUF  * sizeof(float);
    size_t smemB = 3 * BUFB * sizeof(float);
    cudaFuncSetAttribute(k_eig_M,    cudaFuncAttributeMaxDynamicSharedMemorySize, (int)smemS);
    cudaFuncSetAttribute(k_batch_oe, cudaFuncAttributeMaxDynamicSharedMemorySize, (int)smemB);
    cudaFuncSetAttribute(k_update_M, cudaFuncAttributeMaxDynamicSharedMemorySize, (int)smemS);
    cudaFuncSetAttribute(k_bias,     cudaFuncAttributeMaxDynamicSharedMemorySize, (int)smemS);
    cudaFuncSetAttribute(k_final,    cudaFuncAttributeMaxDynamicSharedMemorySize, (int)smemB);

    // arithmetic mean
    k_zero<<<16, 256>>>(0);
    {
        int nchunk = 64;
        while (nchunk > 1 && (nb % nchunk) != 0) nchunk >>= 1;
        int per_chunk = nb / nchunk;
        dim3 g(NN / 256, nchunk);
        k_mean_acc<<<g, 256>>>(data, per_chunk, inv_nb);
    }

    // 3 Karcher iterations
    for (int it = 0; it < 3; ++it) {
        k_eig_M<<<1, TPB, smemS>>>();
        k_zero<<<16, 256>>>(1);
        k_batch_oe<<<nb, TPB, smemB>>>(data, inv_nb);
        k_update_M<<<1, TPB, smemS>>>();
    }

    // final whitening + bias congruence
    k_eig_M<<<1, TPB, smemS>>>();
    k_bias<<<1, TPB, smemS>>>(bias);
    k_final<<<nb, TPB, smemB>>>(data, out);
}

// round 10
// speedup vs baseline: 5.4100x; 1.0003x over previous
#include <cuda_runtime.h>
#include <cuda_bf16.h>
#include <math.h>

// ============================================================================
// BatchNormSPDMean R9: R8 (smem column migration, 2-term reduction) with the
// divergent-shfl hang fixed: collectives run unconditionally on all lanes;
// boundary groups get zero neighbor columns -> identity rotation.
// ============================================================================

#define NN 4096
#define LD 65        // single-matrix kernels row stride
#define BLD 66       // batch row-major stride
#define CST 68       // batch col-major column stride
#define BUFB 4352
#define NSWEEP_B 7
#define NSWEEP_S 10
#define TPB 256
#define BUF 4160
#define FULLM 0xffffffffu

typedef unsigned long long ull;

// ---- persistent scratch ----
__device__ float g_M [NN];
__device__ float g_Ms[NN];
__device__ float g_Mi[NN];
__device__ float g_T [NN];
__device__ float g_W [NN];

// ---------------------------------------------------------------------------
// f32x2 packed helpers
// ---------------------------------------------------------------------------
__device__ __forceinline__ ull pk2(float lo, float hi) {
    ull r; asm("mov.b64 %0,{%1,%2};" : "=l"(r) : "f"(lo), "f"(hi)); return r;
}
__device__ __forceinline__ float2 upk2(ull v) {
    float2 r; asm("mov.b64 {%0,%1},%2;" : "=f"(r.x), "=f"(r.y) : "l"(v)); return r;
}
__device__ __forceinline__ ull fma2(ull a, ull b, ull c) {
    ull r; asm("fma.rn.f32x2 %0,%1,%2,%3;" : "=l"(r) : "l"(a), "l"(b), "l"(c)); return r;
}
__device__ __forceinline__ ull mul2(ull a, ull b) {
    ull r; asm("mul.rn.f32x2 %0,%1,%2;" : "=l"(r) : "l"(a), "l"(b)); return r;
}
__device__ __forceinline__ float hadd2(ull v) { float2 f = upk2(v); return f.x + f.y; }
__device__ __forceinline__ float d4(float4 a, float4 b) {
    return fmaf(a.x, b.x, fmaf(a.y, b.y, fmaf(a.z, b.z, a.w * b.w)));
}
// 2-term dots: dd = |v|^2 - |u|^2, apq = <u,v>, reduced over 8-lane group.
// MUST be executed by all 32 lanes of a warp (contains full-mask shfl).
__device__ __forceinline__ void dots2(const ull* u, const ull* v,
                                      float& dd, float& apq) {
    ull U = mul2(u[0], u[0]), V = mul2(v[0], v[0]), P = mul2(u[0], v[0]);
#pragma unroll
    for (int i = 1; i < 4; i++) {
        U = fma2(u[i], u[i], U);
        V = fma2(v[i], v[i], V);
        P = fma2(u[i], v[i], P);
    }
    float d = hadd2(V) - hadd2(U);
    float p = hadd2(P);
#pragma unroll
    for (int k = 1; k < 8; k <<= 1) {
        d += __shfl_xor_sync(FULLM, d, k);
        p += __shfl_xor_sync(FULLM, p, k);
    }
    dd = d; apq = p;
}
// rotation params from dd = aqq-app and apq (apq==0 -> exact identity)
__device__ __forceinline__ void rot_params2(float dd, float apq, float& c, float& s) {
    if (fabsf(apq) > 1e-34f) {
        float tau = __fdividef(dd, 2.f * apq);
        float tt  = copysignf(1.f, tau) / (fabsf(tau) + sqrtf(1.f + tau * tau));
        c = rsqrtf(1.f + tt * tt);
        s = tt * c;
    } else { c = 1.f; s = 0.f; }
}

// tournament pairing (two-sided jacobi only)
__device__ __forceinline__ void get_pair(int r, int k, int& p, int& q) {
    int a = (k == 0) ? 0 : 1 + (k - 1 + r) % 63;
    int b = 1 + (62 - k + r) % 63;
    p = a < b ? a : b;
    q = a < b ? b : a;
}

// ---------------------------------------------------------------------------
// single-matrix helpers (LD=65 world)
// ---------------------------------------------------------------------------
__device__ __forceinline__ void load_g2s(const float* __restrict__ g, float* S) {
    for (int idx = threadIdx.x; idx < NN; idx += TPB)
        S[(idx >> 6) * LD + (idx & 63)] = g[idx];
}
__device__ __forceinline__ void store_s2g(const float* S, float* __restrict__ g) {
    for (int idx = threadIdx.x; idx < NN; idx += TPB)
        g[idx] = S[(idx >> 6) * LD + (idx & 63)];
}
__device__ __forceinline__ void sym_s(float* A) {
    for (int idx = threadIdx.x; idx < NN; idx += TPB) {
        int i = idx >> 6, j = idx & 63;
        if (i < j) {
            float v = 0.5f * (A[i * LD + j] + A[j * LD + i]);
            A[i * LD + j] = v;
            A[j * LD + i] = v;
        }
    }
}
__device__ __forceinline__ void smm(const float* A, const float* B, float* C) {
    int j  = threadIdx.x & 63;
    int ib = (threadIdx.x >> 6) << 4;
    float acc[16];
#pragma unroll
    for (int i = 0; i < 16; i++) acc[i] = 0.f;
    for (int k = 0; k < 64; k++) {
        float bv = B[k * LD + j];
#pragma unroll
        for (int i = 0; i < 16; i++) acc[i] = fmaf(A[(ib + i) * LD + k], bv, acc[i]);
    }
#pragma unroll
    for (int i = 0; i < 16; i++) C[(ib + i) * LD + j] = acc[i];
}
__device__ __forceinline__ void smm_bt(const float* A, const float* B, float* C) {
    int j  = threadIdx.x & 63;
    int ib = (threadIdx.x >> 6) << 4;
    float acc[16];
#pragma unroll
    for (int i = 0; i < 16; i++) acc[i] = 0.f;
    for (int k = 0; k < 64; k++) {
        float bv = B[j * LD + k];
#pragma unroll
        for (int i = 0; i < 16; i++) acc[i] = fmaf(A[(ib + i) * LD + k], bv, acc[i]);
    }
#pragma unroll
    for (int i = 0; i < 16; i++) C[(ib + i) * LD + j] = acc[i];
}
__device__ __forceinline__ void smm_glob(const float* A, const float* B, float* __restrict__ gout) {
    int j  = threadIdx.x & 63;
    int ib = (threadIdx.x >> 6) << 4;
    float acc[16];
#pragma unroll
    for (int i = 0; i < 16; i++) acc[i] = 0.f;
    for (int k = 0; k < 64; k++) {
        float bv = B[k * LD + j];
#pragma unroll
        for (int i = 0; i < 16; i++) acc[i] = fmaf(A[(ib + i) * LD + k], bv, acc[i]);
    }
#pragma unroll
    for (int i = 0; i < 16; i++) gout[(ib + i) * 64 + j] = acc[i];
}
__device__ __forceinline__ void scalecols(const float* V, const float* w, float* O) {
    for (int idx = threadIdx.x; idx < NN; idx += TPB) {
        int i = idx >> 6, k = idx & 63;
        O[i * LD + k] = V[i * LD + k] * w[k];
    }
}

// two-sided Jacobi (single-matrix kernels only)
__device__ void jacobi2s(float* A, float* V, int nsweeps) {
    int t = threadIdx.x;
    __shared__ float cs[32], sn[32];
    __shared__ uchar2 tab2[63 * 32];
    for (int idx = t; idx < 63 * 32; idx += TPB) {
        int r = idx >> 5, k = idx & 31, p, q;
        get_pair(r, k, p, q);
        tab2[idx] = make_uchar2((unsigned char)p, (unsigned char)q);
    }
    for (int idx = t; idx < NN; idx += TPB) {
        int i = idx >> 6, j = idx & 63;
        V[i * LD + j] = (i == j) ? 1.f : 0.f;
    }
    __syncthreads();
    for (int sw = 0; sw < nsweeps; ++sw) {
        for (int r = 0; r < 63; ++r) {
            const uchar2* trow = tab2 + (r << 5);
            if (t < 32) {
                uchar2 pq = trow[t];
                int pl = pq.x * LD, ql = pq.y * LD;
                float app = A[pl + pq.x], aqq = A[ql + pq.y], apq = A[pl + pq.y];
                float c, s;
                if (fabsf(apq) < 1e-30f) { c = 1.f; s = 0.f; }
                else {
                    float tau = (aqq - app) / (2.f * apq);
                    float tt  = copysignf(1.f, tau) / (fabsf(tau) + sqrtf(1.f + tau * tau));
                    c = rsqrtf(1.f + tt * tt);
                    s = tt * c;
                }
                cs[t] = c; sn[t] = s;
            }
            __syncthreads();
#pragma unroll
            for (int m = 0; m < 2048 / TPB; m++) {
                int w = t + m * TPB;
                int k = w >> 6, j = w & 63;
                uchar2 pq = trow[k];
                int pl = pq.x * LD + j, ql = pq.y * LD + j;
                float c = cs[k], s = sn[k];
                float ap = A[pl], aq = A[ql];
                A[pl] = c * ap - s * aq;
                A[ql] = fmaf(s, ap, c * aq);
            }
            __syncthreads();
#pragma unroll
            for (int m = 0; m < 2048 / TPB; m++) {
                int w = t + m * TPB;
                int k = w >> 6, i = w & 63;
                uchar2 pq = trow[k];
                int il = i * LD;
                int pl = il + pq.x, ql = il + pq.y;
                float c = cs[k], s = sn[k];
                float ap = A[pl], aq = A[ql];
                A[pl] = c * ap - s * aq;
                A[ql] = fmaf(s, ap, c * aq);
                float vp = V[pl], vq = V[ql];
                V[pl] = c * vp - s * vq;
                V[ql] = fmaf(s, vp, c * vq);
            }
            __syncthreads();
        }
    }
}

// ---------------------------------------------------------------------------
// batch GEMMs (f32x2)
// ---------------------------------------------------------------------------
__device__ __forceinline__ void gemm_rr(const float* A, const float* B, float* C) {
    int j  = threadIdx.x & 63;
    int ib = (threadIdx.x >> 6) << 4;
    ull acc[16];
#pragma unroll
    for (int i = 0; i < 16; i++) acc[i] = 0ull;
    for (int k = 0; k < 64; k += 2) {
        ull b2 = pk2(B[k * BLD + j], B[(k + 1) * BLD + j]);
#pragma unroll
        for (int i = 0; i < 16; i++) {
            ull a2 = *(const ull*)(A + (ib + i) * BLD + k);
            acc[i] = fma2(a2, b2, acc[i]);
        }
    }
#pragma unroll
    for (int i = 0; i < 16; i++) {
        float2 f = upk2(acc[i]);
        C[(ib + i) * BLD + j] = f.x + f.y;
    }
}
__device__ __forceinline__ void gemm_r2c(const float* A, const float* B, float* C) {
    int j  = threadIdx.x & 63;
    int ib = (threadIdx.x >> 6) << 4;
    ull acc[16];
#pragma unroll
    for (int i = 0; i < 16; i++) acc[i] = 0ull;
    for (int k = 0; k < 64; k += 2) {
        ull b2 = pk2(B[k * BLD + j], B[(k + 1) * BLD + j]);
#pragma unroll
        for (int i = 0; i < 16; i++) {
            ull a2 = *(const ull*)(A + (ib + i) * BLD + k);
            acc[i] = fma2(a2, b2, acc[i]);
        }
    }
    float r[16];
#pragma unroll
    for (int i = 0; i < 16; i++) { float2 f = upk2(acc[i]); r[i] = f.x + f.y; }
    float4* dst = (float4*)(C + j * CST + ib);
    dst[0] = make_float4(r[0],  r[1],  r[2],  r[3]);
    dst[1] = make_float4(r[4],  r[5],  r[6],  r[7]);
    dst[2] = make_float4(r[8],  r[9],  r[10], r[11]);
    dst[3] = make_float4(r[12], r[13], r[14], r[15]);
}

// epilogue: W[:,k] = B[:,k] * 0.5*log(n2)/n2
__device__ __forceinline__ void colscale_log(const float* B, float* W) {
    int t = threadIdx.x;
    int col = t >> 2, qc = t & 3;
    const float4* bc = (const float4*)(B + col * CST);
    float4 v0 = bc[qc * 4 + 0], v1 = bc[qc * 4 + 1];
    float4 v2 = bc[qc * 4 + 2], v3 = bc[qc * 4 + 3];
    float pn = d4(v0, v0) + d4(v1, v1) + d4(v2, v2) + d4(v3, v3);
    pn += __shfl_xor_sync(FULLM, pn, 1);
    pn += __shfl_xor_sync(FULLM, pn, 2);
    float n2 = fmaxf(pn, 1e-24f);
    float g = 0.5f * logf(n2) / n2;
    float4* wc = (float4*)(W + col * CST);
    v0.x *= g; v0.y *= g; v0.z *= g; v0.w *= g;
    v1.x *= g; v1.y *= g; v1.z *= g; v1.w *= g;
    v2.x *= g; v2.y *= g; v2.z *= g; v2.w *= g;
    v3.x *= g; v3.y *= g; v3.z *= g; v3.w *= g;
    wc[qc * 4 + 0] = v0; wc[qc * 4 + 1] = v1;
    wc[qc * 4 + 2] = v2; wc[qc * 4 + 3] = v3;
}
__device__ __forceinline__ void logm_atomic(const float* W, const float* B, float scale) {
    int j  = threadIdx.x & 63;
    int ib = (threadIdx.x >> 6) << 4;
    float acc[16];
#pragma unroll
    for (int i = 0; i < 16; i++) acc[i] = 0.f;
    for (int k = 0; k < 64; k++) {
        float bj = B[k * CST + j];
        const float4* wr = (const float4*)(W + k * CST + ib);
        float4 w0 = wr[0], w1 = wr[1], w2 = wr[2], w3 = wr[3];
        acc[0]  = fmaf(w0.x, bj, acc[0]);  acc[1]  = fmaf(w0.y, bj, acc[1]);
        acc[2]  = fmaf(w0.z, bj, acc[2]);  acc[3]  = fmaf(w0.w, bj, acc[3]);
        acc[4]  = fmaf(w1.x, bj, acc[4]);  acc[5]  = fmaf(w1.y, bj, acc[5]);
        acc[6]  = fmaf(w1.z, bj, acc[6]);  acc[7]  = fmaf(w1.w, bj, acc[7]);
        acc[8]  = fmaf(w2.x, bj, acc[8]);  acc[9]  = fmaf(w2.y, bj, acc[9]);
        acc[10] = fmaf(w2.z, bj, acc[10]); acc[11] = fmaf(w2.w, bj, acc[11]);
        acc[12] = fmaf(w3.x, bj, acc[12]); acc[13] = fmaf(w3.y, bj, acc[13]);
        acc[14] = fmaf(w3.z, bj, acc[14]); acc[15] = fmaf(w3.w, bj, acc[15]);
    }
#pragma unroll
    for (int i = 0; i < 16; i++) atomicAdd(&g_T[(ib + i) * 64 + j], acc[i] * scale);
}

// ---------------------------------------------------------------------------
// kernels
// ---------------------------------------------------------------------------
__global__ void k_zero(int which) {
    int i = blockIdx.x * blockDim.x + threadIdx.x;
    if (i < NN) { if (which == 0) g_M[i] = 0.f; else g_T[i] = 0.f; }
}

__global__ void k_mean_acc(const float* __restrict__ data, int per_chunk, float inv_nb) {
    int e = blockIdx.x * blockDim.x + threadIdx.x;
    const float* p = data + (size_t)(blockIdx.y) * per_chunk * NN + e;
    float sum = 0.f;
#pragma unroll 8
    for (int i = 0; i < per_chunk; i++) sum += p[(size_t)i * NN];
    atomicAdd(&g_M[e], sum * inv_nb);
}

__global__ void __launch_bounds__(TPB) k_eig_M() {
    extern __shared__ float sm[];
    float* A  = sm;
    float* V  = sm + BUF;
    float* T1 = sm + 2 * BUF;
    float* T2 = sm + 3 * BUF;
    __shared__ float w1[64], w2[64];
    load_g2s(g_M, A);
    __syncthreads();
    sym_s(A);
    __syncthreads();
    jacobi2s(A, V, NSWEEP_S);
    int t = threadIdx.x;
    if (t < 64) {
        float w = fmaxf(A[t * LD + t], 1e-12f);
        w1[t] = sqrtf(w);
        w2[t] = rsqrtf(w);
    }
    __syncthreads();
    scalecols(V, w1, T1); __syncthreads();
    smm_bt(T1, V, T2);    __syncthreads();
    store_s2g(T2, g_Ms);
    __syncthreads();
    scalecols(V, w2, T1); __syncthreads();
    smm_bt(T1, V, T2);    __syncthreads();
    store_s2g(T2, g_Mi);
}

// -------- register odd-even one-sided Jacobi, SMEM migration ----------------
__global__ void __launch_bounds__(TPB, 4) k_batch_oe(const float* __restrict__ data,
                                                     float inv_nb) {
    extern __shared__ float sm[];
    float* s0 = sm;             // Mi (row) -> xL overlay -> W (col)
    float* s1 = sm + BUFB;      // D (row)  -> C (col) -> B (col)
    float* s2 = sm + 2 * BUFB;  // temp (row) -> xR overlay
    __shared__ float2 prm[2][32];
    int t = threadIdx.x;
    size_t b = blockIdx.x;

    for (int idx = t; idx < NN; idx += TPB)
        s0[(idx >> 6) * BLD + (idx & 63)] = g_Mi[idx];
    const float* D = data + b * NN;
    for (int idx = t; idx < NN; idx += TPB)
        s1[(idx >> 6) * BLD + (idx & 63)] = D[idx];
    __syncthreads();
    gemm_rr(s0, s1, s2);    // s2 = Mi * D (row)
    __syncthreads();
    gemm_r2c(s2, s0, s1);   // s1 = C (col-major CST)
    __syncthreads();
    // symmetrize C in place
    for (int idx = t; idx < NN; idx += TPB) {
        int i = idx >> 6, j = idx & 63;
        if (i < j) {
            float v = 0.5f * (s1[i * CST + j] + s1[j * CST + i]);
            s1[i * CST + j] = v;
            s1[j * CST + i] = v;
        }
    }
    __syncthreads();

    // ---- load 2 columns per 8-lane group into registers ----
    int lane = t & 31, warp = t >> 5, grp = lane >> 3, sub = lane & 7;
    int G = warp * 4 + grp;           // group id; owns slots (2G, 2G+1)
    ull cL[4], cR[4];
    {
        const ulonglong2* pc = (const ulonglong2*)(s1 + (2 * G) * CST);
        ulonglong2 q0 = pc[2 * sub], q1 = pc[2 * sub + 1];
        cL[0] = q0.x; cL[1] = q0.y; cL[2] = q1.x; cL[3] = q1.y;
        const ulonglong2* pd = (const ulonglong2*)(s1 + (2 * G + 1) * CST);
        q0 = pd[2 * sub]; q1 = pd[2 * sub + 1];
        cR[0] = q0.x; cR[1] = q0.y; cR[2] = q1.x; cR[3] = q1.y;
    }
    __syncthreads();   // s0/s2 freed for xbuf overlays

    // xbuf layout: [pb][col G] of 64 floats (lane sub: float4 slots sub, sub+8)
    const bool hasR = (G < 31);
    const bool hasL = (G > 0);
    int pb = 0;

    for (int sw = 0; sw < NSWEEP_B; ++sw) {
        for (int rr = 0; rr < 32; ++rr) {
            // ---- EVEN round: pair (2G, 2G+1), registers only, swap ----
            {
                float dd, apq;
                dots2(cL, cR, dd, apq);          // all lanes (collective)
                float c, s;
                rot_params2(dd, apq, c, s);
                ull c2 = pk2(c, c), s2p = pk2(s, s), ns2 = pk2(-s, -s);
#pragma unroll
                for (int i = 0; i < 4; i++) {
                    ull u = cL[i], v = cR[i];
                    cL[i] = fma2(s2p, u, mul2(c2, v));   // v' = s u + c v
                    cR[i] = fma2(ns2, v, mul2(c2, u));   // u' = c u - s v
                }
            }
            // ---- ODD round: pair (2G+1, 2G+2) via smem exchange ----
            {
                float4* Lb = (float4*)(s0 + ((pb << 5) + G) * 64);
                float4* Rb = (float4*)(s2 + ((pb << 5) + G) * 64);
                Lb[sub]     = *(float4*)&cL[0];
                Lb[sub + 8] = *(float4*)&cL[2];
                Rb[sub]     = *(float4*)&cR[0];
                Rb[sub + 8] = *(float4*)&cR[2];
                __syncthreads();
                // zero-init neighbors: boundary groups -> apq==0 -> identity
                ull vR[4] = {0ull, 0ull, 0ull, 0ull};
                ull uL[4] = {0ull, 0ull, 0ull, 0ull};
                if (hasR) {
                    const float4* p = (const float4*)(s0 + ((pb << 5) + G + 1) * 64);
                    *(float4*)&vR[0] = p[sub];
                    *(float4*)&vR[2] = p[sub + 8];
                }
                if (hasL) {
                    const float4* p = (const float4*)(s2 + ((pb << 5) + G - 1) * 64);
                    *(float4*)&uL[0] = p[sub];
                    *(float4*)&uL[2] = p[sub + 8];
                }
                // collective: all lanes participate (vR=0 for G=31 -> identity)
                float dd, apq;
                dots2(cR, vR, dd, apq);
                float c, s;
                rot_params2(dd, apq, c, s);
                if (sub == 0) prm[pb][G] = make_float2(c, s);
                __syncthreads();
                if (hasR) {
                    ull c2 = pk2(c, c), s2p = pk2(s, s);
#pragma unroll
                    for (int i = 0; i < 4; i++)
                        cR[i] = fma2(s2p, cR[i], mul2(c2, vR[i]));   // v' = s u + c v
                }
                if (hasL) {
                    float2 ps = prm[pb][G - 1];
                    ull cl2 = pk2(ps.x, ps.x), nsl2 = pk2(-ps.y, -ps.y);
#pragma unroll
                    for (int i = 0; i < 4; i++)
                        cL[i] = fma2(nsl2, cL[i], mul2(cl2, uL[i])); // u' = c u - s v
                }
                pb ^= 1;
            }
        }
    }

    // ---- store columns back to s1 (col-major CST), permutation irrelevant ----
    {
        ulonglong2* pc = (ulonglong2*)(s1 + (2 * G) * CST);
        pc[2 * sub]     = make_ulonglong2(cL[0], cL[1]);
        pc[2 * sub + 1] = make_ulonglong2(cL[2], cL[3]);
        ulonglong2* pd = (ulonglong2*)(s1 + (2 * G + 1) * CST);
        pd[2 * sub]     = make_ulonglong2(cR[0], cR[1]);
        pd[2 * sub + 1] = make_ulonglong2(cR[2], cR[3]);
    }
    __syncthreads();
    colscale_log(s1, s0);     // s0 = W = B * diag(log l / l^2)
    __syncthreads();
    logm_atomic(s0, s1, inv_nb);
}

__global__ void __launch_bounds__(TPB) k_update_M() {
    extern __shared__ float sm[];
    float* A  = sm;
    float* V  = sm + BUF;
    float* T1 = sm + 2 * BUF;
    float* T2 = sm + 3 * BUF;
    __shared__ float ew[64];
    load_g2s(g_T, A);
    __syncthreads();
    sym_s(A);
    __syncthreads();
    jacobi2s(A, V, NSWEEP_S);
    int t = threadIdx.x;
    if (t < 64) ew[t] = expf(A[t * LD + t]);
    __syncthreads();
    scalecols(V, ew, T1); __syncthreads();
    smm_bt(T1, V, T2);    __syncthreads();
    load_g2s(g_Ms, A);    __syncthreads();
    smm(A, T2, T1);       __syncthreads();
    smm_glob(T1, A, g_M);
}

__global__ void __launch_bounds__(TPB) k_bias(const float* __restrict__ bias) {
    extern __shared__ float sm[];
    float* A  = sm;
    float* V  = sm + BUF;
    float* T1 = sm + 2 * BUF;
    float* T2 = sm + 3 * BUF;
    __shared__ float ew[64];
    int t = threadIdx.x;
    for (int idx = t; idx < NN; idx += TPB) {
        int i = idx >> 6, j = idx & 63;
        A[i * LD + j] = 0.5f * (bias[i * 64 + j] + bias[j * 64 + i]);
    }
    __syncthreads();
    jacobi2s(A, V, NSWEEP_S);
    if (t < 64) ew[t] = expf(0.5f * A[t * LD + t]);
    __syncthreads();
    scalecols(V, ew, T1); __syncthreads();
    smm_bt(T1, V, T2);    __syncthreads();
    load_g2s(g_Mi, A);    __syncthreads();
    smm_glob(T2, A, g_W);
}

__global__ void __launch_bounds__(TPB, 4) k_final(const float* __restrict__ data,
                                                  float* __restrict__ out) {
    extern __shared__ float sm[];
    float* sW = sm;
    float* sD = sm + BUFB;
    float* sT = sm + 2 * BUFB;
    size_t b = blockIdx.x;
    int t = threadIdx.x;
    for (int idx = t; idx < NN; idx += TPB)
        sW[(idx >> 6) * BLD + (idx & 63)] = g_W[idx];
    const float* D = data + b * NN;
    for (int idx = t; idx < NN; idx += TPB)
        sD[(idx >> 6) * BLD + (idx & 63)] = D[idx];
    __syncthreads();
    gemm_rr(sW, sD, sT);
    __syncthreads();
    int j  = t & 63;
    int ib = (t >> 6) << 4;
    ull acc[16];
#pragma unroll
    for (int i = 0; i < 16; i++) acc[i] = 0ull;
    for (int k = 0; k < 64; k += 2) {
        ull b2 = *(const ull*)(sW + j * BLD + k);
#pragma unroll
        for (int i = 0; i < 16; i++) {
            ull a2 = *(const ull*)(sT + (ib + i) * BLD + k);
            acc[i] = fma2(a2, b2, acc[i]);
        }
    }
    float* o = out + b * NN;
#pragma unroll
    for (int i = 0; i < 16; i++) {
        float2 f = upk2(acc[i]);
        o[(ib + i) * 64 + j] = f.x + f.y;
    }
}

// ---------------------------------------------------------------------------
extern "C" void kernel_launch(void* const* d_in, const int* in_sizes, int n_in,
                              void* d_out, int out_size) {
    const float* data;
    const float* bias;
    int nb;
    if (in_sizes[0] >= in_sizes[1]) {
        data = (const float*)d_in[0]; bias = (const float*)d_in[1];
        nb = in_sizes[0] / NN;
    } else {
        data = (const float*)d_in[1]; bias = (const float*)d_in[0];
        nb = in_sizes[1] / NN;
    }
    float* out = (float*)d_out;
    float inv_nb = 1.0f / (float)nb;

    size_t smemS = 4 * BUF  * sizeof(float);
    size_t smemB = 3 * BUFB * sizeof(float);
    cudaFuncSetAttribute(k_eig_M,    cudaFuncAttributeMaxDynamicSharedMemorySize, (int)smemS);
    cudaFuncSetAttribute(k_batch_oe, cudaFuncAttributeMaxDynamicSharedMemorySize, (int)smemB);
    cudaFuncSetAttribute(k_update_M, cudaFuncAttributeMaxDynamicSharedMemorySize, (int)smemS);
    cudaFuncSetAttribute(k_bias,     cudaFuncAttributeMaxDynamicSharedMemorySize, (int)smemS);
    cudaFuncSetAttribute(k_final,    cudaFuncAttributeMaxDynamicSharedMemorySize, (int)smemB);

    // arithmetic mean
    k_zero<<<16, 256>>>(0);
    {
        int nchunk = 64;
        while (nchunk > 1 && (nb % nchunk) != 0) nchunk >>= 1;
        int per_chunk = nb / nchunk;
        dim3 g(NN / 256, nchunk);
        k_mean_acc<<<g, 256>>>(data, per_chunk, inv_nb);
    }

    // 3 Karcher iterations
    for (int it = 0; it < 3; ++it) {
        k_eig_M<<<1, TPB, smemS>>>();
        k_zero<<<16, 256>>>(1);
        k_batch_oe<<<nb, TPB, smemB>>>(data, inv_nb);
        k_update_M<<<1, TPB, smemS>>>();
    }

    // final whitening + bias congruence
    k_eig_M<<<1, TPB, smemS>>>();
    k_bias<<<1, TPB, smemS>>>(bias);
    k_final<<<nb, TPB, smemB>>>(data, out);
}

// round 13
// speedup vs baseline: 5.5610x; 1.0279x over previous
#include <cuda_runtime.h>
#include <cuda_bf16.h>
#include <math.h>

// ============================================================================
// BatchNormSPDMean R13: R9 baseline (register odd-even Jacobi, smem migration)
// with per-iteration sweep schedule 6/7/7 (iter-1 residual is Karcher-damped).
// Warm-start removed (falsified: convergence is ~3.3x/sweep, not quadratic).
// ============================================================================

#define NN 4096
#define LD 65        // single-matrix kernels row stride
#define BLD 66       // batch row-major stride
#define CST 68       // batch col-major column stride
#define BUFB 4352
#define NSWEEP_S 10
#define TPB 256
#define BUF 4160
#define FULLM 0xffffffffu

typedef unsigned long long ull;

__device__ float g_M [NN];
__device__ float g_Ms[NN];
__device__ float g_Mi[NN];
__device__ float g_T [NN];
__device__ float g_W [NN];

// ---- f32x2 helpers ----
__device__ __forceinline__ ull pk2(float lo, float hi) {
    ull r; asm("mov.b64 %0,{%1,%2};" : "=l"(r) : "f"(lo), "f"(hi)); return r;
}
__device__ __forceinline__ float2 upk2(ull v) {
    float2 r; asm("mov.b64 {%0,%1},%2;" : "=f"(r.x), "=f"(r.y) : "l"(v)); return r;
}
__device__ __forceinline__ ull fma2(ull a, ull b, ull c) {
    ull r; asm("fma.rn.f32x2 %0,%1,%2,%3;" : "=l"(r) : "l"(a), "l"(b), "l"(c)); return r;
}
__device__ __forceinline__ ull mul2(ull a, ull b) {
    ull r; asm("mul.rn.f32x2 %0,%1,%2;" : "=l"(r) : "l"(a), "l"(b)); return r;
}
__device__ __forceinline__ float hadd2(ull v) { float2 f = upk2(v); return f.x + f.y; }
__device__ __forceinline__ float d4(float4 a, float4 b) {
    return fmaf(a.x, b.x, fmaf(a.y, b.y, fmaf(a.z, b.z, a.w * b.w)));
}
// collective: all 32 lanes must execute (full-mask shfl)
__device__ __forceinline__ void dots2(const ull* u, const ull* v, float& dd, float& apq) {
    ull U = mul2(u[0], u[0]), V = mul2(v[0], v[0]), P = mul2(u[0], v[0]);
#pragma unroll
    for (int i = 1; i < 4; i++) {
        U = fma2(u[i], u[i], U); V = fma2(v[i], v[i], V); P = fma2(u[i], v[i], P);
    }
    float d = hadd2(V) - hadd2(U);
    float p = hadd2(P);
#pragma unroll
    for (int k = 1; k < 8; k <<= 1) {
        d += __shfl_xor_sync(FULLM, d, k);
        p += __shfl_xor_sync(FULLM, p, k);
    }
    dd = d; apq = p;
}
__device__ __forceinline__ void rot_params2(float dd, float apq, float& c, float& s) {
    if (fabsf(apq) > 1e-34f) {
        float tau = __fdividef(dd, 2.f * apq);
        float tt  = copysignf(1.f, tau) / (fabsf(tau) + sqrtf(1.f + tau * tau));
        c = rsqrtf(1.f + tt * tt);
        s = tt * c;
    } else { c = 1.f; s = 0.f; }
}
__device__ __forceinline__ void get_pair(int r, int k, int& p, int& q) {
    int a = (k == 0) ? 0 : 1 + (k - 1 + r) % 63;
    int b = 1 + (62 - k + r) % 63;
    p = a < b ? a : b;
    q = a < b ? b : a;
}

// ---- single-matrix helpers ----
__device__ __forceinline__ void load_g2s(const float* __restrict__ g, float* S) {
    for (int idx = threadIdx.x; idx < NN; idx += TPB)
        S[(idx >> 6) * LD + (idx & 63)] = g[idx];
}
__device__ __forceinline__ void store_s2g(const float* S, float* __restrict__ g) {
    for (int idx = threadIdx.x; idx < NN; idx += TPB)
        g[idx] = S[(idx >> 6) * LD + (idx & 63)];
}
__device__ __forceinline__ void sym_s(float* A) {
    for (int idx = threadIdx.x; idx < NN; idx += TPB) {
        int i = idx >> 6, j = idx & 63;
        if (i < j) {
            float v = 0.5f * (A[i * LD + j] + A[j * LD + i]);
            A[i * LD + j] = v; A[j * LD + i] = v;
        }
    }
}
__device__ __forceinline__ void smm(const float* A, const float* B, float* C) {
    int j = threadIdx.x & 63, ib = (threadIdx.x >> 6) << 4;
    float acc[16];
#pragma unroll
    for (int i = 0; i < 16; i++) acc[i] = 0.f;
    for (int k = 0; k < 64; k++) {
        float bv = B[k * LD + j];
#pragma unroll
        for (int i = 0; i < 16; i++) acc[i] = fmaf(A[(ib + i) * LD + k], bv, acc[i]);
    }
#pragma unroll
    for (int i = 0; i < 16; i++) C[(ib + i) * LD + j] = acc[i];
}
__device__ __forceinline__ void smm_bt(const float* A, const float* B, float* C) {
    int j = threadIdx.x & 63, ib = (threadIdx.x >> 6) << 4;
    float acc[16];
#pragma unroll
    for (int i = 0; i < 16; i++) acc[i] = 0.f;
    for (int k = 0; k < 64; k++) {
        float bv = B[j * LD + k];
#pragma unroll
        for (int i = 0; i < 16; i++) acc[i] = fmaf(A[(ib + i) * LD + k], bv, acc[i]);
    }
#pragma unroll
    for (int i = 0; i < 16; i++) C[(ib + i) * LD + j] = acc[i];
}
__device__ __forceinline__ void smm_glob(const float* A, const float* B, float* __restrict__ g) {
    int j = threadIdx.x & 63, ib = (threadIdx.x >> 6) << 4;
    float acc[16];
#pragma unroll
    for (int i = 0; i < 16; i++) acc[i] = 0.f;
    for (int k = 0; k < 64; k++) {
        float bv = B[k * LD + j];
#pragma unroll
        for (int i = 0; i < 16; i++) acc[i] = fmaf(A[(ib + i) * LD + k], bv, acc[i]);
    }
#pragma unroll
    for (int i = 0; i < 16; i++) g[(ib + i) * 64 + j] = acc[i];
}
__device__ __forceinline__ void scalecols(const float* V, const float* w, float* O) {
    for (int idx = threadIdx.x; idx < NN; idx += TPB) {
        int i = idx >> 6, k = idx & 63;
        O[i * LD + k] = V[i * LD + k] * w[k];
    }
}

__device__ void jacobi2s(float* A, float* V, int nsweeps) {
    int t = threadIdx.x;
    __shared__ float cs[32], sn[32];
    __shared__ uchar2 tab2[63 * 32];
    for (int idx = t; idx < 63 * 32; idx += TPB) {
        int r = idx >> 5, k = idx & 31, p, q;
        get_pair(r, k, p, q);
        tab2[idx] = make_uchar2((unsigned char)p, (unsigned char)q);
    }
    for (int idx = t; idx < NN; idx += TPB) {
        int i = idx >> 6, j = idx & 63;
        V[i * LD + j] = (i == j) ? 1.f : 0.f;
    }
    __syncthreads();
    for (int sw = 0; sw < nsweeps; ++sw)
        for (int r = 0; r < 63; ++r) {
            const uchar2* trow = tab2 + (r << 5);
            if (t < 32) {
                uchar2 pq = trow[t];
                int pl = pq.x * LD, ql = pq.y * LD;
                float app = A[pl + pq.x], aqq = A[ql + pq.y], apq = A[pl + pq.y];
                float c, s;
                if (fabsf(apq) < 1e-30f) { c = 1.f; s = 0.f; }
                else {
                    float tau = (aqq - app) / (2.f * apq);
                    float tt  = copysignf(1.f, tau) / (fabsf(tau) + sqrtf(1.f + tau * tau));
                    c = rsqrtf(1.f + tt * tt); s = tt * c;
                }
                cs[t] = c; sn[t] = s;
            }
            __syncthreads();
#pragma unroll
            for (int m = 0; m < 2048 / TPB; m++) {
                int w = t + m * TPB, k = w >> 6, j = w & 63;
                uchar2 pq = trow[k];
                int pl = pq.x * LD + j, ql = pq.y * LD + j;
                float c = cs[k], s = sn[k];
                float ap = A[pl], aq = A[ql];
                A[pl] = c * ap - s * aq;
                A[ql] = fmaf(s, ap, c * aq);
            }
            __syncthreads();
#pragma unroll
            for (int m = 0; m < 2048 / TPB; m++) {
                int w = t + m * TPB, k = w >> 6, i = w & 63;
                uchar2 pq = trow[k];
                int il = i * LD, pl = il + pq.x, ql = il + pq.y;
                float c = cs[k], s = sn[k];
                float ap = A[pl], aq = A[ql];
                A[pl] = c * ap - s * aq;
                A[ql] = fmaf(s, ap, c * aq);
                float vp = V[pl], vq = V[ql];
                V[pl] = c * vp - s * vq;
                V[ql] = fmaf(s, vp, c * vq);
            }
            __syncthreads();
        }
}

// ---- batch GEMMs ----
__device__ __forceinline__ void gemm_rr(const float* A, const float* B, float* C) {
    int j = threadIdx.x & 63, ib = (threadIdx.x >> 6) << 4;
    ull acc[16];
#pragma unroll
    for (int i = 0; i < 16; i++) acc[i] = 0ull;
    for (int k = 0; k < 64; k += 2) {
        ull b2 = pk2(B[k * BLD + j], B[(k + 1) * BLD + j]);
#pragma unroll
        for (int i = 0; i < 16; i++)
            acc[i] = fma2(*(const ull*)(A + (ib + i) * BLD + k), b2, acc[i]);
    }
#pragma unroll
    for (int i = 0; i < 16; i++) { float2 f = upk2(acc[i]); C[(ib + i) * BLD + j] = f.x + f.y; }
}
__device__ __forceinline__ void gemm_r2c(const float* A, const float* B, float* C) {
    int j = threadIdx.x & 63, ib = (threadIdx.x >> 6) << 4;
    ull acc[16];
#pragma unroll
    for (int i = 0; i < 16; i++) acc[i] = 0ull;
    for (int k = 0; k < 64; k += 2) {
        ull b2 = pk2(B[k * BLD + j], B[(k + 1) * BLD + j]);
#pragma unroll
        for (int i = 0; i < 16; i++)
            acc[i] = fma2(*(const ull*)(A + (ib + i) * BLD + k), b2, acc[i]);
    }
    float r[16];
#pragma unroll
    for (int i = 0; i < 16; i++) { float2 f = upk2(acc[i]); r[i] = f.x + f.y; }
    float4* dst = (float4*)(C + j * CST + ib);
    dst[0] = make_float4(r[0], r[1], r[2], r[3]);
    dst[1] = make_float4(r[4], r[5], r[6], r[7]);
    dst[2] = make_float4(r[8], r[9], r[10], r[11]);
    dst[3] = make_float4(r[12], r[13], r[14], r[15]);
}

__device__ __forceinline__ void colscale_log(const float* B, float* W) {
    int t = threadIdx.x, col = t >> 2, qc = t & 3;
    const float4* bc = (const float4*)(B + col * CST);
    float4 v0 = bc[qc * 4 + 0], v1 = bc[qc * 4 + 1];
    float4 v2 = bc[qc * 4 + 2], v3 = bc[qc * 4 + 3];
    float pn = d4(v0, v0) + d4(v1, v1) + d4(v2, v2) + d4(v3, v3);
    pn += __shfl_xor_sync(FULLM, pn, 1);
    pn += __shfl_xor_sync(FULLM, pn, 2);
    float n2 = fmaxf(pn, 1e-24f);
    float g = 0.5f * logf(n2) / n2;
    float4* wc = (float4*)(W + col * CST);
    v0.x *= g; v0.y *= g; v0.z *= g; v0.w *= g;
    v1.x *= g; v1.y *= g; v1.z *= g; v1.w *= g;
    v2.x *= g; v2.y *= g; v2.z *= g; v2.w *= g;
    v3.x *= g; v3.y *= g; v3.z *= g; v3.w *= g;
    wc[qc * 4 + 0] = v0; wc[qc * 4 + 1] = v1;
    wc[qc * 4 + 2] = v2; wc[qc * 4 + 3] = v3;
}
__device__ __forceinline__ void logm_atomic(const float* W, const float* B, float scale) {
    int j = threadIdx.x & 63, ib = (threadIdx.x >> 6) << 4;
    float acc[16];
#pragma unroll
    for (int i = 0; i < 16; i++) acc[i] = 0.f;
    for (int k = 0; k < 64; k++) {
        float bj = B[k * CST + j];
        const float4* wr = (const float4*)(W + k * CST + ib);
        float4 w0 = wr[0], w1 = wr[1], w2 = wr[2], w3 = wr[3];
        acc[0]  = fmaf(w0.x, bj, acc[0]);  acc[1]  = fmaf(w0.y, bj, acc[1]);
        acc[2]  = fmaf(w0.z, bj, acc[2]);  acc[3]  = fmaf(w0.w, bj, acc[3]);
        acc[4]  = fmaf(w1.x, bj, acc[4]);  acc[5]  = fmaf(w1.y, bj, acc[5]);
        acc[6]  = fmaf(w1.z, bj, acc[6]);  acc[7]  = fmaf(w1.w, bj, acc[7]);
        acc[8]  = fmaf(w2.x, bj, acc[8]);  acc[9]  = fmaf(w2.y, bj, acc[9]);
        acc[10] = fmaf(w2.z, bj, acc[10]); acc[11] = fmaf(w2.w, bj, acc[11]);
        acc[12] = fmaf(w3.x, bj, acc[12]); acc[13] = fmaf(w3.y, bj, acc[13]);
        acc[14] = fmaf(w3.z, bj, acc[14]); acc[15] = fmaf(w3.w, bj, acc[15]);
    }
#pragma unroll
    for (int i = 0; i < 16; i++) atomicAdd(&g_T[(ib + i) * 64 + j], acc[i] * scale);
}

// ---- kernels ----
__global__ void k_zero(int which) {
    int i = blockIdx.x * blockDim.x + threadIdx.x;
    if (i < NN) { if (which == 0) g_M[i] = 0.f; else g_T[i] = 0.f; }
}
__global__ void k_mean_acc(const float* __restrict__ data, int per_chunk, float inv_nb) {
    int e = blockIdx.x * blockDim.x + threadIdx.x;
    const float* p = data + (size_t)(blockIdx.y) * per_chunk * NN + e;
    float sum = 0.f;
#pragma unroll 8
    for (int i = 0; i < per_chunk; i++) sum += p[(size_t)i * NN];
    atomicAdd(&g_M[e], sum * inv_nb);
}
__global__ void __launch_bounds__(TPB) k_eig_M() {
    extern __shared__ float sm[];
    float* A = sm; float* V = sm + BUF; float* T1 = sm + 2 * BUF; float* T2 = sm + 3 * BUF;
    __shared__ float w1[64], w2[64];
    load_g2s(g_M, A); __syncthreads();
    sym_s(A); __syncthreads();
    jacobi2s(A, V, NSWEEP_S);
    int t = threadIdx.x;
    if (t < 64) {
        float w = fmaxf(A[t * LD + t], 1e-12f);
        w1[t] = sqrtf(w); w2[t] = rsqrtf(w);
    }
    __syncthreads();
    scalecols(V, w1, T1); __syncthreads();
    smm_bt(T1, V, T2);    __syncthreads();
    store_s2g(T2, g_Ms);  __syncthreads();
    scalecols(V, w2, T1); __syncthreads();
    smm_bt(T1, V, T2);    __syncthreads();
    store_s2g(T2, g_Mi);
}

// batch step: C = Mi*D*Mi; register odd-even one-sided Jacobi; T += logm(C)/nb
__global__ void __launch_bounds__(TPB, 4) k_batch_oe(const float* __restrict__ data,
                                                     float inv_nb, int nsweep) {
    extern __shared__ float sm[];
    float* s0 = sm;             // Mi(row) -> xL overlay -> W(col)
    float* s1 = sm + BUFB;      // D(row) -> C(col) -> B(col)
    float* s2 = sm + 2 * BUFB;  // temp(row) -> xR overlay
    __shared__ float2 prm[2][32];
    int t = threadIdx.x;
    size_t b = blockIdx.x;

    for (int idx = t; idx < NN; idx += TPB)
        s0[(idx >> 6) * BLD + (idx & 63)] = g_Mi[idx];
    const float* D = data + b * NN;
    for (int idx = t; idx < NN; idx += TPB)
        s1[(idx >> 6) * BLD + (idx & 63)] = D[idx];
    __syncthreads();
    gemm_rr(s0, s1, s2);    // s2 = Mi*D (row)
    __syncthreads();
    gemm_r2c(s2, s0, s1);   // s1 = C (col CST)
    __syncthreads();
    for (int idx = t; idx < NN; idx += TPB) {   // symmetrize
        int i = idx >> 6, j = idx & 63;
        if (i < j) {
            float v = 0.5f * (s1[i * CST + j] + s1[j * CST + i]);
            s1[i * CST + j] = v; s1[j * CST + i] = v;
        }
    }
    __syncthreads();

    // ---- load 2 columns per 8-lane group into registers ----
    int lane = t & 31, warp = t >> 5, grp = lane >> 3, sub = lane & 7;
    int G = warp * 4 + grp;
    ull cL[4], cR[4];
    {
        const ulonglong2* pc = (const ulonglong2*)(s1 + (2 * G) * CST);
        ulonglong2 q0 = pc[2 * sub], q1 = pc[2 * sub + 1];
        cL[0] = q0.x; cL[1] = q0.y; cL[2] = q1.x; cL[3] = q1.y;
        const ulonglong2* pd = (const ulonglong2*)(s1 + (2 * G + 1) * CST);
        q0 = pd[2 * sub]; q1 = pd[2 * sub + 1];
        cR[0] = q0.x; cR[1] = q0.y; cR[2] = q1.x; cR[3] = q1.y;
    }
    __syncthreads();   // s0/s2 freed for xbuf overlays

    const bool hasR = (G < 31);
    const bool hasL = (G > 0);
    int pb = 0;
    for (int sw = 0; sw < nsweep; ++sw)
        for (int rr = 0; rr < 32; ++rr) {
            {   // EVEN round: pair (2G, 2G+1), registers only, swap
                float dd, apq;
                dots2(cL, cR, dd, apq);
                float c, s;
                rot_params2(dd, apq, c, s);
                ull c2 = pk2(c, c), s2p = pk2(s, s), ns2 = pk2(-s, -s);
#pragma unroll
                for (int i = 0; i < 4; i++) {
                    ull u = cL[i], v = cR[i];
                    cL[i] = fma2(s2p, u, mul2(c2, v));
                    cR[i] = fma2(ns2, v, mul2(c2, u));
                }
            }
            {   // ODD round: pair (2G+1, 2G+2) via smem exchange
                float4* Lb = (float4*)(s0 + ((pb << 5) + G) * 64);
                float4* Rb = (float4*)(s2 + ((pb << 5) + G) * 64);
                Lb[sub]     = *(float4*)&cL[0];
                Lb[sub + 8] = *(float4*)&cL[2];
                Rb[sub]     = *(float4*)&cR[0];
                Rb[sub + 8] = *(float4*)&cR[2];
                __syncthreads();
                ull vR[4] = {0, 0, 0, 0}, uL[4] = {0, 0, 0, 0};
                if (hasR) {
                    const float4* p = (const float4*)(s0 + ((pb << 5) + G + 1) * 64);
                    *(float4*)&vR[0] = p[sub];
                    *(float4*)&vR[2] = p[sub + 8];
                }
                if (hasL) {
                    const float4* p = (const float4*)(s2 + ((pb << 5) + G - 1) * 64);
                    *(float4*)&uL[0] = p[sub];
                    *(float4*)&uL[2] = p[sub + 8];
                }
                float dd, apq;
                dots2(cR, vR, dd, apq);   // collective (vR=0 -> identity)
                float c, s;
                rot_params2(dd, apq, c, s);
                if (sub == 0) prm[pb][G] = make_float2(c, s);
                __syncthreads();
                if (hasR) {
                    ull c2 = pk2(c, c), s2p = pk2(s, s);
#pragma unroll
                    for (int i = 0; i < 4; i++)
                        cR[i] = fma2(s2p, cR[i], mul2(c2, vR[i]));
                }
                if (hasL) {
                    float2 ps = prm[pb][G - 1];
                    ull cl2 = pk2(ps.x, ps.x), nsl2 = pk2(-ps.y, -ps.y);
#pragma unroll
                    for (int i = 0; i < 4; i++)
                        cL[i] = fma2(nsl2, cL[i], mul2(cl2, uL[i]));
                }
                pb ^= 1;
            }
        }

    // store columns back to s1 (col CST), permutation irrelevant
    {
        ulonglong2* pc = (ulonglong2*)(s1 + (2 * G) * CST);
        pc[2 * sub]     = make_ulonglong2(cL[0], cL[1]);
        pc[2 * sub + 1] = make_ulonglong2(cL[2], cL[3]);
        ulonglong2* pd = (ulonglong2*)(s1 + (2 * G + 1) * CST);
        pd[2 * sub]     = make_ulonglong2(cR[0], cR[1]);
        pd[2 * sub + 1] = make_ulonglong2(cR[2], cR[3]);
    }
    __syncthreads();
    colscale_log(s1, s0);
    __syncthreads();
    logm_atomic(s0, s1, inv_nb);
}

__global__ void __launch_bounds__(TPB) k_update_M() {
    extern __shared__ float sm[];
    float* A = sm; float* V = sm + BUF; float* T1 = sm + 2 * BUF; float* T2 = sm + 3 * BUF;
    __shared__ float ew[64];
    load_g2s(g_T, A); __syncthreads();
    sym_s(A); __syncthreads();
    jacobi2s(A, V, NSWEEP_S);
    int t = threadIdx.x;
    if (t < 64) ew[t] = expf(A[t * LD + t]);
    __syncthreads();
    scalecols(V, ew, T1); __syncthreads();
    smm_bt(T1, V, T2);    __syncthreads();
    load_g2s(g_Ms, A);    __syncthreads();
    smm(A, T2, T1);       __syncthreads();
    smm_glob(T1, A, g_M);
}
__global__ void __launch_bounds__(TPB) k_bias(const float* __restrict__ bias) {
    extern __shared__ float sm[];
    float* A = sm; float* V = sm + BUF; float* T1 = sm + 2 * BUF; float* T2 = sm + 3 * BUF;
    __shared__ float ew[64];
    int t = threadIdx.x;
    for (int idx = t; idx < NN; idx += TPB) {
        int i = idx >> 6, j = idx & 63;
        A[i * LD + j] = 0.5f * (bias[i * 64 + j] + bias[j * 64 + i]);
    }
    __syncthreads();
    jacobi2s(A, V, NSWEEP_S);
    if (t < 64) ew[t] = expf(0.5f * A[t * LD + t]);
    __syncthreads();
    scalecols(V, ew, T1); __syncthreads();
    smm_bt(T1, V, T2);    __syncthreads();
    load_g2s(g_Mi, A);    __syncthreads();
    smm_glob(T2, A, g_W);
}
__global__ void __launch_bounds__(TPB, 4) k_final(const float* __restrict__ data,
                                                  float* __restrict__ out) {
    extern __shared__ float sm[];
    float* sW = sm; float* sD = sm + BUFB; float* sT = sm + 2 * BUFB;
    size_t b = blockIdx.x;
    int t = threadIdx.x;
    for (int idx = t; idx < NN; idx += TPB)
        sW[(idx >> 6) * BLD + (idx & 63)] = g_W[idx];
    const float* D = data + b * NN;
    for (int idx = t; idx < NN; idx += TPB)
        sD[(idx >> 6) * BLD + (idx & 63)] = D[idx];
    __syncthreads();
    gemm_rr(sW, sD, sT);
    __syncthreads();
    int j = t & 63, ib = (t >> 6) << 4;
    ull acc[16];
#pragma unroll
    for (int i = 0; i < 16; i++) acc[i] = 0ull;
    for (int k = 0; k < 64; k += 2) {
        ull b2 = *(const ull*)(sW + j * BLD + k);
#pragma unroll
        for (int i = 0; i < 16; i++)
            acc[i] = fma2(*(const ull*)(sT + (ib + i) * BLD + k), b2, acc[i]);
    }
    float* o = out + b * NN;
#pragma unroll
    for (int i = 0; i < 16; i++) { float2 f = upk2(acc[i]); o[(ib + i) * 64 + j] = f.x + f.y; }
}

// ---------------------------------------------------------------------------
extern "C" void kernel_launch(void* const* d_in, const int* in_sizes, int n_in,
                              void* d_out, int out_size) {
    const float* data;
    const float* bias;
    int nb;
    if (in_sizes[0] >= in_sizes[1]) {
        data = (const float*)d_in[0]; bias = (const float*)d_in[1];
        nb = in_sizes[0] / NN;
    } else {
        data = (const float*)d_in[1]; bias = (const float*)d_in[0];
        nb = in_sizes[1] / NN;
    }
    float* out = (float*)d_out;
    float inv_nb = 1.0f / (float)nb;

    size_t smemS = 4 * BUF  * sizeof(float);
    size_t smemB = 3 * BUFB * sizeof(float);
    cudaFuncSetAttribute(k_eig_M,    cudaFuncAttributeMaxDynamicSharedMemorySize, (int)smemS);
    cudaFuncSetAttribute(k_batch_oe, cudaFuncAttributeMaxDynamicSharedMemorySize, (int)smemB);
    cudaFuncSetAttribute(k_update_M, cudaFuncAttributeMaxDynamicSharedMemorySize, (int)smemS);
    cudaFuncSetAttribute(k_bias,     cudaFuncAttributeMaxDynamicSharedMemorySize, (int)smemS);
    cudaFuncSetAttribute(k_final,    cudaFuncAttributeMaxDynamicSharedMemorySize, (int)smemB);

    k_zero<<<16, 256>>>(0);
    {
        int nchunk = 64;
        while (nchunk > 1 && (nb % nchunk) != 0) nchunk >>= 1;
        int per_chunk = nb / nchunk;
        dim3 g(NN / 256, nchunk);
        k_mean_acc<<<g, 256>>>(data, per_chunk, inv_nb);
    }

    // Karcher iterations: sweep schedule 6/7/7 (iter-1 residual damped twice)
    const int sweeps[3] = {6, 7, 7};
    for (int it = 0; it < 3; ++it) {
        k_eig_M<<<1, TPB, smemS>>>();
        k_zero<<<16, 256>>>(1);
        k_batch_oe<<<nb, TPB, smemB>>>(data, inv_nb, sweeps[it]);
        k_update_M<<<1, TPB, smemS>>>();
    }

    k_eig_M<<<1, TPB, smemS>>>();
    k_bias<<<1, TPB, smemS>>>(bias);
    k_final<<<nb, TPB, smemB>>>(data, out);
}